// round 1
// baseline (speedup 1.0000x reference)
#include <cuda_runtime.h>
#include <math.h>

#define NN 20000
#define EE 320000
#define NB 256
#define HIDC 64
#define CHUNK 128

// ---------------- scratch (device globals; no allocation) ----------------
__device__ float g_h[(size_t)NN * 512];
__device__ float g_z[(size_t)NN * 512];
__device__ float g_es[(size_t)EE * 4];
__device__ float g_ssrc[NN * 4];
__device__ float g_sdst[NN * 4];
__device__ float g_posc[NN * 3];
__device__ float g_cnt[NB];
__device__ float g_psum[NB * 3];
__device__ int   g_deg[NN];
__device__ int   g_off[NN + 1];
__device__ int   g_cur[NN];
__device__ int   g_eid[EE];
__device__ float g_gsum[NB * HIDC];

// ---------------- helpers ----------------
__device__ __forceinline__ float lrelu(float v) { return v > 0.f ? v : 0.2f * v; }
__device__ __forceinline__ float sigmoidf(float v) { return 1.f / (1.f + __expf(-v)); }

__device__ __forceinline__ float blockMax4w(float v, float* red) {
    #pragma unroll
    for (int o = 16; o; o >>= 1) v = fmaxf(v, __shfl_xor_sync(0xffffffffu, v, o));
    __syncthreads();
    if ((threadIdx.x & 31) == 0) red[threadIdx.x >> 5] = v;
    __syncthreads();
    return fmaxf(fmaxf(red[0], red[1]), fmaxf(red[2], red[3]));
}

__device__ __forceinline__ float blockSum4w(float v, float* red) {
    #pragma unroll
    for (int o = 16; o; o >>= 1) v += __shfl_xor_sync(0xffffffffu, v, o);
    __syncthreads();
    if ((threadIdx.x & 31) == 0) red[threadIdx.x >> 5] = v;
    __syncthreads();
    return red[0] + red[1] + red[2] + red[3];
}

// ---------------- init / batch statistics ----------------
__global__ void k_zero(int N) {
    int total = NB + NB * 3 + NB * HIDC + N;
    for (int i = blockIdx.x * blockDim.x + threadIdx.x; i < total; i += gridDim.x * blockDim.x) {
        if (i < NB) g_cnt[i] = 0.f;
        else if (i < NB + NB * 3) g_psum[i - NB] = 0.f;
        else if (i < NB + NB * 3 + NB * HIDC) g_gsum[i - NB - NB * 3] = 0.f;
        else g_deg[i - NB - NB * 3 - NB * HIDC] = 0;
    }
}

__global__ void k_batch(const float* __restrict__ pos, const int* __restrict__ batch, int N) {
    int n = blockIdx.x * blockDim.x + threadIdx.x;
    if (n >= N) return;
    int b = batch[n];
    atomicAdd(&g_cnt[b], 1.f);
    atomicAdd(&g_psum[b * 3 + 0], pos[n * 3 + 0]);
    atomicAdd(&g_psum[b * 3 + 1], pos[n * 3 + 1]);
    atomicAdd(&g_psum[b * 3 + 2], pos[n * 3 + 2]);
}

__global__ void k_posc(const float* __restrict__ pos, const int* __restrict__ batch, int N) {
    int n = blockIdx.x * blockDim.x + threadIdx.x;
    if (n >= N) return;
    int b = batch[n];
    float c = fmaxf(g_cnt[b], 1.f);
    float inv = 1.f / c;
    g_posc[n * 3 + 0] = pos[n * 3 + 0] - g_psum[b * 3 + 0] * inv;
    g_posc[n * 3 + 1] = pos[n * 3 + 1] - g_psum[b * 3 + 1] * inv;
    g_posc[n * 3 + 2] = pos[n * 3 + 2] - g_psum[b * 3 + 2] * inv;
}

// ---------------- node embedding + input projection ----------------
// h[n,o,0] = sum_i inw[o,i]*atom[i] + inb[o];  h[n,o,1..3] = inw[o,64]*pos_c;  rest 0
__global__ void __launch_bounds__(64) k_embed(const int* __restrict__ zi,
        const float* __restrict__ atomw, const float* __restrict__ inw,
        const float* __restrict__ inb, int N) {
    __shared__ float sa[64];
    int n = blockIdx.x, tid = threadIdx.x;
    sa[tid] = atomw[zi[n] * 64 + tid];
    __syncthreads();
    float acc = inb[tid];
    const float* wr = inw + tid * 65;
    #pragma unroll 8
    for (int i = 0; i < 64; i++) acc += wr[i] * sa[i];
    float vw = wr[64];
    float px = g_posc[n * 3], py = g_posc[n * 3 + 1], pz = g_posc[n * 3 + 2];
    float4* hp = (float4*)(g_h + (size_t)n * 512 + tid * 8);
    hp[0] = make_float4(acc, vw * px, vw * py, vw * pz);
    hp[1] = make_float4(0.f, 0.f, 0.f, 0.f);
}

// ---------------- edge RBF + MLP -> per-head scalar bias ----------------
__global__ void __launch_bounds__(128) k_edge(const float* __restrict__ pos,
        const int* __restrict__ src, const int* __restrict__ dst,
        const float* __restrict__ ew1, const float* __restrict__ eb1,
        const float* __restrict__ ew2, const float* __restrict__ eb2, int E) {
    __shared__ float s1[64 * 20];
    __shared__ float sb1[64];
    __shared__ float s2[4 * 64];
    __shared__ float sb2v[4];
    int tid = threadIdx.x;
    for (int i = tid; i < 1280; i += 128) s1[i] = ew1[i];
    if (tid < 64) sb1[tid] = eb1[tid];
    for (int i = tid; i < 256; i += 128) s2[i] = ew2[i];
    if (tid < 4) sb2v[tid] = eb2[tid];
    __syncthreads();
    int e = blockIdx.x * 128 + tid;
    if (e >= E) return;
    int s = src[e], d = dst[e];
    float dx = pos[s * 3] - pos[d * 3];
    float dy = pos[s * 3 + 1] - pos[d * 3 + 1];
    float dz = pos[s * 3 + 2] - pos[d * 3 + 2];
    float d2 = dx * dx + dy * dy + dz * dz;
    float dist = d2 > 0.f ? sqrtf(d2) : 0.f;
    const float width = 10.f / 19.f;
    const float invw = 19.f / 10.f;
    float rbf[20];
    #pragma unroll
    for (int k = 0; k < 20; k++) {
        float t = (dist - width * k) * invw;
        rbf[k] = __expf(-0.5f * t * t);
    }
    float a0 = 0.f, a1 = 0.f, a2 = 0.f, a3 = 0.f;
    for (int o = 0; o < 64; o++) {
        float hv = sb1[o];
        #pragma unroll
        for (int k = 0; k < 20; k++) hv += s1[o * 20 + k] * rbf[k];
        float sv = hv * sigmoidf(hv);
        a0 += s2[o] * sv; a1 += s2[64 + o] * sv; a2 += s2[128 + o] * sv; a3 += s2[192 + o] * sv;
    }
    ((float4*)g_es)[e] = make_float4(a0 + sb2v[0], a1 + sb2v[1], a2 + sb2v[2], a3 + sb2v[3]);
}

// ---------------- CSR by dst ----------------
__global__ void k_deg(const int* __restrict__ dst, int E) {
    int e = blockIdx.x * blockDim.x + threadIdx.x;
    if (e < E) atomicAdd(&g_deg[dst[e]], 1);
}

__global__ void __launch_bounds__(1024) k_scan(int N, int E) {
    __shared__ int part[1024];
    int tid = threadIdx.x;
    int per = (N + 1023) >> 10;
    int s0 = tid * per, s1 = min(s0 + per, N);
    int s = 0;
    for (int i = s0; i < s1; i++) s += g_deg[i];
    part[tid] = s;
    __syncthreads();
    for (int o = 1; o < 1024; o <<= 1) {
        int v = (tid >= o) ? part[tid - o] : 0;
        __syncthreads();
        part[tid] += v;
        __syncthreads();
    }
    int base = (tid == 0) ? 0 : part[tid - 1];
    for (int i = s0; i < s1; i++) { g_off[i] = base; g_cur[i] = base; base += g_deg[i]; }
    if (tid == 0) g_off[N] = E;
}

__global__ void k_fill(const int* __restrict__ dst, int E) {
    int e = blockIdx.x * blockDim.x + threadIdx.x;
    if (e < E) {
        int p = atomicAdd(&g_cur[dst[e]], 1);
        g_eid[p] = e;
    }
}

// ---------------- per-grade MVLinear: z = W_g(b) @ h + bias(blade 0) ----------------
// 16-node tile, W (4x64x64, padded rows) + X tile in dynamic smem. FFMA-bound via float4 X loads.
__global__ void __launch_bounds__(256) k_mvlin(const float* __restrict__ W,
        const float* __restrict__ B, int N) {
    extern __shared__ float sm[];
    float* Ws = sm;                  // 4*64*65 = 16640
    float* Xs = sm + 16640;          // 16*512 = 8192
    float* Bs = sm + 16640 + 8192;   // 64
    int tid = threadIdx.x;
    int n0 = blockIdx.x * 16;
    for (int idx = tid; idx < 16384; idx += 256) {
        int row = idx >> 6, i = idx & 63;
        Ws[row * 65 + i] = W[idx];
    }
    if (tid < 64) Bs[tid] = B[tid];
    for (int f = tid; f < 2048; f += 256) {
        int j = f >> 7, e4 = f & 127;
        int n = n0 + j;
        float4 v = (n < N) ? ((const float4*)g_h)[(size_t)n * 128 + e4]
                           : make_float4(0.f, 0.f, 0.f, 0.f);
        ((float4*)Xs)[j * 128 + e4] = v;
    }
    __syncthreads();
    int combo = tid & 127;
    int o = combo >> 1, half = combo & 1;
    int j0 = (tid >> 7) * 8;
    float acc[8][4];
    #pragma unroll
    for (int j = 0; j < 8; j++)
        #pragma unroll
        for (int c = 0; c < 4; c++) acc[j][c] = 0.f;
    const float* wrowA = Ws + ((half * 2) * 64 + o) * 65;  // grade half*2
    const float* wrowB = wrowA + 64 * 65;                  // grade half*2+1
    #pragma unroll 4
    for (int i = 0; i < 64; i++) {
        float wA = wrowA[i];
        float wB = wrowB[i];
        // half==0: blades 0..3 grades {0,1,1,1}; half==1: blades 4..7 grades {2,2,2,3}
        float w0 = wA;
        float w1 = half ? wA : wB;
        float w2 = half ? wA : wB;
        float w3 = wB;
        #pragma unroll
        for (int j = 0; j < 8; j++) {
            float4 x = *(const float4*)&Xs[(j0 + j) * 512 + i * 8 + half * 4];
            acc[j][0] += w0 * x.x;
            acc[j][1] += w1 * x.y;
            acc[j][2] += w2 * x.z;
            acc[j][3] += w3 * x.w;
        }
    }
    float bb = (half == 0) ? Bs[o] : 0.f;
    #pragma unroll
    for (int j = 0; j < 8; j++) {
        int n = n0 + j0 + j;
        if (n < N) {
            float4 v = make_float4(acc[j][0] + bb, acc[j][1], acc[j][2], acc[j][3]);
            ((float4*)g_z)[(size_t)n * 128 + o * 2 + half] = v;
        }
    }
}

// ---------------- per-node attention logit contractions ----------------
__global__ void __launch_bounds__(128) k_sprep(const float* __restrict__ Asrc,
        const float* __restrict__ Adst, const float* __restrict__ Wsrc,
        const float* __restrict__ Wdst, int N) {
    int gw = (blockIdx.x * blockDim.x + threadIdx.x) >> 5;
    int lane = threadIdx.x & 31;
    if (gw >= N) return;
    int h = lane >> 3;
    const float4* zp = (const float4*)(g_z + (size_t)gw * 512 + lane * 16);
    float ws0 = Wsrc[h * 4 + 0], ws1 = Wsrc[h * 4 + 1], ws2 = Wsrc[h * 4 + 2], ws3 = Wsrc[h * 4 + 3];
    float wd0 = Wdst[h * 4 + 0], wd1 = Wdst[h * 4 + 1], wd2 = Wdst[h * 4 + 2], wd3 = Wdst[h * 4 + 3];
    float ps = 0.f, pd = 0.f;
    #pragma unroll
    for (int k4 = 0; k4 < 4; k4++) {
        float4 zv = zp[k4];
        int eb = lane * 16 + k4 * 4;
        float4 as = *(const float4*)(Asrc + eb);
        float4 ad = *(const float4*)(Adst + eb);
        if ((k4 & 1) == 0) {  // blades 0..3: grades 0,1,1,1
            ps += zv.x * as.x * ws0 + zv.y * as.y * ws1 + zv.z * as.z * ws1 + zv.w * as.w * ws1;
            pd += zv.x * ad.x * wd0 + zv.y * ad.y * wd1 + zv.z * ad.z * wd1 + zv.w * ad.w * wd1;
        } else {              // blades 4..7: grades 2,2,2,3
            ps += zv.x * as.x * ws2 + zv.y * as.y * ws2 + zv.z * as.z * ws2 + zv.w * as.w * ws3;
            pd += zv.x * ad.x * wd2 + zv.y * ad.y * wd2 + zv.z * ad.z * wd2 + zv.w * ad.w * wd3;
        }
    }
    #pragma unroll
    for (int o = 4; o; o >>= 1) {
        ps += __shfl_down_sync(0xffffffffu, ps, o);
        pd += __shfl_down_sync(0xffffffffu, pd, o);
    }
    if ((lane & 7) == 0) {
        g_ssrc[gw * 4 + h] = ps;
        g_sdst[gw * 4 + h] = pd;
    }
}

// ---------------- fused attention + MVSiLU + residual + MVLayerNorm ----------------
// one block per dst node; thread t owns elements [4t,4t+4): head = t/32, channel = t/2,
// even t -> blades 0..3 (grades 0,1), odd t -> blades 4..7 (grades 2,3).
__global__ void __launch_bounds__(128) k_attn(const int* __restrict__ src,
        const float* __restrict__ sa, const float* __restrict__ sbp,
        const float* __restrict__ lna, int N) {
    __shared__ float sw[CHUNK * 4];
    __shared__ int sv[CHUNK];
    __shared__ float red[4];
    int n = blockIdx.x;
    int tid = threadIdx.x;
    int e0 = g_off[n];
    int deg = g_off[n + 1] - e0;
    float4 sd = ((const float4*)g_sdst)[n];

    // pass A: per-head max of leaky-relu logits
    float mx0 = -3e38f, mx1 = -3e38f, mx2 = -3e38f, mx3 = -3e38f;
    for (int j = tid; j < deg; j += 128) {
        int e = g_eid[e0 + j];
        float4 ss = ((const float4*)g_ssrc)[src[e]];
        float4 ev = ((const float4*)g_es)[e];
        mx0 = fmaxf(mx0, lrelu(ss.x + sd.x + ev.x));
        mx1 = fmaxf(mx1, lrelu(ss.y + sd.y + ev.y));
        mx2 = fmaxf(mx2, lrelu(ss.z + sd.z + ev.z));
        mx3 = fmaxf(mx3, lrelu(ss.w + sd.w + ev.w));
    }
    mx0 = blockMax4w(mx0, red);
    mx1 = blockMax4w(mx1, red);
    mx2 = blockMax4w(mx2, red);
    mx3 = blockMax4w(mx3, red);

    int head = tid >> 5;
    float ac0 = 0.f, ac1 = 0.f, ac2 = 0.f, ac3 = 0.f;
    float su0 = 0.f, su1 = 0.f, su2 = 0.f, su3 = 0.f;
    for (int base = 0; base < deg; base += CHUNK) {
        int m = min(CHUNK, deg - base);
        __syncthreads();
        for (int j = tid; j < m; j += 128) {
            int e = g_eid[e0 + base + j];
            int s = src[e];
            sv[j] = s;
            float4 ss = ((const float4*)g_ssrc)[s];
            float4 ev = ((const float4*)g_es)[e];
            float w0 = __expf(lrelu(ss.x + sd.x + ev.x) - mx0); su0 += w0;
            float w1 = __expf(lrelu(ss.y + sd.y + ev.y) - mx1); su1 += w1;
            float w2 = __expf(lrelu(ss.z + sd.z + ev.z) - mx2); su2 += w2;
            float w3 = __expf(lrelu(ss.w + sd.w + ev.w) - mx3); su3 += w3;
            ((float4*)sw)[j] = make_float4(w0, w1, w2, w3);
        }
        __syncthreads();
        for (int j = 0; j < m; j++) {
            float w = sw[j * 4 + head];
            float4 zv = *(const float4*)(g_z + (size_t)sv[j] * 512 + tid * 4);
            ac0 += w * zv.x; ac1 += w * zv.y; ac2 += w * zv.z; ac3 += w * zv.w;
        }
    }
    su0 = blockSum4w(su0, red);
    su1 = blockSum4w(su1, red);
    su2 = blockSum4w(su2, red);
    su3 = blockSum4w(su3, red);
    float tot = head == 0 ? su0 : head == 1 ? su1 : head == 2 ? su2 : su3;
    float inv = 1.f / (tot + 1e-16f);
    float x0 = ac0 * inv, x1 = ac1 * inv, x2 = ac2 * inv, x3 = ac3 * inv;

    // MVSiLU gating
    int c = tid >> 1;
    int hf = tid & 1;
    if (hf == 0) {
        float nA = x0;                               // scalar value (grade 0)
        float nB = x1 * x1 + x2 * x2 + x3 * x3;      // grade 1 |.|^2
        float gA = sigmoidf(sa[c * 4 + 0] * nA + sbp[c * 4 + 0]);
        float gB = sigmoidf(sa[c * 4 + 1] * nB + sbp[c * 4 + 1]);
        x0 *= gA; x1 *= gB; x2 *= gB; x3 *= gB;
    } else {
        float nA = x0 * x0 + x1 * x1 + x2 * x2;      // grade 2 |.|^2
        float nB = x3 * x3;                          // grade 3 |.|^2
        float gA = sigmoidf(sa[c * 4 + 2] * nA + sbp[c * 4 + 2]);
        float gB = sigmoidf(sa[c * 4 + 3] * nB + sbp[c * 4 + 3]);
        x0 *= gA; x1 *= gA; x2 *= gA; x3 *= gB;
    }

    // residual
    float4 r = *(const float4*)(g_h + (size_t)n * 512 + tid * 4);
    x0 += r.x; x1 += r.y; x2 += r.z; x3 += r.w;

    // MVLayerNorm: per-channel norm, mean over 64 channels per node
    float ssq = x0 * x0 + x1 * x1 + x2 * x2 + x3 * x3;
    ssq += __shfl_xor_sync(0xffffffffu, ssq, 1);
    float cn = sqrtf(ssq);                           // each channel counted by 2 threads
    float totn = blockSum4w(cn, red);
    float mean = totn * (1.f / 128.f) + 1e-6f;       // (totn/2)/64
    float scale = lna[c] / mean;
    *(float4*)(g_h + (size_t)n * 512 + tid * 4) =
        make_float4(x0 * scale, x1 * scale, x2 * scale, x3 * scale);
}

// ---------------- prepool (scalar blade) + graph pooling ----------------
__global__ void __launch_bounds__(64) k_prepool(const float* __restrict__ ppw,
        const float* __restrict__ ppb, const int* __restrict__ batch, int N) {
    __shared__ float x0[64];
    int n = blockIdx.x, tid = threadIdx.x;
    x0[tid] = g_h[(size_t)n * 512 + tid * 8];
    __syncthreads();
    float acc = ppb[tid];
    const float* wr = ppw + tid * 64;   // grade-0 weight matrix
    #pragma unroll 8
    for (int i = 0; i < 64; i++) acc += wr[i] * x0[i];
    atomicAdd(&g_gsum[batch[n] * 64 + tid], acc);
}

__global__ void __launch_bounds__(64) k_post(const float* __restrict__ pw1,
        const float* __restrict__ pb1, const float* __restrict__ pw2,
        const float* __restrict__ pb2, float* __restrict__ out) {
    __shared__ float sg[64];
    __shared__ float sh[64];
    int b = blockIdx.x, tid = threadIdx.x;
    sg[tid] = g_gsum[b * 64 + tid];
    __syncthreads();
    float a = pb1[tid];
    const float* wr = pw1 + tid * 64;
    #pragma unroll 8
    for (int i = 0; i < 64; i++) a += wr[i] * sg[i];
    float s = a * sigmoidf(a);
    sh[tid] = s * pw2[tid];
    __syncthreads();
    for (int st = 32; st; st >>= 1) {
        if (tid < st) sh[tid] += sh[tid + st];
        __syncthreads();
    }
    if (tid == 0) out[b] = sh[0] + pb2[0];
}

// ---------------- launch ----------------
extern "C" void kernel_launch(void* const* d_in, const int* in_sizes, int n_in,
                              void* d_out, int out_size) {
    const float* pos   = (const float*)d_in[0];
    const int*   zi    = (const int*)d_in[1];
    const int*   ei    = (const int*)d_in[2];
    const int*   batch = (const int*)d_in[3];
    const float* atomw = (const float*)d_in[4];
    const float* inw   = (const float*)d_in[5];
    const float* inb   = (const float*)d_in[6];
    const float* ew1   = (const float*)d_in[7];
    const float* eb1   = (const float*)d_in[8];
    const float* ew2   = (const float*)d_in[9];
    const float* eb2   = (const float*)d_in[10];
    const float* projw = (const float*)d_in[11];
    const float* projb = (const float*)d_in[12];
    const float* asrc  = (const float*)d_in[13];
    const float* adst  = (const float*)d_in[14];
    const float* wsrc  = (const float*)d_in[15];
    const float* wdst  = (const float*)d_in[16];
    const float* lna   = (const float*)d_in[17];
    const float* silua = (const float*)d_in[18];
    const float* silub = (const float*)d_in[19];
    const float* ppw   = (const float*)d_in[20];
    const float* ppb   = (const float*)d_in[21];
    const float* pw1   = (const float*)d_in[22];
    const float* pb1   = (const float*)d_in[23];
    const float* pw2   = (const float*)d_in[24];
    const float* pb2   = (const float*)d_in[25];
    float* out = (float*)d_out;

    int N = in_sizes[0] / 3;
    int E = in_sizes[2] / 2;
    const int* src = ei;
    const int* dst = ei + E;

    cudaFuncSetAttribute(k_mvlin, cudaFuncAttributeMaxDynamicSharedMemorySize, 99584);

    k_zero<<<64, 256>>>(N);
    k_batch<<<(N + 255) / 256, 256>>>(pos, batch, N);
    k_posc<<<(N + 255) / 256, 256>>>(pos, batch, N);
    k_embed<<<N, 64>>>(zi, atomw, inw, inb, N);
    k_edge<<<(E + 127) / 128, 128>>>(pos, src, dst, ew1, eb1, ew2, eb2, E);
    k_deg<<<(E + 255) / 256, 256>>>(dst, E);
    k_scan<<<1, 1024>>>(N, E);
    k_fill<<<(E + 255) / 256, 256>>>(dst, E);

    for (int l = 0; l < 4; l++) {
        k_mvlin<<<(N + 15) / 16, 256, 99584>>>(projw + (size_t)l * 4 * 64 * 64,
                                               projb + l * 64, N);
        k_sprep<<<(N + 3) / 4, 128>>>(asrc + l * 512, adst + l * 512,
                                      wsrc + l * 16, wdst + l * 16, N);
        k_attn<<<N, 128>>>(src, silua + l * 256, silub + l * 256, lna + l * 64, N);
    }

    k_prepool<<<N, 64>>>(ppw, ppb, batch, N);
    k_post<<<NB, 64>>>(pw1, pb1, pw2, pb2, out);
}

// round 2
// speedup vs baseline: 1.0003x; 1.0003x over previous
#include <cuda_runtime.h>
#include <math.h>

#define NN 20000
#define EE 320000
#define NB 256
#define HIDC 64
#define CHUNK 128

// ---------------- scratch (device globals; no allocation) ----------------
__device__ float g_h[(size_t)NN * 512];
__device__ float g_z[(size_t)NN * 512];
__device__ float g_es[(size_t)EE * 4];
__device__ float g_ssrc[NN * 4];
__device__ float g_sdst[NN * 4];
__device__ float g_posc[NN * 3];
__device__ float g_cnt[NB];
__device__ float g_psum[NB * 3];
__device__ int   g_deg[NN];
__device__ int   g_off[NN + 1];
__device__ int   g_cur[NN];
__device__ int   g_eid[EE];
__device__ float g_gsum[NB * HIDC];

// ---------------- helpers ----------------
__device__ __forceinline__ float lrelu(float v) { return v > 0.f ? v : 0.2f * v; }
__device__ __forceinline__ float sigmoidf(float v) { return 1.f / (1.f + __expf(-v)); }

__device__ __forceinline__ float blockMax4w(float v, float* red) {
    #pragma unroll
    for (int o = 16; o; o >>= 1) v = fmaxf(v, __shfl_xor_sync(0xffffffffu, v, o));
    __syncthreads();
    if ((threadIdx.x & 31) == 0) red[threadIdx.x >> 5] = v;
    __syncthreads();
    return fmaxf(fmaxf(red[0], red[1]), fmaxf(red[2], red[3]));
}

__device__ __forceinline__ float blockSum4w(float v, float* red) {
    #pragma unroll
    for (int o = 16; o; o >>= 1) v += __shfl_xor_sync(0xffffffffu, v, o);
    __syncthreads();
    if ((threadIdx.x & 31) == 0) red[threadIdx.x >> 5] = v;
    __syncthreads();
    return red[0] + red[1] + red[2] + red[3];
}

// ---------------- init / batch statistics ----------------
__global__ void k_zero(int N) {
    int total = NB + NB * 3 + NB * HIDC + N;
    for (int i = blockIdx.x * blockDim.x + threadIdx.x; i < total; i += gridDim.x * blockDim.x) {
        if (i < NB) g_cnt[i] = 0.f;
        else if (i < NB + NB * 3) g_psum[i - NB] = 0.f;
        else if (i < NB + NB * 3 + NB * HIDC) g_gsum[i - NB - NB * 3] = 0.f;
        else g_deg[i - NB - NB * 3 - NB * HIDC] = 0;
    }
}

__global__ void k_batch(const float* __restrict__ pos, const int* __restrict__ batch, int N) {
    int n = blockIdx.x * blockDim.x + threadIdx.x;
    if (n >= N) return;
    int b = batch[n];
    atomicAdd(&g_cnt[b], 1.f);
    atomicAdd(&g_psum[b * 3 + 0], pos[n * 3 + 0]);
    atomicAdd(&g_psum[b * 3 + 1], pos[n * 3 + 1]);
    atomicAdd(&g_psum[b * 3 + 2], pos[n * 3 + 2]);
}

__global__ void k_posc(const float* __restrict__ pos, const int* __restrict__ batch, int N) {
    int n = blockIdx.x * blockDim.x + threadIdx.x;
    if (n >= N) return;
    int b = batch[n];
    float c = fmaxf(g_cnt[b], 1.f);
    float inv = 1.f / c;
    g_posc[n * 3 + 0] = pos[n * 3 + 0] - g_psum[b * 3 + 0] * inv;
    g_posc[n * 3 + 1] = pos[n * 3 + 1] - g_psum[b * 3 + 1] * inv;
    g_posc[n * 3 + 2] = pos[n * 3 + 2] - g_psum[b * 3 + 2] * inv;
}

// ---------------- node embedding + input projection ----------------
// h[n,o,0] = sum_i inw[o,i]*atom[i] + inb[o];  h[n,o,1..3] = inw[o,64]*pos_c;  rest 0
__global__ void __launch_bounds__(64) k_embed(const int* __restrict__ zi,
        const float* __restrict__ atomw, const float* __restrict__ inw,
        const float* __restrict__ inb, int N) {
    __shared__ float sa[64];
    int n = blockIdx.x, tid = threadIdx.x;
    sa[tid] = atomw[zi[n] * 64 + tid];
    __syncthreads();
    float acc = inb[tid];
    const float* wr = inw + tid * 65;
    #pragma unroll 8
    for (int i = 0; i < 64; i++) acc += wr[i] * sa[i];
    float vw = wr[64];
    float px = g_posc[n * 3], py = g_posc[n * 3 + 1], pz = g_posc[n * 3 + 2];
    float4* hp = (float4*)(g_h + (size_t)n * 512 + tid * 8);
    hp[0] = make_float4(acc, vw * px, vw * py, vw * pz);
    hp[1] = make_float4(0.f, 0.f, 0.f, 0.f);
}

// ---------------- edge RBF + MLP -> per-head scalar bias ----------------
__global__ void __launch_bounds__(128) k_edge(const float* __restrict__ pos,
        const int* __restrict__ src, const int* __restrict__ dst,
        const float* __restrict__ ew1, const float* __restrict__ eb1,
        const float* __restrict__ ew2, const float* __restrict__ eb2, int E) {
    __shared__ float s1[64 * 20];
    __shared__ float sb1[64];
    __shared__ float s2[4 * 64];
    __shared__ float sb2v[4];
    int tid = threadIdx.x;
    for (int i = tid; i < 1280; i += 128) s1[i] = ew1[i];
    if (tid < 64) sb1[tid] = eb1[tid];
    for (int i = tid; i < 256; i += 128) s2[i] = ew2[i];
    if (tid < 4) sb2v[tid] = eb2[tid];
    __syncthreads();
    int e = blockIdx.x * 128 + tid;
    if (e >= E) return;
    int s = src[e], d = dst[e];
    float dx = pos[s * 3] - pos[d * 3];
    float dy = pos[s * 3 + 1] - pos[d * 3 + 1];
    float dz = pos[s * 3 + 2] - pos[d * 3 + 2];
    float d2 = dx * dx + dy * dy + dz * dz;
    float dist = d2 > 0.f ? sqrtf(d2) : 0.f;
    const float width = 10.f / 19.f;
    const float invw = 19.f / 10.f;
    float rbf[20];
    #pragma unroll
    for (int k = 0; k < 20; k++) {
        float t = (dist - width * k) * invw;
        rbf[k] = __expf(-0.5f * t * t);
    }
    float a0 = 0.f, a1 = 0.f, a2 = 0.f, a3 = 0.f;
    for (int o = 0; o < 64; o++) {
        float hv = sb1[o];
        #pragma unroll
        for (int k = 0; k < 20; k++) hv += s1[o * 20 + k] * rbf[k];
        float sv = hv * sigmoidf(hv);
        a0 += s2[o] * sv; a1 += s2[64 + o] * sv; a2 += s2[128 + o] * sv; a3 += s2[192 + o] * sv;
    }
    ((float4*)g_es)[e] = make_float4(a0 + sb2v[0], a1 + sb2v[1], a2 + sb2v[2], a3 + sb2v[3]);
}

// ---------------- CSR by dst ----------------
__global__ void k_deg(const int* __restrict__ dst, int E) {
    int e = blockIdx.x * blockDim.x + threadIdx.x;
    if (e < E) atomicAdd(&g_deg[dst[e]], 1);
}

__global__ void __launch_bounds__(1024) k_scan(int N, int E) {
    __shared__ int part[1024];
    int tid = threadIdx.x;
    int per = (N + 1023) >> 10;
    int s0 = tid * per, s1 = min(s0 + per, N);
    int s = 0;
    for (int i = s0; i < s1; i++) s += g_deg[i];
    part[tid] = s;
    __syncthreads();
    for (int o = 1; o < 1024; o <<= 1) {
        int v = (tid >= o) ? part[tid - o] : 0;
        __syncthreads();
        part[tid] += v;
        __syncthreads();
    }
    int base = (tid == 0) ? 0 : part[tid - 1];
    for (int i = s0; i < s1; i++) { g_off[i] = base; g_cur[i] = base; base += g_deg[i]; }
    if (tid == 0) g_off[N] = E;
}

__global__ void k_fill(const int* __restrict__ dst, int E) {
    int e = blockIdx.x * blockDim.x + threadIdx.x;
    if (e < E) {
        int p = atomicAdd(&g_cur[dst[e]], 1);
        g_eid[p] = e;
    }
}

// ---------------- per-grade MVLinear: z = W_g(b) @ h + bias(blade 0) ----------------
// 16-node tile, W (4x64x64, padded rows) + X tile in dynamic smem. FFMA-bound via float4 X loads.
__global__ void __launch_bounds__(256) k_mvlin(const float* __restrict__ W,
        const float* __restrict__ B, int N) {
    extern __shared__ float sm[];
    float* Ws = sm;                  // 4*64*65 = 16640
    float* Xs = sm + 16640;          // 16*512 = 8192
    float* Bs = sm + 16640 + 8192;   // 64
    int tid = threadIdx.x;
    int n0 = blockIdx.x * 16;
    for (int idx = tid; idx < 16384; idx += 256) {
        int row = idx >> 6, i = idx & 63;
        Ws[row * 65 + i] = W[idx];
    }
    if (tid < 64) Bs[tid] = B[tid];
    for (int f = tid; f < 2048; f += 256) {
        int j = f >> 7, e4 = f & 127;
        int n = n0 + j;
        float4 v = (n < N) ? ((const float4*)g_h)[(size_t)n * 128 + e4]
                           : make_float4(0.f, 0.f, 0.f, 0.f);
        ((float4*)Xs)[j * 128 + e4] = v;
    }
    __syncthreads();
    int combo = tid & 127;
    int o = combo >> 1, half = combo & 1;
    int j0 = (tid >> 7) * 8;
    float acc[8][4];
    #pragma unroll
    for (int j = 0; j < 8; j++)
        #pragma unroll
        for (int c = 0; c < 4; c++) acc[j][c] = 0.f;
    const float* wrowA = Ws + ((half * 2) * 64 + o) * 65;  // grade half*2
    const float* wrowB = wrowA + 64 * 65;                  // grade half*2+1
    #pragma unroll 4
    for (int i = 0; i < 64; i++) {
        float wA = wrowA[i];
        float wB = wrowB[i];
        // half==0: blades 0..3 grades {0,1,1,1}; half==1: blades 4..7 grades {2,2,2,3}
        float w0 = wA;
        float w1 = half ? wA : wB;
        float w2 = half ? wA : wB;
        float w3 = wB;
        #pragma unroll
        for (int j = 0; j < 8; j++) {
            float4 x = *(const float4*)&Xs[(j0 + j) * 512 + i * 8 + half * 4];
            acc[j][0] += w0 * x.x;
            acc[j][1] += w1 * x.y;
            acc[j][2] += w2 * x.z;
            acc[j][3] += w3 * x.w;
        }
    }
    float bb = (half == 0) ? Bs[o] : 0.f;
    #pragma unroll
    for (int j = 0; j < 8; j++) {
        int n = n0 + j0 + j;
        if (n < N) {
            float4 v = make_float4(acc[j][0] + bb, acc[j][1], acc[j][2], acc[j][3]);
            ((float4*)g_z)[(size_t)n * 128 + o * 2 + half] = v;
        }
    }
}

// ---------------- per-node attention logit contractions ----------------
__global__ void __launch_bounds__(128) k_sprep(const float* __restrict__ Asrc,
        const float* __restrict__ Adst, const float* __restrict__ Wsrc,
        const float* __restrict__ Wdst, int N) {
    int gw = (blockIdx.x * blockDim.x + threadIdx.x) >> 5;
    int lane = threadIdx.x & 31;
    if (gw >= N) return;
    int h = lane >> 3;
    const float4* zp = (const float4*)(g_z + (size_t)gw * 512 + lane * 16);
    float ws0 = Wsrc[h * 4 + 0], ws1 = Wsrc[h * 4 + 1], ws2 = Wsrc[h * 4 + 2], ws3 = Wsrc[h * 4 + 3];
    float wd0 = Wdst[h * 4 + 0], wd1 = Wdst[h * 4 + 1], wd2 = Wdst[h * 4 + 2], wd3 = Wdst[h * 4 + 3];
    float ps = 0.f, pd = 0.f;
    #pragma unroll
    for (int k4 = 0; k4 < 4; k4++) {
        float4 zv = zp[k4];
        int eb = lane * 16 + k4 * 4;
        float4 as = *(const float4*)(Asrc + eb);
        float4 ad = *(const float4*)(Adst + eb);
        if ((k4 & 1) == 0) {  // blades 0..3: grades 0,1,1,1
            ps += zv.x * as.x * ws0 + zv.y * as.y * ws1 + zv.z * as.z * ws1 + zv.w * as.w * ws1;
            pd += zv.x * ad.x * wd0 + zv.y * ad.y * wd1 + zv.z * ad.z * wd1 + zv.w * ad.w * wd1;
        } else {              // blades 4..7: grades 2,2,2,3
            ps += zv.x * as.x * ws2 + zv.y * as.y * ws2 + zv.z * as.z * ws2 + zv.w * as.w * ws3;
            pd += zv.x * ad.x * wd2 + zv.y * ad.y * wd2 + zv.z * ad.z * wd2 + zv.w * ad.w * wd3;
        }
    }
    #pragma unroll
    for (int o = 4; o; o >>= 1) {
        ps += __shfl_down_sync(0xffffffffu, ps, o);
        pd += __shfl_down_sync(0xffffffffu, pd, o);
    }
    if ((lane & 7) == 0) {
        g_ssrc[gw * 4 + h] = ps;
        g_sdst[gw * 4 + h] = pd;
    }
}

// ---------------- fused attention + MVSiLU + residual + MVLayerNorm ----------------
// one block per dst node; thread t owns elements [4t,4t+4): head = t/32, channel = t/2,
// even t -> blades 0..3 (grades 0,1), odd t -> blades 4..7 (grades 2,3).
__global__ void __launch_bounds__(128) k_attn(const int* __restrict__ src,
        const float* __restrict__ sa, const float* __restrict__ sbp,
        const float* __restrict__ lna, int N) {
    __shared__ float sw[CHUNK * 4];
    __shared__ int sv[CHUNK];
    __shared__ float red[4];
    int n = blockIdx.x;
    int tid = threadIdx.x;
    int e0 = g_off[n];
    int deg = g_off[n + 1] - e0;
    float4 sd = ((const float4*)g_sdst)[n];

    // pass A: per-head max of leaky-relu logits
    float mx0 = -3e38f, mx1 = -3e38f, mx2 = -3e38f, mx3 = -3e38f;
    for (int j = tid; j < deg; j += 128) {
        int e = g_eid[e0 + j];
        float4 ss = ((const float4*)g_ssrc)[src[e]];
        float4 ev = ((const float4*)g_es)[e];
        mx0 = fmaxf(mx0, lrelu(ss.x + sd.x + ev.x));
        mx1 = fmaxf(mx1, lrelu(ss.y + sd.y + ev.y));
        mx2 = fmaxf(mx2, lrelu(ss.z + sd.z + ev.z));
        mx3 = fmaxf(mx3, lrelu(ss.w + sd.w + ev.w));
    }
    mx0 = blockMax4w(mx0, red);
    mx1 = blockMax4w(mx1, red);
    mx2 = blockMax4w(mx2, red);
    mx3 = blockMax4w(mx3, red);

    int head = tid >> 5;
    float ac0 = 0.f, ac1 = 0.f, ac2 = 0.f, ac3 = 0.f;
    float su0 = 0.f, su1 = 0.f, su2 = 0.f, su3 = 0.f;
    for (int base = 0; base < deg; base += CHUNK) {
        int m = min(CHUNK, deg - base);
        __syncthreads();
        for (int j = tid; j < m; j += 128) {
            int e = g_eid[e0 + base + j];
            int s = src[e];
            sv[j] = s;
            float4 ss = ((const float4*)g_ssrc)[s];
            float4 ev = ((const float4*)g_es)[e];
            float w0 = __expf(lrelu(ss.x + sd.x + ev.x) - mx0); su0 += w0;
            float w1 = __expf(lrelu(ss.y + sd.y + ev.y) - mx1); su1 += w1;
            float w2 = __expf(lrelu(ss.z + sd.z + ev.z) - mx2); su2 += w2;
            float w3 = __expf(lrelu(ss.w + sd.w + ev.w) - mx3); su3 += w3;
            ((float4*)sw)[j] = make_float4(w0, w1, w2, w3);
        }
        __syncthreads();
        for (int j = 0; j < m; j++) {
            float w = sw[j * 4 + head];
            float4 zv = *(const float4*)(g_z + (size_t)sv[j] * 512 + tid * 4);
            ac0 += w * zv.x; ac1 += w * zv.y; ac2 += w * zv.z; ac3 += w * zv.w;
        }
    }
    su0 = blockSum4w(su0, red);
    su1 = blockSum4w(su1, red);
    su2 = blockSum4w(su2, red);
    su3 = blockSum4w(su3, red);
    float tot = head == 0 ? su0 : head == 1 ? su1 : head == 2 ? su2 : su3;
    float inv = 1.f / (tot + 1e-16f);
    float x0 = ac0 * inv, x1 = ac1 * inv, x2 = ac2 * inv, x3 = ac3 * inv;

    // MVSiLU gating
    int c = tid >> 1;
    int hf = tid & 1;
    if (hf == 0) {
        float nA = x0;                               // scalar value (grade 0)
        float nB = x1 * x1 + x2 * x2 + x3 * x3;      // grade 1 |.|^2
        float gA = sigmoidf(sa[c * 4 + 0] * nA + sbp[c * 4 + 0]);
        float gB = sigmoidf(sa[c * 4 + 1] * nB + sbp[c * 4 + 1]);
        x0 *= gA; x1 *= gB; x2 *= gB; x3 *= gB;
    } else {
        float nA = x0 * x0 + x1 * x1 + x2 * x2;      // grade 2 |.|^2
        float nB = x3 * x3;                          // grade 3 |.|^2
        float gA = sigmoidf(sa[c * 4 + 2] * nA + sbp[c * 4 + 2]);
        float gB = sigmoidf(sa[c * 4 + 3] * nB + sbp[c * 4 + 3]);
        x0 *= gA; x1 *= gA; x2 *= gA; x3 *= gB;
    }

    // residual
    float4 r = *(const float4*)(g_h + (size_t)n * 512 + tid * 4);
    x0 += r.x; x1 += r.y; x2 += r.z; x3 += r.w;

    // MVLayerNorm: per-channel norm, mean over 64 channels per node
    float ssq = x0 * x0 + x1 * x1 + x2 * x2 + x3 * x3;
    ssq += __shfl_xor_sync(0xffffffffu, ssq, 1);
    float cn = sqrtf(ssq);                           // each channel counted by 2 threads
    float totn = blockSum4w(cn, red);
    float mean = totn * (1.f / 128.f) + 1e-6f;       // (totn/2)/64
    float scale = lna[c] / mean;
    *(float4*)(g_h + (size_t)n * 512 + tid * 4) =
        make_float4(x0 * scale, x1 * scale, x2 * scale, x3 * scale);
}

// ---------------- prepool (scalar blade) + graph pooling ----------------
__global__ void __launch_bounds__(64) k_prepool(const float* __restrict__ ppw,
        const float* __restrict__ ppb, const int* __restrict__ batch, int N) {
    __shared__ float x0[64];
    int n = blockIdx.x, tid = threadIdx.x;
    x0[tid] = g_h[(size_t)n * 512 + tid * 8];
    __syncthreads();
    float acc = ppb[tid];
    const float* wr = ppw + tid * 64;   // grade-0 weight matrix
    #pragma unroll 8
    for (int i = 0; i < 64; i++) acc += wr[i] * x0[i];
    atomicAdd(&g_gsum[batch[n] * 64 + tid], acc);
}

__global__ void __launch_bounds__(64) k_post(const float* __restrict__ pw1,
        const float* __restrict__ pb1, const float* __restrict__ pw2,
        const float* __restrict__ pb2, float* __restrict__ out) {
    __shared__ float sg[64];
    __shared__ float sh[64];
    int b = blockIdx.x, tid = threadIdx.x;
    sg[tid] = g_gsum[b * 64 + tid];
    __syncthreads();
    float a = pb1[tid];
    const float* wr = pw1 + tid * 64;
    #pragma unroll 8
    for (int i = 0; i < 64; i++) a += wr[i] * sg[i];
    float s = a * sigmoidf(a);
    sh[tid] = s * pw2[tid];
    __syncthreads();
    for (int st = 32; st; st >>= 1) {
        if (tid < st) sh[tid] += sh[tid + st];
        __syncthreads();
    }
    if (tid == 0) out[b] = sh[0] + pb2[0];
}

// ---------------- launch ----------------
extern "C" void kernel_launch(void* const* d_in, const int* in_sizes, int n_in,
                              void* d_out, int out_size) {
    const float* pos   = (const float*)d_in[0];
    const int*   zi    = (const int*)d_in[1];
    const int*   ei    = (const int*)d_in[2];
    const int*   batch = (const int*)d_in[3];
    const float* atomw = (const float*)d_in[4];
    const float* inw   = (const float*)d_in[5];
    const float* inb   = (const float*)d_in[6];
    const float* ew1   = (const float*)d_in[7];
    const float* eb1   = (const float*)d_in[8];
    const float* ew2   = (const float*)d_in[9];
    const float* eb2   = (const float*)d_in[10];
    const float* projw = (const float*)d_in[11];
    const float* projb = (const float*)d_in[12];
    const float* asrc  = (const float*)d_in[13];
    const float* adst  = (const float*)d_in[14];
    const float* wsrc  = (const float*)d_in[15];
    const float* wdst  = (const float*)d_in[16];
    const float* lna   = (const float*)d_in[17];
    const float* silua = (const float*)d_in[18];
    const float* silub = (const float*)d_in[19];
    const float* ppw   = (const float*)d_in[20];
    const float* ppb   = (const float*)d_in[21];
    const float* pw1   = (const float*)d_in[22];
    const float* pb1   = (const float*)d_in[23];
    const float* pw2   = (const float*)d_in[24];
    const float* pb2   = (const float*)d_in[25];
    float* out = (float*)d_out;

    int N = in_sizes[0] / 3;
    int E = in_sizes[2] / 2;
    const int* src = ei;
    const int* dst = ei + E;

    cudaFuncSetAttribute(k_mvlin, cudaFuncAttributeMaxDynamicSharedMemorySize, 99584);

    k_zero<<<64, 256>>>(N);
    k_batch<<<(N + 255) / 256, 256>>>(pos, batch, N);
    k_posc<<<(N + 255) / 256, 256>>>(pos, batch, N);
    k_embed<<<N, 64>>>(zi, atomw, inw, inb, N);
    k_edge<<<(E + 127) / 128, 128>>>(pos, src, dst, ew1, eb1, ew2, eb2, E);
    k_deg<<<(E + 255) / 256, 256>>>(dst, E);
    k_scan<<<1, 1024>>>(N, E);
    k_fill<<<(E + 255) / 256, 256>>>(dst, E);

    for (int l = 0; l < 4; l++) {
        k_mvlin<<<(N + 15) / 16, 256, 99584>>>(projw + (size_t)l * 4 * 64 * 64,
                                               projb + l * 64, N);
        k_sprep<<<(N + 3) / 4, 128>>>(asrc + l * 512, adst + l * 512,
                                      wsrc + l * 16, wdst + l * 16, N);
        k_attn<<<N, 128>>>(src, silua + l * 256, silub + l * 256, lna + l * 64, N);
    }

    k_prepool<<<N, 64>>>(ppw, ppb, batch, N);
    k_post<<<NB, 64>>>(pw1, pb1, pw2, pb2, out);
}

// round 3
// speedup vs baseline: 1.0718x; 1.0715x over previous
#include <cuda_runtime.h>
#include <math.h>

#define NN 20000
#define EE 320000
#define NB 256
#define HIDC 64
#define CHUNK 128

// ---------------- scratch (device globals; no allocation) ----------------
__device__ float g_h[(size_t)NN * 512];
__device__ float g_z[(size_t)NN * 512];
__device__ float g_es[(size_t)EE * 4];
__device__ float g_esp[(size_t)EE * 4];   // edge scalar permuted to CSR order
__device__ float g_lg[(size_t)EE * 4];    // per-layer logits (CSR order, post-lrelu)
__device__ int   g_srcp[EE];              // src permuted to CSR order
__device__ int   g_dstp[EE];              // dst permuted to CSR order
__device__ float g_ssrc[NN * 4];
__device__ float g_sdst[NN * 4];
__device__ float g_posc[NN * 3];
__device__ float g_cnt[NB];
__device__ float g_psum[NB * 3];
__device__ int   g_deg[NN];
__device__ int   g_off[NN + 1];
__device__ int   g_cur[NN];
__device__ int   g_eid[EE];
__device__ float g_gsum[NB * HIDC];

// ---------------- helpers ----------------
__device__ __forceinline__ float lrelu(float v) { return v > 0.f ? v : 0.2f * v; }
__device__ __forceinline__ float sigmoidf(float v) { return 1.f / (1.f + __expf(-v)); }

__device__ __forceinline__ float blockMax4w(float v, float* red) {
    #pragma unroll
    for (int o = 16; o; o >>= 1) v = fmaxf(v, __shfl_xor_sync(0xffffffffu, v, o));
    __syncthreads();
    if ((threadIdx.x & 31) == 0) red[threadIdx.x >> 5] = v;
    __syncthreads();
    return fmaxf(fmaxf(red[0], red[1]), fmaxf(red[2], red[3]));
}

__device__ __forceinline__ float blockSum4w(float v, float* red) {
    #pragma unroll
    for (int o = 16; o; o >>= 1) v += __shfl_xor_sync(0xffffffffu, v, o);
    __syncthreads();
    if ((threadIdx.x & 31) == 0) red[threadIdx.x >> 5] = v;
    __syncthreads();
    return red[0] + red[1] + red[2] + red[3];
}

// ---------------- init / batch statistics ----------------
__global__ void k_zero(int N) {
    int total = NB + NB * 3 + NB * HIDC + N;
    for (int i = blockIdx.x * blockDim.x + threadIdx.x; i < total; i += gridDim.x * blockDim.x) {
        if (i < NB) g_cnt[i] = 0.f;
        else if (i < NB + NB * 3) g_psum[i - NB] = 0.f;
        else if (i < NB + NB * 3 + NB * HIDC) g_gsum[i - NB - NB * 3] = 0.f;
        else g_deg[i - NB - NB * 3 - NB * HIDC] = 0;
    }
}

__global__ void k_batch(const float* __restrict__ pos, const int* __restrict__ batch, int N) {
    int n = blockIdx.x * blockDim.x + threadIdx.x;
    if (n >= N) return;
    int b = batch[n];
    atomicAdd(&g_cnt[b], 1.f);
    atomicAdd(&g_psum[b * 3 + 0], pos[n * 3 + 0]);
    atomicAdd(&g_psum[b * 3 + 1], pos[n * 3 + 1]);
    atomicAdd(&g_psum[b * 3 + 2], pos[n * 3 + 2]);
}

__global__ void k_posc(const float* __restrict__ pos, const int* __restrict__ batch, int N) {
    int n = blockIdx.x * blockDim.x + threadIdx.x;
    if (n >= N) return;
    int b = batch[n];
    float c = fmaxf(g_cnt[b], 1.f);
    float inv = 1.f / c;
    g_posc[n * 3 + 0] = pos[n * 3 + 0] - g_psum[b * 3 + 0] * inv;
    g_posc[n * 3 + 1] = pos[n * 3 + 1] - g_psum[b * 3 + 1] * inv;
    g_posc[n * 3 + 2] = pos[n * 3 + 2] - g_psum[b * 3 + 2] * inv;
}

// ---------------- node embedding + input projection (tiled GEMM) ----------------
// 64 nodes/block, 256 threads, 4x4 register tiling. thread t: o0=(t&15)*4, n0l=(t>>4)*4.
__global__ void __launch_bounds__(256) k_embed(const int* __restrict__ zi,
        const float* __restrict__ atomw, const float* __restrict__ inw,
        const float* __restrict__ inb, int N) {
    __shared__ float wT[65 * 68];   // wT[i*68+o] = inw[o*65+i]  (i=64 row is vec weight)
    __shared__ float aT[64 * 68];   // aT[i*68+n] = atomw[z[n]][i]
    __shared__ float sb[64];
    __shared__ float sp[64 * 3];
    __shared__ int   sz[64];
    int tid = threadIdx.x;
    int n0 = blockIdx.x * 64;

    if (tid < 64) {
        int n = n0 + tid;
        sz[tid] = (n < N) ? zi[n] : 0;
        sb[tid] = inb[tid];
    }
    for (int idx = tid; idx < 64 * 3; idx += 256) {
        int n = n0 + idx / 3;
        sp[idx] = (n < N) ? g_posc[(size_t)n * 3 + (idx % 3)] : 0.f;
    }
    for (int idx = tid; idx < 64 * 65; idx += 256) {
        int o = idx / 65, i = idx % 65;
        wT[i * 68 + o] = inw[idx];
    }
    __syncthreads();
    for (int idx = tid; idx < 64 * 64; idx += 256) {
        int n = idx >> 6, i = idx & 63;
        aT[i * 68 + n] = atomw[(size_t)sz[n] * 64 + i];
    }
    __syncthreads();

    int o0 = (tid & 15) * 4;
    int nl = (tid >> 4) * 4;
    float acc[4][4];
    #pragma unroll
    for (int a = 0; a < 4; a++)
        #pragma unroll
        for (int b = 0; b < 4; b++) acc[a][b] = 0.f;

    #pragma unroll 4
    for (int i = 0; i < 64; i++) {
        float4 w = *(const float4*)&wT[i * 68 + o0];
        float4 a = *(const float4*)&aT[i * 68 + nl];
        acc[0][0] += a.x * w.x; acc[0][1] += a.x * w.y; acc[0][2] += a.x * w.z; acc[0][3] += a.x * w.w;
        acc[1][0] += a.y * w.x; acc[1][1] += a.y * w.y; acc[1][2] += a.y * w.z; acc[1][3] += a.y * w.w;
        acc[2][0] += a.z * w.x; acc[2][1] += a.z * w.y; acc[2][2] += a.z * w.z; acc[2][3] += a.z * w.w;
        acc[3][0] += a.w * w.x; acc[3][1] += a.w * w.y; acc[3][2] += a.w * w.z; acc[3][3] += a.w * w.w;
    }

    #pragma unroll
    for (int jj = 0; jj < 4; jj++) {
        int n = n0 + nl + jj;
        if (n >= N) break;
        float px = sp[(nl + jj) * 3], py = sp[(nl + jj) * 3 + 1], pz = sp[(nl + jj) * 3 + 2];
        #pragma unroll
        for (int cc = 0; cc < 4; cc++) {
            int o = o0 + cc;
            float vw = wT[64 * 68 + o];
            float4* hp = (float4*)(g_h + (size_t)n * 512 + o * 8);
            hp[0] = make_float4(acc[jj][cc] + sb[o], vw * px, vw * py, vw * pz);
            hp[1] = make_float4(0.f, 0.f, 0.f, 0.f);
        }
    }
}

// ---------------- edge RBF + MLP -> per-head scalar bias ----------------
__global__ void __launch_bounds__(128) k_edge(const float* __restrict__ pos,
        const int* __restrict__ src, const int* __restrict__ dst,
        const float* __restrict__ ew1, const float* __restrict__ eb1,
        const float* __restrict__ ew2, const float* __restrict__ eb2, int E) {
    __shared__ float s1[64 * 20];
    __shared__ float sb1[64];
    __shared__ float s2[4 * 64];
    __shared__ float sb2v[4];
    int tid = threadIdx.x;
    for (int i = tid; i < 1280; i += 128) s1[i] = ew1[i];
    if (tid < 64) sb1[tid] = eb1[tid];
    for (int i = tid; i < 256; i += 128) s2[i] = ew2[i];
    if (tid < 4) sb2v[tid] = eb2[tid];
    __syncthreads();
    int e = blockIdx.x * 128 + tid;
    if (e >= E) return;
    int s = src[e], d = dst[e];
    float dx = pos[s * 3] - pos[d * 3];
    float dy = pos[s * 3 + 1] - pos[d * 3 + 1];
    float dz = pos[s * 3 + 2] - pos[d * 3 + 2];
    float d2 = dx * dx + dy * dy + dz * dz;
    float dist = d2 > 0.f ? sqrtf(d2) : 0.f;
    const float width = 10.f / 19.f;
    const float invw = 19.f / 10.f;
    float rbf[20];
    #pragma unroll
    for (int k = 0; k < 20; k++) {
        float t = (dist - width * k) * invw;
        rbf[k] = __expf(-0.5f * t * t);
    }
    float a0 = 0.f, a1 = 0.f, a2 = 0.f, a3 = 0.f;
    for (int o = 0; o < 64; o++) {
        float hv = sb1[o];
        #pragma unroll
        for (int k = 0; k < 20; k++) hv += s1[o * 20 + k] * rbf[k];
        float sv = hv * sigmoidf(hv);
        a0 += s2[o] * sv; a1 += s2[64 + o] * sv; a2 += s2[128 + o] * sv; a3 += s2[192 + o] * sv;
    }
    ((float4*)g_es)[e] = make_float4(a0 + sb2v[0], a1 + sb2v[1], a2 + sb2v[2], a3 + sb2v[3]);
}

// ---------------- CSR by dst + permutation ----------------
__global__ void k_deg(const int* __restrict__ dst, int E) {
    int e = blockIdx.x * blockDim.x + threadIdx.x;
    if (e < E) atomicAdd(&g_deg[dst[e]], 1);
}

__global__ void __launch_bounds__(1024) k_scan(int N, int E) {
    __shared__ int part[1024];
    int tid = threadIdx.x;
    int per = (N + 1023) >> 10;
    int s0 = tid * per, s1 = min(s0 + per, N);
    int s = 0;
    for (int i = s0; i < s1; i++) s += g_deg[i];
    part[tid] = s;
    __syncthreads();
    for (int o = 1; o < 1024; o <<= 1) {
        int v = (tid >= o) ? part[tid - o] : 0;
        __syncthreads();
        part[tid] += v;
        __syncthreads();
    }
    int base = (tid == 0) ? 0 : part[tid - 1];
    for (int i = s0; i < s1; i++) { g_off[i] = base; g_cur[i] = base; base += g_deg[i]; }
    if (tid == 0) g_off[N] = E;
}

__global__ void k_fill(const int* __restrict__ dst, int E) {
    int e = blockIdx.x * blockDim.x + threadIdx.x;
    if (e < E) {
        int p = atomicAdd(&g_cur[dst[e]], 1);
        g_eid[p] = e;
    }
}

// one-time: permute src/dst/edge_scalar into CSR order (layer loop never touches g_eid)
__global__ void k_perm(const int* __restrict__ src, const int* __restrict__ dst, int E) {
    int p = blockIdx.x * blockDim.x + threadIdx.x;
    if (p >= E) return;
    int e = g_eid[p];
    g_srcp[p] = src[e];
    g_dstp[p] = dst[e];
    ((float4*)g_esp)[p] = ((const float4*)g_es)[e];
}

// ---------------- per-grade MVLinear ----------------
__global__ void __launch_bounds__(256) k_mvlin(const float* __restrict__ W,
        const float* __restrict__ B, int N) {
    extern __shared__ float sm[];
    float* Ws = sm;                  // 4*64*65 = 16640
    float* Xs = sm + 16640;          // 16*512 = 8192
    float* Bs = sm + 16640 + 8192;   // 64
    int tid = threadIdx.x;
    int n0 = blockIdx.x * 16;
    for (int idx = tid; idx < 16384; idx += 256) {
        int row = idx >> 6, i = idx & 63;
        Ws[row * 65 + i] = W[idx];
    }
    if (tid < 64) Bs[tid] = B[tid];
    for (int f = tid; f < 2048; f += 256) {
        int j = f >> 7, e4 = f & 127;
        int n = n0 + j;
        float4 v = (n < N) ? ((const float4*)g_h)[(size_t)n * 128 + e4]
                           : make_float4(0.f, 0.f, 0.f, 0.f);
        ((float4*)Xs)[j * 128 + e4] = v;
    }
    __syncthreads();
    int combo = tid & 127;
    int o = combo >> 1, half = combo & 1;
    int j0 = (tid >> 7) * 8;
    float acc[8][4];
    #pragma unroll
    for (int j = 0; j < 8; j++)
        #pragma unroll
        for (int c = 0; c < 4; c++) acc[j][c] = 0.f;
    const float* wrowA = Ws + ((half * 2) * 64 + o) * 65;
    const float* wrowB = wrowA + 64 * 65;
    #pragma unroll 4
    for (int i = 0; i < 64; i++) {
        float wA = wrowA[i];
        float wB = wrowB[i];
        float w0 = wA;
        float w1 = half ? wA : wB;
        float w2 = half ? wA : wB;
        float w3 = wB;
        #pragma unroll
        for (int j = 0; j < 8; j++) {
            float4 x = *(const float4*)&Xs[(j0 + j) * 512 + i * 8 + half * 4];
            acc[j][0] += w0 * x.x;
            acc[j][1] += w1 * x.y;
            acc[j][2] += w2 * x.z;
            acc[j][3] += w3 * x.w;
        }
    }
    float bb = (half == 0) ? Bs[o] : 0.f;
    #pragma unroll
    for (int j = 0; j < 8; j++) {
        int n = n0 + j0 + j;
        if (n < N) {
            float4 v = make_float4(acc[j][0] + bb, acc[j][1], acc[j][2], acc[j][3]);
            ((float4*)g_z)[(size_t)n * 128 + o * 2 + half] = v;
        }
    }
}

// ---------------- per-node attention logit contractions ----------------
__global__ void __launch_bounds__(128) k_sprep(const float* __restrict__ Asrc,
        const float* __restrict__ Adst, const float* __restrict__ Wsrc,
        const float* __restrict__ Wdst, int N) {
    int gw = (blockIdx.x * blockDim.x + threadIdx.x) >> 5;
    int lane = threadIdx.x & 31;
    if (gw >= N) return;
    int h = lane >> 3;
    const float4* zp = (const float4*)(g_z + (size_t)gw * 512 + lane * 16);
    float ws0 = Wsrc[h * 4 + 0], ws1 = Wsrc[h * 4 + 1], ws2 = Wsrc[h * 4 + 2], ws3 = Wsrc[h * 4 + 3];
    float wd0 = Wdst[h * 4 + 0], wd1 = Wdst[h * 4 + 1], wd2 = Wdst[h * 4 + 2], wd3 = Wdst[h * 4 + 3];
    float ps = 0.f, pd = 0.f;
    #pragma unroll
    for (int k4 = 0; k4 < 4; k4++) {
        float4 zv = zp[k4];
        int eb = lane * 16 + k4 * 4;
        float4 as = *(const float4*)(Asrc + eb);
        float4 ad = *(const float4*)(Adst + eb);
        if ((k4 & 1) == 0) {
            ps += zv.x * as.x * ws0 + zv.y * as.y * ws1 + zv.z * as.z * ws1 + zv.w * as.w * ws1;
            pd += zv.x * ad.x * wd0 + zv.y * ad.y * wd1 + zv.z * ad.z * wd1 + zv.w * ad.w * wd1;
        } else {
            ps += zv.x * as.x * ws2 + zv.y * as.y * ws2 + zv.z * as.z * ws2 + zv.w * as.w * ws3;
            pd += zv.x * ad.x * wd2 + zv.y * ad.y * wd2 + zv.z * ad.z * wd2 + zv.w * ad.w * wd3;
        }
    }
    #pragma unroll
    for (int o = 4; o; o >>= 1) {
        ps += __shfl_down_sync(0xffffffffu, ps, o);
        pd += __shfl_down_sync(0xffffffffu, pd, o);
    }
    if ((lane & 7) == 0) {
        g_ssrc[gw * 4 + h] = ps;
        g_sdst[gw * 4 + h] = pd;
    }
}

// ---------------- edge-parallel logits (CSR order, post-leakyrelu) ----------------
__global__ void __launch_bounds__(256) k_logit(int E) {
    int p = blockIdx.x * 256 + threadIdx.x;
    if (p >= E) return;
    int s = g_srcp[p], d = g_dstp[p];
    float4 ss = ((const float4*)g_ssrc)[s];
    float4 sd = ((const float4*)g_sdst)[d];
    float4 ev = ((const float4*)g_esp)[p];
    ((float4*)g_lg)[p] = make_float4(lrelu(ss.x + sd.x + ev.x),
                                     lrelu(ss.y + sd.y + ev.y),
                                     lrelu(ss.z + sd.z + ev.z),
                                     lrelu(ss.w + sd.w + ev.w));
}

// ---------------- fused attention + MVSiLU + residual + MVLayerNorm ----------------
__global__ void __launch_bounds__(128) k_attn(const float* __restrict__ sa,
        const float* __restrict__ sbp, const float* __restrict__ lna, int N) {
    __shared__ float sw[CHUNK * 4];
    __shared__ int sv[CHUNK];
    __shared__ float red[4];
    int n = blockIdx.x;
    int tid = threadIdx.x;
    int e0 = g_off[n];
    int deg = g_off[n + 1] - e0;

    // pass A: per-head max (contiguous stream)
    float mx0 = -3e38f, mx1 = -3e38f, mx2 = -3e38f, mx3 = -3e38f;
    for (int j = tid; j < deg; j += 128) {
        float4 lg = ((const float4*)g_lg)[e0 + j];
        mx0 = fmaxf(mx0, lg.x); mx1 = fmaxf(mx1, lg.y);
        mx2 = fmaxf(mx2, lg.z); mx3 = fmaxf(mx3, lg.w);
    }
    mx0 = blockMax4w(mx0, red);
    mx1 = blockMax4w(mx1, red);
    mx2 = blockMax4w(mx2, red);
    mx3 = blockMax4w(mx3, red);

    int head = tid >> 5;
    float ac0 = 0.f, ac1 = 0.f, ac2 = 0.f, ac3 = 0.f;
    float su0 = 0.f, su1 = 0.f, su2 = 0.f, su3 = 0.f;
    for (int base = 0; base < deg; base += CHUNK) {
        int m = min(CHUNK, deg - base);
        __syncthreads();
        for (int j = tid; j < m; j += 128) {
            sv[j] = g_srcp[e0 + base + j];
            float4 lg = ((const float4*)g_lg)[e0 + base + j];
            float w0 = __expf(lg.x - mx0); su0 += w0;
            float w1 = __expf(lg.y - mx1); su1 += w1;
            float w2 = __expf(lg.z - mx2); su2 += w2;
            float w3 = __expf(lg.w - mx3); su3 += w3;
            ((float4*)sw)[j] = make_float4(w0, w1, w2, w3);
        }
        __syncthreads();
        #pragma unroll 4
        for (int j = 0; j < m; j++) {
            float w = sw[j * 4 + head];
            float4 zv = *(const float4*)(g_z + (size_t)sv[j] * 512 + tid * 4);
            ac0 += w * zv.x; ac1 += w * zv.y; ac2 += w * zv.z; ac3 += w * zv.w;
        }
    }
    su0 = blockSum4w(su0, red);
    su1 = blockSum4w(su1, red);
    su2 = blockSum4w(su2, red);
    su3 = blockSum4w(su3, red);
    float tot = head == 0 ? su0 : head == 1 ? su1 : head == 2 ? su2 : su3;
    float inv = 1.f / (tot + 1e-16f);
    float x0 = ac0 * inv, x1 = ac1 * inv, x2 = ac2 * inv, x3 = ac3 * inv;

    // MVSiLU gating
    int c = tid >> 1;
    int hf = tid & 1;
    if (hf == 0) {
        float nA = x0;
        float nB = x1 * x1 + x2 * x2 + x3 * x3;
        float gA = sigmoidf(sa[c * 4 + 0] * nA + sbp[c * 4 + 0]);
        float gB = sigmoidf(sa[c * 4 + 1] * nB + sbp[c * 4 + 1]);
        x0 *= gA; x1 *= gB; x2 *= gB; x3 *= gB;
    } else {
        float nA = x0 * x0 + x1 * x1 + x2 * x2;
        float nB = x3 * x3;
        float gA = sigmoidf(sa[c * 4 + 2] * nA + sbp[c * 4 + 2]);
        float gB = sigmoidf(sa[c * 4 + 3] * nB + sbp[c * 4 + 3]);
        x0 *= gA; x1 *= gA; x2 *= gA; x3 *= gB;
    }

    // residual
    float4 r = *(const float4*)(g_h + (size_t)n * 512 + tid * 4);
    x0 += r.x; x1 += r.y; x2 += r.z; x3 += r.w;

    // MVLayerNorm
    float ssq = x0 * x0 + x1 * x1 + x2 * x2 + x3 * x3;
    ssq += __shfl_xor_sync(0xffffffffu, ssq, 1);
    float cn = sqrtf(ssq);
    float totn = blockSum4w(cn, red);
    float mean = totn * (1.f / 128.f) + 1e-6f;
    float scale = lna[c] / mean;
    *(float4*)(g_h + (size_t)n * 512 + tid * 4) =
        make_float4(x0 * scale, x1 * scale, x2 * scale, x3 * scale);
}

// ---------------- prepool (scalar blade) + graph pooling ----------------
__global__ void __launch_bounds__(64) k_prepool(const float* __restrict__ ppw,
        const float* __restrict__ ppb, const int* __restrict__ batch, int N) {
    __shared__ float x0[64];
    int n = blockIdx.x, tid = threadIdx.x;
    x0[tid] = g_h[(size_t)n * 512 + tid * 8];
    __syncthreads();
    float acc = ppb[tid];
    const float* wr = ppw + tid * 64;
    #pragma unroll 8
    for (int i = 0; i < 64; i++) acc += wr[i] * x0[i];
    atomicAdd(&g_gsum[batch[n] * 64 + tid], acc);
}

__global__ void __launch_bounds__(64) k_post(const float* __restrict__ pw1,
        const float* __restrict__ pb1, const float* __restrict__ pw2,
        const float* __restrict__ pb2, float* __restrict__ out) {
    __shared__ float sg[64];
    __shared__ float sh[64];
    int b = blockIdx.x, tid = threadIdx.x;
    sg[tid] = g_gsum[b * 64 + tid];
    __syncthreads();
    float a = pb1[tid];
    const float* wr = pw1 + tid * 64;
    #pragma unroll 8
    for (int i = 0; i < 64; i++) a += wr[i] * sg[i];
    float s = a * sigmoidf(a);
    sh[tid] = s * pw2[tid];
    __syncthreads();
    for (int st = 32; st; st >>= 1) {
        if (tid < st) sh[tid] += sh[tid + st];
        __syncthreads();
    }
    if (tid == 0) out[b] = sh[0] + pb2[0];
}

// ---------------- launch ----------------
extern "C" void kernel_launch(void* const* d_in, const int* in_sizes, int n_in,
                              void* d_out, int out_size) {
    const float* pos   = (const float*)d_in[0];
    const int*   zi    = (const int*)d_in[1];
    const int*   ei    = (const int*)d_in[2];
    const int*   batch = (const int*)d_in[3];
    const float* atomw = (const float*)d_in[4];
    const float* inw   = (const float*)d_in[5];
    const float* inb   = (const float*)d_in[6];
    const float* ew1   = (const float*)d_in[7];
    const float* eb1   = (const float*)d_in[8];
    const float* ew2   = (const float*)d_in[9];
    const float* eb2   = (const float*)d_in[10];
    const float* projw = (const float*)d_in[11];
    const float* projb = (const float*)d_in[12];
    const float* asrc  = (const float*)d_in[13];
    const float* adst  = (const float*)d_in[14];
    const float* wsrc  = (const float*)d_in[15];
    const float* wdst  = (const float*)d_in[16];
    const float* lna   = (const float*)d_in[17];
    const float* silua = (const float*)d_in[18];
    const float* silub = (const float*)d_in[19];
    const float* ppw   = (const float*)d_in[20];
    const float* ppb   = (const float*)d_in[21];
    const float* pw1   = (const float*)d_in[22];
    const float* pb1   = (const float*)d_in[23];
    const float* pw2   = (const float*)d_in[24];
    const float* pb2   = (const float*)d_in[25];
    float* out = (float*)d_out;

    int N = in_sizes[0] / 3;
    int E = in_sizes[2] / 2;
    const int* src = ei;
    const int* dst = ei + E;

    cudaFuncSetAttribute(k_mvlin, cudaFuncAttributeMaxDynamicSharedMemorySize, 99584);

    k_zero<<<64, 256>>>(N);
    k_batch<<<(N + 255) / 256, 256>>>(pos, batch, N);
    k_posc<<<(N + 255) / 256, 256>>>(pos, batch, N);
    k_embed<<<(N + 63) / 64, 256>>>(zi, atomw, inw, inb, N);
    k_edge<<<(E + 127) / 128, 128>>>(pos, src, dst, ew1, eb1, ew2, eb2, E);
    k_deg<<<(E + 255) / 256, 256>>>(dst, E);
    k_scan<<<1, 1024>>>(N, E);
    k_fill<<<(E + 255) / 256, 256>>>(dst, E);
    k_perm<<<(E + 255) / 256, 256>>>(src, dst, E);

    for (int l = 0; l < 4; l++) {
        k_mvlin<<<(N + 15) / 16, 256, 99584>>>(projw + (size_t)l * 4 * 64 * 64,
                                               projb + l * 64, N);
        k_sprep<<<(N + 3) / 4, 128>>>(asrc + l * 512, adst + l * 512,
                                      wsrc + l * 16, wdst + l * 16, N);
        k_logit<<<(E + 255) / 256, 256>>>(E);
        k_attn<<<N, 128>>>(silua + l * 256, silub + l * 256, lna + l * 64, N);
    }

    k_prepool<<<N, 64>>>(ppw, ppb, batch, N);
    k_post<<<NB, 64>>>(pw1, pb1, pw2, pb2, out);
}

// round 4
// speedup vs baseline: 1.0832x; 1.0107x over previous
#include <cuda_runtime.h>
#include <math.h>

#define NN 20000
#define EE 320000
#define NB 256
#define HIDC 64
#define STASH 1024

// ---------------- scratch (device globals; no allocation) ----------------
__device__ float g_h[(size_t)NN * 512];
__device__ float g_z[(size_t)NN * 512];
__device__ float g_esp[(size_t)EE * 4];   // edge scalar, CSR order
__device__ int   g_srcp[EE];              // src, CSR order
__device__ float g_ssrc[NN * 4];
__device__ float g_sdst[NN * 4];
__device__ float g_cnt[NB];
__device__ float g_psum[NB * 3];
__device__ int   g_deg[NN];
__device__ int   g_off[NN + 1];
__device__ int   g_cur[NN];
__device__ float g_gsum[NB * HIDC];

// ---------------- helpers ----------------
__device__ __forceinline__ float lrelu(float v) { return v > 0.f ? v : 0.2f * v; }
__device__ __forceinline__ float sigmoidf(float v) { return 1.f / (1.f + __expf(-v)); }

// ---------------- 0: zero scratch ----------------
__global__ void k_zero(int N) {
    int total = NB + NB * 3 + NB * HIDC + N;
    for (int i = blockIdx.x * blockDim.x + threadIdx.x; i < total; i += gridDim.x * blockDim.x) {
        if (i < NB) g_cnt[i] = 0.f;
        else if (i < NB + NB * 3) g_psum[i - NB] = 0.f;
        else if (i < NB + NB * 3 + NB * HIDC) g_gsum[i - NB - NB * 3] = 0.f;
        else g_deg[i - NB - NB * 3 - NB * HIDC] = 0;
    }
}

// ---------------- 1: batch stats + degree count ----------------
__global__ void k_init(const float* __restrict__ pos, const int* __restrict__ batch,
                       const int* __restrict__ dst, int N, int E) {
    int i = blockIdx.x * blockDim.x + threadIdx.x;
    if (i < N) {
        int b = batch[i];
        atomicAdd(&g_cnt[b], 1.f);
        atomicAdd(&g_psum[b * 3 + 0], pos[i * 3 + 0]);
        atomicAdd(&g_psum[b * 3 + 1], pos[i * 3 + 1]);
        atomicAdd(&g_psum[b * 3 + 2], pos[i * 3 + 2]);
    }
    if (i < E) atomicAdd(&g_deg[dst[i]], 1);
}

// ---------------- 2: exclusive scan -> CSR offsets ----------------
__global__ void __launch_bounds__(1024) k_scan(int N, int E) {
    __shared__ int part[1024];
    int tid = threadIdx.x;
    int per = (N + 1023) >> 10;
    int s0 = tid * per, s1 = min(s0 + per, N);
    int s = 0;
    for (int i = s0; i < s1; i++) s += g_deg[i];
    part[tid] = s;
    __syncthreads();
    for (int o = 1; o < 1024; o <<= 1) {
        int v = (tid >= o) ? part[tid - o] : 0;
        __syncthreads();
        part[tid] += v;
        __syncthreads();
    }
    int base = (tid == 0) ? 0 : part[tid - 1];
    for (int i = s0; i < s1; i++) { g_off[i] = base; g_cur[i] = base; base += g_deg[i]; }
    if (tid == 0) g_off[N] = E;
}

// ---------------- 3: edge RBF-MLP + direct CSR scatter ----------------
__global__ void __launch_bounds__(128) k_edgefill(const float* __restrict__ pos,
        const int* __restrict__ src, const int* __restrict__ dst,
        const float* __restrict__ ew1, const float* __restrict__ eb1,
        const float* __restrict__ ew2, const float* __restrict__ eb2, int E) {
    __shared__ float s1[64 * 20];     // rows of 20 floats = 80B (16B aligned)
    __shared__ float sb1[64];
    __shared__ float s2[4 * 64];
    __shared__ float sb2v[4];
    int tid = threadIdx.x;
    for (int i = tid; i < 1280; i += 128) s1[i] = ew1[i];
    if (tid < 64) sb1[tid] = eb1[tid];
    for (int i = tid; i < 256; i += 128) s2[i] = ew2[i];
    if (tid < 4) sb2v[tid] = eb2[tid];
    __syncthreads();
    int e = blockIdx.x * 128 + tid;
    if (e >= E) return;
    int s = src[e], d = dst[e];
    float dx = pos[s * 3] - pos[d * 3];
    float dy = pos[s * 3 + 1] - pos[d * 3 + 1];
    float dz = pos[s * 3 + 2] - pos[d * 3 + 2];
    float d2 = dx * dx + dy * dy + dz * dz;
    float dist = d2 > 0.f ? sqrtf(d2) : 0.f;
    const float width = 10.f / 19.f;
    const float invw = 19.f / 10.f;
    float rbf[20];
    #pragma unroll
    for (int k = 0; k < 20; k++) {
        float t = (dist - width * k) * invw;
        rbf[k] = __expf(-0.5f * t * t);
    }
    float a0 = 0.f, a1 = 0.f, a2 = 0.f, a3 = 0.f;
    for (int o = 0; o < 64; o++) {
        float hv = sb1[o];
        const float4* w4 = (const float4*)&s1[o * 20];
        #pragma unroll
        for (int q = 0; q < 5; q++) {
            float4 w = w4[q];
            hv += w.x * rbf[q * 4] + w.y * rbf[q * 4 + 1] + w.z * rbf[q * 4 + 2] + w.w * rbf[q * 4 + 3];
        }
        float sv = hv * sigmoidf(hv);
        a0 += s2[o] * sv; a1 += s2[64 + o] * sv; a2 += s2[128 + o] * sv; a3 += s2[192 + o] * sv;
    }
    int p = atomicAdd(&g_cur[d], 1);
    g_srcp[p] = s;
    ((float4*)g_esp)[p] = make_float4(a0 + sb2v[0], a1 + sb2v[1], a2 + sb2v[2], a3 + sb2v[3]);
}

// ---------------- 4: node embedding + input proj (32 nodes/block) ----------------
__global__ void __launch_bounds__(256) k_embed(const int* __restrict__ zi,
        const int* __restrict__ batch, const float* __restrict__ pos,
        const float* __restrict__ atomw, const float* __restrict__ inw,
        const float* __restrict__ inb, int N) {
    __shared__ float wT[65 * 68];   // wT[i*68+o] = inw[o*65+i]
    __shared__ float aT[64 * 36];   // aT[i*36+n]
    __shared__ float sb[64];
    __shared__ float spx[32], spy[32], spz[32];
    __shared__ int   sz[32];
    int tid = threadIdx.x;
    int n0 = blockIdx.x * 32;

    if (tid < 32) {
        int n = n0 + tid;
        if (n < N) {
            int b = batch[n];
            float ic = 1.f / fmaxf(g_cnt[b], 1.f);
            spx[tid] = pos[n * 3 + 0] - g_psum[b * 3 + 0] * ic;
            spy[tid] = pos[n * 3 + 1] - g_psum[b * 3 + 1] * ic;
            spz[tid] = pos[n * 3 + 2] - g_psum[b * 3 + 2] * ic;
            sz[tid] = zi[n];
        } else { spx[tid] = spy[tid] = spz[tid] = 0.f; sz[tid] = 0; }
    }
    if (tid >= 32 && tid < 96) sb[tid - 32] = inb[tid - 32];
    for (int idx = tid; idx < 64 * 65; idx += 256) {
        int o = idx / 65, i = idx % 65;
        wT[i * 68 + o] = inw[idx];
    }
    __syncthreads();
    for (int idx = tid; idx < 64 * 32; idx += 256) {
        int n = idx & 31, i = idx >> 5;
        aT[i * 36 + n] = atomw[(size_t)sz[n] * 64 + i];
    }
    __syncthreads();

    int ox = (tid & 15) * 4;
    int nl = (tid >> 4) * 2;
    float acc[2][4];
    #pragma unroll
    for (int a = 0; a < 2; a++)
        #pragma unroll
        for (int b = 0; b < 4; b++) acc[a][b] = 0.f;

    #pragma unroll 8
    for (int i = 0; i < 64; i++) {
        float4 w = *(const float4*)&wT[i * 68 + ox];
        float2 a = *(const float2*)&aT[i * 36 + nl];
        acc[0][0] += a.x * w.x; acc[0][1] += a.x * w.y; acc[0][2] += a.x * w.z; acc[0][3] += a.x * w.w;
        acc[1][0] += a.y * w.x; acc[1][1] += a.y * w.y; acc[1][2] += a.y * w.z; acc[1][3] += a.y * w.w;
    }

    #pragma unroll
    for (int jj = 0; jj < 2; jj++) {
        int n = n0 + nl + jj;
        if (n >= N) break;
        float px = spx[nl + jj], py = spy[nl + jj], pz = spz[nl + jj];
        #pragma unroll
        for (int cc = 0; cc < 4; cc++) {
            int o = ox + cc;
            float vw = wT[64 * 68 + o];
            float4* hp = (float4*)(g_h + (size_t)n * 512 + o * 8);
            hp[0] = make_float4(acc[jj][cc] + sb[o], vw * px, vw * py, vw * pz);
            hp[1] = make_float4(0.f, 0.f, 0.f, 0.f);
        }
    }
}

// ---------------- per-grade MVLinear + fused sprep epilogue ----------------
__global__ void __launch_bounds__(256) k_mvlin(const float* __restrict__ W,
        const float* __restrict__ B, const float* __restrict__ Asrc,
        const float* __restrict__ Adst, const float* __restrict__ Wsrc,
        const float* __restrict__ Wdst, int N) {
    extern __shared__ float sm[];
    float* Ws = sm;                  // 4*64*65 = 16640
    float* Xs = sm + 16640;          // 16*512 = 8192
    float* Bs = sm + 16640 + 8192;   // 64
    int tid = threadIdx.x;
    int n0 = blockIdx.x * 16;
    for (int idx = tid; idx < 16384; idx += 256) {
        int row = idx >> 6, i = idx & 63;
        Ws[row * 65 + i] = W[idx];
    }
    if (tid < 64) Bs[tid] = B[tid];
    for (int f = tid; f < 2048; f += 256) {
        int j = f >> 7, e4 = f & 127;
        int n = n0 + j;
        float4 v = (n < N) ? ((const float4*)g_h)[(size_t)n * 128 + e4]
                           : make_float4(0.f, 0.f, 0.f, 0.f);
        ((float4*)Xs)[j * 128 + e4] = v;
    }
    __syncthreads();
    int combo = tid & 127;
    int o = combo >> 1, half = combo & 1;
    int j0 = (tid >> 7) * 8;
    float acc[8][4];
    #pragma unroll
    for (int j = 0; j < 8; j++)
        #pragma unroll
        for (int c = 0; c < 4; c++) acc[j][c] = 0.f;
    const float* wrowA = Ws + ((half * 2) * 64 + o) * 65;
    const float* wrowB = wrowA + 64 * 65;
    #pragma unroll 4
    for (int i = 0; i < 64; i++) {
        float wA = wrowA[i];
        float wB = wrowB[i];
        float w0 = wA;
        float w1 = half ? wA : wB;
        float w2 = half ? wA : wB;
        float w3 = wB;
        #pragma unroll
        for (int j = 0; j < 8; j++) {
            float4 x = *(const float4*)&Xs[(j0 + j) * 512 + i * 8 + half * 4];
            acc[j][0] += w0 * x.x;
            acc[j][1] += w1 * x.y;
            acc[j][2] += w2 * x.z;
            acc[j][3] += w3 * x.w;
        }
    }
    // fold attention contraction vectors for this thread's (o, half)
    int h = o >> 4, c = o & 15;
    const float* Ab = Asrc + ((h * 16 + c) * 8) + half * 4;
    const float* Db = Adst + ((h * 16 + c) * 8) + half * 4;
    float wsA, wsB, wdA, wdB;
    if (half == 0) { wsA = Wsrc[h * 4 + 0]; wsB = Wsrc[h * 4 + 1];
                     wdA = Wdst[h * 4 + 0]; wdB = Wdst[h * 4 + 1]; }
    else           { wsA = Wsrc[h * 4 + 2]; wsB = Wsrc[h * 4 + 3];
                     wdA = Wdst[h * 4 + 2]; wdB = Wdst[h * 4 + 3]; }
    // half0 blades 0..3: grades {A,B,B,B}; half1 blades 4..7: grades {A,A,A,B}
    float avs0, avs1, avs2, avs3, avd0, avd1, avd2, avd3;
    if (half == 0) {
        avs0 = Ab[0] * wsA; avs1 = Ab[1] * wsB; avs2 = Ab[2] * wsB; avs3 = Ab[3] * wsB;
        avd0 = Db[0] * wdA; avd1 = Db[1] * wdB; avd2 = Db[2] * wdB; avd3 = Db[3] * wdB;
    } else {
        avs0 = Ab[0] * wsA; avs1 = Ab[1] * wsA; avs2 = Ab[2] * wsA; avs3 = Ab[3] * wsB;
        avd0 = Db[0] * wdA; avd1 = Db[1] * wdA; avd2 = Db[2] * wdA; avd3 = Db[3] * wdB;
    }
    float bb = (half == 0) ? Bs[o] : 0.f;
    int lane = tid & 31;
    int hwarp = (tid >> 5) & 3;
    #pragma unroll
    for (int j = 0; j < 8; j++) {
        int n = n0 + j0 + j;
        float v0 = acc[j][0] + bb, v1 = acc[j][1], v2 = acc[j][2], v3 = acc[j][3];
        if (n < N)
            ((float4*)g_z)[(size_t)n * 128 + o * 2 + half] = make_float4(v0, v1, v2, v3);
        float ps = v0 * avs0 + v1 * avs1 + v2 * avs2 + v3 * avs3;
        float pd = v0 * avd0 + v1 * avd1 + v2 * avd2 + v3 * avd3;
        #pragma unroll
        for (int off = 16; off; off >>= 1) {
            ps += __shfl_xor_sync(0xffffffffu, ps, off);
            pd += __shfl_xor_sync(0xffffffffu, pd, off);
        }
        if (lane == 0 && n < N) {
            g_ssrc[n * 4 + hwarp] = ps;
            g_sdst[n * 4 + hwarp] = pd;
        }
    }
}

// ---------------- fused attention (inline logits) + MVSiLU + residual + LN ----------------
__global__ void __launch_bounds__(128) k_attn(const float* __restrict__ sa,
        const float* __restrict__ sbp, const float* __restrict__ lna, int N) {
    __shared__ float4 slg[STASH];
    __shared__ int    ssv[STASH];
    __shared__ float4 red4[4];
    int n = blockIdx.x;
    int tid = threadIdx.x;
    int lane = tid & 31, wid = tid >> 5;
    int e0 = g_off[n];
    int deg = g_off[n + 1] - e0;
    float4 sd = ((const float4*)g_sdst)[n];

    float4 mx = make_float4(-3e38f, -3e38f, -3e38f, -3e38f);
    bool fits = (deg <= STASH);

    // sweep 1: compute logits (stash if fits), track max
    for (int j = tid; j < deg; j += 128) {
        int s = g_srcp[e0 + j];
        float4 ss = ((const float4*)g_ssrc)[s];
        float4 ev = ((const float4*)g_esp)[e0 + j];
        float4 lg = make_float4(lrelu(ss.x + sd.x + ev.x), lrelu(ss.y + sd.y + ev.y),
                                lrelu(ss.z + sd.z + ev.z), lrelu(ss.w + sd.w + ev.w));
        if (fits) { slg[j] = lg; ssv[j] = s; }
        mx.x = fmaxf(mx.x, lg.x); mx.y = fmaxf(mx.y, lg.y);
        mx.z = fmaxf(mx.z, lg.z); mx.w = fmaxf(mx.w, lg.w);
    }
    // block max reduce (float4)
    #pragma unroll
    for (int off = 16; off; off >>= 1) {
        mx.x = fmaxf(mx.x, __shfl_xor_sync(0xffffffffu, mx.x, off));
        mx.y = fmaxf(mx.y, __shfl_xor_sync(0xffffffffu, mx.y, off));
        mx.z = fmaxf(mx.z, __shfl_xor_sync(0xffffffffu, mx.z, off));
        mx.w = fmaxf(mx.w, __shfl_xor_sync(0xffffffffu, mx.w, off));
    }
    if (lane == 0) red4[wid] = mx;
    __syncthreads();
    {
        float4 a = red4[0], b = red4[1], c = red4[2], d = red4[3];
        mx.x = fmaxf(fmaxf(a.x, b.x), fmaxf(c.x, d.x));
        mx.y = fmaxf(fmaxf(a.y, b.y), fmaxf(c.y, d.y));
        mx.z = fmaxf(fmaxf(a.z, b.z), fmaxf(c.z, d.z));
        mx.w = fmaxf(fmaxf(a.w, b.w), fmaxf(c.w, d.w));
    }
    __syncthreads();

    int head = wid;
    float4 su = make_float4(0.f, 0.f, 0.f, 0.f);
    float ac0 = 0.f, ac1 = 0.f, ac2 = 0.f, ac3 = 0.f;

    if (fits) {
        // sweep 2: exp in place + sum
        for (int j = tid; j < deg; j += 128) {
            float4 lg = slg[j];
            lg.x = __expf(lg.x - mx.x); lg.y = __expf(lg.y - mx.y);
            lg.z = __expf(lg.z - mx.z); lg.w = __expf(lg.w - mx.w);
            su.x += lg.x; su.y += lg.y; su.z += lg.z; su.w += lg.w;
            slg[j] = lg;
        }
    } else {
        for (int j = tid; j < deg; j += 128) {
            int s = g_srcp[e0 + j];
            float4 ss = ((const float4*)g_ssrc)[s];
            float4 ev = ((const float4*)g_esp)[e0 + j];
            su.x += __expf(lrelu(ss.x + sd.x + ev.x) - mx.x);
            su.y += __expf(lrelu(ss.y + sd.y + ev.y) - mx.y);
            su.z += __expf(lrelu(ss.z + sd.z + ev.z) - mx.z);
            su.w += __expf(lrelu(ss.w + sd.w + ev.w) - mx.w);
        }
    }
    #pragma unroll
    for (int off = 16; off; off >>= 1) {
        su.x += __shfl_xor_sync(0xffffffffu, su.x, off);
        su.y += __shfl_xor_sync(0xffffffffu, su.y, off);
        su.z += __shfl_xor_sync(0xffffffffu, su.z, off);
        su.w += __shfl_xor_sync(0xffffffffu, su.w, off);
    }
    if (lane == 0) red4[wid] = su;
    __syncthreads();
    {
        float4 a = red4[0], b = red4[1], c = red4[2], d = red4[3];
        su.x = a.x + b.x + c.x + d.x;
        su.y = a.y + b.y + c.y + d.y;
        su.z = a.z + b.z + c.z + d.z;
        su.w = a.w + b.w + c.w + d.w;
    }

    if (fits) {
        const float* slgS = (const float*)slg;
        int j = 0;
        for (; j + 4 <= deg; j += 4) {
            float w0 = slgS[(j + 0) * 4 + head];
            float w1 = slgS[(j + 1) * 4 + head];
            float w2 = slgS[(j + 2) * 4 + head];
            float w3 = slgS[(j + 3) * 4 + head];
            float4 z0 = *(const float4*)(g_z + (size_t)ssv[j + 0] * 512 + tid * 4);
            float4 z1 = *(const float4*)(g_z + (size_t)ssv[j + 1] * 512 + tid * 4);
            float4 z2 = *(const float4*)(g_z + (size_t)ssv[j + 2] * 512 + tid * 4);
            float4 z3 = *(const float4*)(g_z + (size_t)ssv[j + 3] * 512 + tid * 4);
            ac0 += w0 * z0.x + w1 * z1.x + w2 * z2.x + w3 * z3.x;
            ac1 += w0 * z0.y + w1 * z1.y + w2 * z2.y + w3 * z3.y;
            ac2 += w0 * z0.z + w1 * z1.z + w2 * z2.z + w3 * z3.z;
            ac3 += w0 * z0.w + w1 * z1.w + w2 * z2.w + w3 * z3.w;
        }
        for (; j < deg; j++) {
            float w = slgS[j * 4 + head];
            float4 zv = *(const float4*)(g_z + (size_t)ssv[j] * 512 + tid * 4);
            ac0 += w * zv.x; ac1 += w * zv.y; ac2 += w * zv.z; ac3 += w * zv.w;
        }
    } else {
        // chunked recompute path
        for (int base = 0; base < deg; base += STASH) {
            int m = min(STASH, deg - base);
            __syncthreads();
            for (int j = tid; j < m; j += 128) {
                int s = g_srcp[e0 + base + j];
                float4 ss = ((const float4*)g_ssrc)[s];
                float4 ev = ((const float4*)g_esp)[e0 + base + j];
                slg[j] = make_float4(__expf(lrelu(ss.x + sd.x + ev.x) - mx.x),
                                     __expf(lrelu(ss.y + sd.y + ev.y) - mx.y),
                                     __expf(lrelu(ss.z + sd.z + ev.z) - mx.z),
                                     __expf(lrelu(ss.w + sd.w + ev.w) - mx.w));
                ssv[j] = s;
            }
            __syncthreads();
            const float* slgS = (const float*)slg;
            for (int j = 0; j < m; j++) {
                float w = slgS[j * 4 + head];
                float4 zv = *(const float4*)(g_z + (size_t)ssv[j] * 512 + tid * 4);
                ac0 += w * zv.x; ac1 += w * zv.y; ac2 += w * zv.z; ac3 += w * zv.w;
            }
        }
    }

    float tot = head == 0 ? su.x : head == 1 ? su.y : head == 2 ? su.z : su.w;
    float inv = 1.f / (tot + 1e-16f);
    float x0 = ac0 * inv, x1 = ac1 * inv, x2 = ac2 * inv, x3 = ac3 * inv;

    // MVSiLU gating
    int c = tid >> 1;
    int hf = tid & 1;
    if (hf == 0) {
        float nA = x0;
        float nB = x1 * x1 + x2 * x2 + x3 * x3;
        float gA = sigmoidf(sa[c * 4 + 0] * nA + sbp[c * 4 + 0]);
        float gB = sigmoidf(sa[c * 4 + 1] * nB + sbp[c * 4 + 1]);
        x0 *= gA; x1 *= gB; x2 *= gB; x3 *= gB;
    } else {
        float nA = x0 * x0 + x1 * x1 + x2 * x2;
        float nB = x3 * x3;
        float gA = sigmoidf(sa[c * 4 + 2] * nA + sbp[c * 4 + 2]);
        float gB = sigmoidf(sa[c * 4 + 3] * nB + sbp[c * 4 + 3]);
        x0 *= gA; x1 *= gA; x2 *= gA; x3 *= gB;
    }

    // residual
    float4 r = *(const float4*)(g_h + (size_t)n * 512 + tid * 4);
    x0 += r.x; x1 += r.y; x2 += r.z; x3 += r.w;

    // MVLayerNorm
    float ssq = x0 * x0 + x1 * x1 + x2 * x2 + x3 * x3;
    ssq += __shfl_xor_sync(0xffffffffu, ssq, 1);
    float cn = sqrtf(ssq);
    #pragma unroll
    for (int off = 16; off; off >>= 1) cn += __shfl_xor_sync(0xffffffffu, cn, off);
    __syncthreads();
    if (lane == 0) red4[wid].x = cn;
    __syncthreads();
    float totn = red4[0].x + red4[1].x + red4[2].x + red4[3].x;
    float mean = totn * (1.f / 128.f) + 1e-6f;
    float scale = lna[c] / mean;
    *(float4*)(g_h + (size_t)n * 512 + tid * 4) =
        make_float4(x0 * scale, x1 * scale, x2 * scale, x3 * scale);
}

// ---------------- prepool (scalar blade) + graph pooling ----------------
__global__ void __launch_bounds__(64) k_prepool(const float* __restrict__ ppw,
        const float* __restrict__ ppb, const int* __restrict__ batch, int N) {
    __shared__ float x0[64];
    int n = blockIdx.x, tid = threadIdx.x;
    x0[tid] = g_h[(size_t)n * 512 + tid * 8];
    __syncthreads();
    float acc = ppb[tid];
    const float* wr = ppw + tid * 64;
    #pragma unroll 8
    for (int i = 0; i < 64; i++) acc += wr[i] * x0[i];
    atomicAdd(&g_gsum[batch[n] * 64 + tid], acc);
}

__global__ void __launch_bounds__(64) k_post(const float* __restrict__ pw1,
        const float* __restrict__ pb1, const float* __restrict__ pw2,
        const float* __restrict__ pb2, float* __restrict__ out) {
    __shared__ float sg[64];
    __shared__ float sh[64];
    int b = blockIdx.x, tid = threadIdx.x;
    sg[tid] = g_gsum[b * 64 + tid];
    __syncthreads();
    float a = pb1[tid];
    const float* wr = pw1 + tid * 64;
    #pragma unroll 8
    for (int i = 0; i < 64; i++) a += wr[i] * sg[i];
    float s = a * sigmoidf(a);
    sh[tid] = s * pw2[tid];
    __syncthreads();
    for (int st = 32; st; st >>= 1) {
        if (tid < st) sh[tid] += sh[tid + st];
        __syncthreads();
    }
    if (tid == 0) out[b] = sh[0] + pb2[0];
}

// ---------------- launch ----------------
extern "C" void kernel_launch(void* const* d_in, const int* in_sizes, int n_in,
                              void* d_out, int out_size) {
    const float* pos   = (const float*)d_in[0];
    const int*   zi    = (const int*)d_in[1];
    const int*   ei    = (const int*)d_in[2];
    const int*   batch = (const int*)d_in[3];
    const float* atomw = (const float*)d_in[4];
    const float* inw   = (const float*)d_in[5];
    const float* inb   = (const float*)d_in[6];
    const float* ew1   = (const float*)d_in[7];
    const float* eb1   = (const float*)d_in[8];
    const float* ew2   = (const float*)d_in[9];
    const float* eb2   = (const float*)d_in[10];
    const float* projw = (const float*)d_in[11];
    const float* projb = (const float*)d_in[12];
    const float* asrc  = (const float*)d_in[13];
    const float* adst  = (const float*)d_in[14];
    const float* wsrc  = (const float*)d_in[15];
    const float* wdst  = (const float*)d_in[16];
    const float* lna   = (const float*)d_in[17];
    const float* silua = (const float*)d_in[18];
    const float* silub = (const float*)d_in[19];
    const float* ppw   = (const float*)d_in[20];
    const float* ppb   = (const float*)d_in[21];
    const float* pw1   = (const float*)d_in[22];
    const float* pb1   = (const float*)d_in[23];
    const float* pw2   = (const float*)d_in[24];
    const float* pb2   = (const float*)d_in[25];
    float* out = (float*)d_out;

    int N = in_sizes[0] / 3;
    int E = in_sizes[2] / 2;
    const int* src = ei;
    const int* dst = ei + E;

    cudaFuncSetAttribute(k_mvlin, cudaFuncAttributeMaxDynamicSharedMemorySize, 99584);

    k_zero<<<64, 256>>>(N);
    k_init<<<(E + 255) / 256, 256>>>(pos, batch, dst, N, E);
    k_scan<<<1, 1024>>>(N, E);
    k_edgefill<<<(E + 127) / 128, 128>>>(pos, src, dst, ew1, eb1, ew2, eb2, E);
    k_embed<<<(N + 31) / 32, 256>>>(zi, batch, pos, atomw, inw, inb, N);

    for (int l = 0; l < 4; l++) {
        k_mvlin<<<(N + 15) / 16, 256, 99584>>>(projw + (size_t)l * 4 * 64 * 64,
                                               projb + l * 64,
                                               asrc + l * 512, adst + l * 512,
                                               wsrc + l * 16, wdst + l * 16, N);
        k_attn<<<N, 128>>>(silua + l * 256, silub + l * 256, lna + l * 64, N);
    }

    k_prepool<<<N, 64>>>(ppw, ppb, batch, N);
    k_post<<<NB, 64>>>(pw1, pb1, pw2, pb2, out);
}

// round 5
// speedup vs baseline: 1.1194x; 1.0334x over previous
#include <cuda_runtime.h>
#include <math.h>

#define NN 20000
#define EE 320000
#define NB 256
#define HIDC 64

// ---------------- scratch (device globals; no allocation) ----------------
__device__ float g_h[(size_t)NN * 512];
__device__ float g_z[(size_t)NN * 512];
__device__ float g_esp[(size_t)EE * 4];   // edge scalar, CSR order
__device__ int   g_srcp[EE];              // src, CSR order
__device__ float g_ssrc[NN * 4];
__device__ float g_sdst[NN * 4];
__device__ float g_cnt[NB];
__device__ float g_psum[NB * 3];
__device__ int   g_deg[NN];
__device__ int   g_off[NN + 1];
__device__ int   g_cur[NN];
__device__ float g_gsum[NB * HIDC];

// ---------------- helpers ----------------
__device__ __forceinline__ float lrelu(float v) { return v > 0.f ? v : 0.2f * v; }
__device__ __forceinline__ float sigmoidf(float v) { return 1.f / (1.f + __expf(-v)); }

// ---------------- 0: zero scratch ----------------
__global__ void k_zero(int N) {
    int total = NB + NB * 3 + NB * HIDC + N;
    for (int i = blockIdx.x * blockDim.x + threadIdx.x; i < total; i += gridDim.x * blockDim.x) {
        if (i < NB) g_cnt[i] = 0.f;
        else if (i < NB + NB * 3) g_psum[i - NB] = 0.f;
        else if (i < NB + NB * 3 + NB * HIDC) g_gsum[i - NB - NB * 3] = 0.f;
        else g_deg[i - NB - NB * 3 - NB * HIDC] = 0;
    }
}

// ---------------- 1: batch stats + degree count ----------------
__global__ void k_init(const float* __restrict__ pos, const int* __restrict__ batch,
                       const int* __restrict__ dst, int N, int E) {
    int i = blockIdx.x * blockDim.x + threadIdx.x;
    if (i < N) {
        int b = batch[i];
        atomicAdd(&g_cnt[b], 1.f);
        atomicAdd(&g_psum[b * 3 + 0], pos[i * 3 + 0]);
        atomicAdd(&g_psum[b * 3 + 1], pos[i * 3 + 1]);
        atomicAdd(&g_psum[b * 3 + 2], pos[i * 3 + 2]);
    }
    if (i < E) atomicAdd(&g_deg[dst[i]], 1);
}

// ---------------- 2: exclusive scan -> CSR offsets ----------------
__global__ void __launch_bounds__(1024) k_scan(int N, int E) {
    __shared__ int part[1024];
    int tid = threadIdx.x;
    int per = (N + 1023) >> 10;
    int s0 = tid * per, s1 = min(s0 + per, N);
    int s = 0;
    for (int i = s0; i < s1; i++) s += g_deg[i];
    part[tid] = s;
    __syncthreads();
    for (int o = 1; o < 1024; o <<= 1) {
        int v = (tid >= o) ? part[tid - o] : 0;
        __syncthreads();
        part[tid] += v;
        __syncthreads();
    }
    int base = (tid == 0) ? 0 : part[tid - 1];
    for (int i = s0; i < s1; i++) { g_off[i] = base; g_cur[i] = base; base += g_deg[i]; }
    if (tid == 0) g_off[N] = E;
}

// ---------------- 3: edge RBF-MLP + direct CSR scatter ----------------
__global__ void __launch_bounds__(128) k_edgefill(const float* __restrict__ pos,
        const int* __restrict__ src, const int* __restrict__ dst,
        const float* __restrict__ ew1, const float* __restrict__ eb1,
        const float* __restrict__ ew2, const float* __restrict__ eb2, int E) {
    __shared__ float s1[64 * 20];
    __shared__ float sb1[64];
    __shared__ float s2[4 * 64];
    __shared__ float sb2v[4];
    int tid = threadIdx.x;
    for (int i = tid; i < 1280; i += 128) s1[i] = ew1[i];
    if (tid < 64) sb1[tid] = eb1[tid];
    for (int i = tid; i < 256; i += 128) s2[i] = ew2[i];
    if (tid < 4) sb2v[tid] = eb2[tid];
    __syncthreads();
    int e = blockIdx.x * 128 + tid;
    if (e >= E) return;
    int s = src[e], d = dst[e];
    float dx = pos[s * 3] - pos[d * 3];
    float dy = pos[s * 3 + 1] - pos[d * 3 + 1];
    float dz = pos[s * 3 + 2] - pos[d * 3 + 2];
    float d2 = dx * dx + dy * dy + dz * dz;
    float dist = d2 > 0.f ? sqrtf(d2) : 0.f;
    const float width = 10.f / 19.f;
    const float invw = 19.f / 10.f;
    float rbf[20];
    #pragma unroll
    for (int k = 0; k < 20; k++) {
        float t = (dist - width * k) * invw;
        rbf[k] = __expf(-0.5f * t * t);
    }
    float a0 = 0.f, a1 = 0.f, a2 = 0.f, a3 = 0.f;
    for (int o = 0; o < 64; o++) {
        float hv = sb1[o];
        const float4* w4 = (const float4*)&s1[o * 20];
        #pragma unroll
        for (int q = 0; q < 5; q++) {
            float4 w = w4[q];
            hv += w.x * rbf[q * 4] + w.y * rbf[q * 4 + 1] + w.z * rbf[q * 4 + 2] + w.w * rbf[q * 4 + 3];
        }
        float sv = hv * sigmoidf(hv);
        a0 += s2[o] * sv; a1 += s2[64 + o] * sv; a2 += s2[128 + o] * sv; a3 += s2[192 + o] * sv;
    }
    int p = atomicAdd(&g_cur[d], 1);
    g_srcp[p] = s;
    ((float4*)g_esp)[p] = make_float4(a0 + sb2v[0], a1 + sb2v[1], a2 + sb2v[2], a3 + sb2v[3]);
}

// ---------------- 4: node embedding + input proj (32 nodes/block) ----------------
__global__ void __launch_bounds__(256) k_embed(const int* __restrict__ zi,
        const int* __restrict__ batch, const float* __restrict__ pos,
        const float* __restrict__ atomw, const float* __restrict__ inw,
        const float* __restrict__ inb, int N) {
    __shared__ float wT[65 * 68];
    __shared__ float aT[64 * 36];
    __shared__ float sb[64];
    __shared__ float spx[32], spy[32], spz[32];
    __shared__ int   sz[32];
    int tid = threadIdx.x;
    int n0 = blockIdx.x * 32;

    if (tid < 32) {
        int n = n0 + tid;
        if (n < N) {
            int b = batch[n];
            float ic = 1.f / fmaxf(g_cnt[b], 1.f);
            spx[tid] = pos[n * 3 + 0] - g_psum[b * 3 + 0] * ic;
            spy[tid] = pos[n * 3 + 1] - g_psum[b * 3 + 1] * ic;
            spz[tid] = pos[n * 3 + 2] - g_psum[b * 3 + 2] * ic;
            sz[tid] = zi[n];
        } else { spx[tid] = spy[tid] = spz[tid] = 0.f; sz[tid] = 0; }
    }
    if (tid >= 32 && tid < 96) sb[tid - 32] = inb[tid - 32];
    for (int idx = tid; idx < 64 * 65; idx += 256) {
        int o = idx / 65, i = idx % 65;
        wT[i * 68 + o] = inw[idx];
    }
    __syncthreads();
    for (int idx = tid; idx < 64 * 32; idx += 256) {
        int n = idx & 31, i = idx >> 5;
        aT[i * 36 + n] = atomw[(size_t)sz[n] * 64 + i];
    }
    __syncthreads();

    int ox = (tid & 15) * 4;
    int nl = (tid >> 4) * 2;
    float acc[2][4];
    #pragma unroll
    for (int a = 0; a < 2; a++)
        #pragma unroll
        for (int b = 0; b < 4; b++) acc[a][b] = 0.f;

    #pragma unroll 8
    for (int i = 0; i < 64; i++) {
        float4 w = *(const float4*)&wT[i * 68 + ox];
        float2 a = *(const float2*)&aT[i * 36 + nl];
        acc[0][0] += a.x * w.x; acc[0][1] += a.x * w.y; acc[0][2] += a.x * w.z; acc[0][3] += a.x * w.w;
        acc[1][0] += a.y * w.x; acc[1][1] += a.y * w.y; acc[1][2] += a.y * w.z; acc[1][3] += a.y * w.w;
    }

    #pragma unroll
    for (int jj = 0; jj < 2; jj++) {
        int n = n0 + nl + jj;
        if (n >= N) break;
        float px = spx[nl + jj], py = spy[nl + jj], pz = spz[nl + jj];
        #pragma unroll
        for (int cc = 0; cc < 4; cc++) {
            int o = ox + cc;
            float vw = wT[64 * 68 + o];
            float4* hp = (float4*)(g_h + (size_t)n * 512 + o * 8);
            hp[0] = make_float4(acc[jj][cc] + sb[o], vw * px, vw * py, vw * pz);
            hp[1] = make_float4(0.f, 0.f, 0.f, 0.f);
        }
    }
}

// ---------------- per-grade MVLinear + fused sprep epilogue ----------------
__global__ void __launch_bounds__(256) k_mvlin(const float* __restrict__ W,
        const float* __restrict__ B, const float* __restrict__ Asrc,
        const float* __restrict__ Adst, const float* __restrict__ Wsrc,
        const float* __restrict__ Wdst, int N) {
    extern __shared__ float sm[];
    float* Ws = sm;
    float* Xs = sm + 16640;
    float* Bs = sm + 16640 + 8192;
    int tid = threadIdx.x;
    int n0 = blockIdx.x * 16;
    for (int idx = tid; idx < 16384; idx += 256) {
        int row = idx >> 6, i = idx & 63;
        Ws[row * 65 + i] = W[idx];
    }
    if (tid < 64) Bs[tid] = B[tid];
    for (int f = tid; f < 2048; f += 256) {
        int j = f >> 7, e4 = f & 127;
        int n = n0 + j;
        float4 v = (n < N) ? ((const float4*)g_h)[(size_t)n * 128 + e4]
                           : make_float4(0.f, 0.f, 0.f, 0.f);
        ((float4*)Xs)[j * 128 + e4] = v;
    }
    __syncthreads();
    int combo = tid & 127;
    int o = combo >> 1, half = combo & 1;
    int j0 = (tid >> 7) * 8;
    float acc[8][4];
    #pragma unroll
    for (int j = 0; j < 8; j++)
        #pragma unroll
        for (int c = 0; c < 4; c++) acc[j][c] = 0.f;
    const float* wrowA = Ws + ((half * 2) * 64 + o) * 65;
    const float* wrowB = wrowA + 64 * 65;
    #pragma unroll 4
    for (int i = 0; i < 64; i++) {
        float wA = wrowA[i];
        float wB = wrowB[i];
        float w0 = wA;
        float w1 = half ? wA : wB;
        float w2 = half ? wA : wB;
        float w3 = wB;
        #pragma unroll
        for (int j = 0; j < 8; j++) {
            float4 x = *(const float4*)&Xs[(j0 + j) * 512 + i * 8 + half * 4];
            acc[j][0] += w0 * x.x;
            acc[j][1] += w1 * x.y;
            acc[j][2] += w2 * x.z;
            acc[j][3] += w3 * x.w;
        }
    }
    int h = o >> 4, c = o & 15;
    const float* Ab = Asrc + ((h * 16 + c) * 8) + half * 4;
    const float* Db = Adst + ((h * 16 + c) * 8) + half * 4;
    float wsA, wsB, wdA, wdB;
    if (half == 0) { wsA = Wsrc[h * 4 + 0]; wsB = Wsrc[h * 4 + 1];
                     wdA = Wdst[h * 4 + 0]; wdB = Wdst[h * 4 + 1]; }
    else           { wsA = Wsrc[h * 4 + 2]; wsB = Wsrc[h * 4 + 3];
                     wdA = Wdst[h * 4 + 2]; wdB = Wdst[h * 4 + 3]; }
    float avs0, avs1, avs2, avs3, avd0, avd1, avd2, avd3;
    if (half == 0) {
        avs0 = Ab[0] * wsA; avs1 = Ab[1] * wsB; avs2 = Ab[2] * wsB; avs3 = Ab[3] * wsB;
        avd0 = Db[0] * wdA; avd1 = Db[1] * wdB; avd2 = Db[2] * wdB; avd3 = Db[3] * wdB;
    } else {
        avs0 = Ab[0] * wsA; avs1 = Ab[1] * wsA; avs2 = Ab[2] * wsA; avs3 = Ab[3] * wsB;
        avd0 = Db[0] * wdA; avd1 = Db[1] * wdA; avd2 = Db[2] * wdA; avd3 = Db[3] * wdB;
    }
    float bb = (half == 0) ? Bs[o] : 0.f;
    int lane = tid & 31;
    int hwarp = (tid >> 5) & 3;
    #pragma unroll
    for (int j = 0; j < 8; j++) {
        int n = n0 + j0 + j;
        float v0 = acc[j][0] + bb, v1 = acc[j][1], v2 = acc[j][2], v3 = acc[j][3];
        if (n < N)
            ((float4*)g_z)[(size_t)n * 128 + o * 2 + half] = make_float4(v0, v1, v2, v3);
        float ps = v0 * avs0 + v1 * avs1 + v2 * avs2 + v3 * avs3;
        float pd = v0 * avd0 + v1 * avd1 + v2 * avd2 + v3 * avd3;
        #pragma unroll
        for (int off = 16; off; off >>= 1) {
            ps += __shfl_xor_sync(0xffffffffu, ps, off);
            pd += __shfl_xor_sync(0xffffffffu, pd, off);
        }
        if (lane == 0 && n < N) {
            g_ssrc[n * 4 + hwarp] = ps;
            g_sdst[n * 4 + hwarp] = pd;
        }
    }
}

// ---------------- warp-per-node attention + MVSiLU + residual + LN ----------------
// lane L owns float4s {q*32+L : q=0..3} of the node's 512-float vector.
// head of component q*128+L*4.. is exactly q, so alpha component q weights acc[q].
__global__ void __launch_bounds__(128) k_attn(const float* __restrict__ sa,
        const float* __restrict__ sbp, const float* __restrict__ lna, int N) {
    int n = blockIdx.x * 4 + (threadIdx.x >> 5);
    int lane = threadIdx.x & 31;
    if (n >= N) return;
    int e0 = g_off[n];
    int deg = g_off[n + 1] - e0;
    float4 sd = ((const float4*)g_sdst)[n];
    const unsigned FULL = 0xffffffffu;

    bool fits = (deg <= 128);
    float4 lgr[4];
    int sr[4];
    float4 mx = make_float4(-3e38f, -3e38f, -3e38f, -3e38f);

    if (fits) {
        #pragma unroll
        for (int r = 0; r < 4; r++) {
            int j = lane + r * 32;
            if (j < deg) {
                int s = g_srcp[e0 + j];
                sr[r] = s;
                float4 ss = ((const float4*)g_ssrc)[s];
                float4 ev = ((const float4*)g_esp)[e0 + j];
                float4 lg = make_float4(lrelu(ss.x + sd.x + ev.x), lrelu(ss.y + sd.y + ev.y),
                                        lrelu(ss.z + sd.z + ev.z), lrelu(ss.w + sd.w + ev.w));
                lgr[r] = lg;
                mx.x = fmaxf(mx.x, lg.x); mx.y = fmaxf(mx.y, lg.y);
                mx.z = fmaxf(mx.z, lg.z); mx.w = fmaxf(mx.w, lg.w);
            } else {
                sr[r] = 0;
                lgr[r] = make_float4(-3e38f, -3e38f, -3e38f, -3e38f);
            }
        }
    } else {
        for (int j = lane; j < deg; j += 32) {
            int s = g_srcp[e0 + j];
            float4 ss = ((const float4*)g_ssrc)[s];
            float4 ev = ((const float4*)g_esp)[e0 + j];
            mx.x = fmaxf(mx.x, lrelu(ss.x + sd.x + ev.x));
            mx.y = fmaxf(mx.y, lrelu(ss.y + sd.y + ev.y));
            mx.z = fmaxf(mx.z, lrelu(ss.z + sd.z + ev.z));
            mx.w = fmaxf(mx.w, lrelu(ss.w + sd.w + ev.w));
        }
    }
    #pragma unroll
    for (int off = 16; off; off >>= 1) {
        mx.x = fmaxf(mx.x, __shfl_xor_sync(FULL, mx.x, off));
        mx.y = fmaxf(mx.y, __shfl_xor_sync(FULL, mx.y, off));
        mx.z = fmaxf(mx.z, __shfl_xor_sync(FULL, mx.z, off));
        mx.w = fmaxf(mx.w, __shfl_xor_sync(FULL, mx.w, off));
    }

    float4 su = make_float4(0.f, 0.f, 0.f, 0.f);
    if (fits) {
        #pragma unroll
        for (int r = 0; r < 4; r++) {
            int j = lane + r * 32;
            if (j < deg) {
                float4 lg = lgr[r];
                lg.x = __expf(lg.x - mx.x); lg.y = __expf(lg.y - mx.y);
                lg.z = __expf(lg.z - mx.z); lg.w = __expf(lg.w - mx.w);
                lgr[r] = lg;
                su.x += lg.x; su.y += lg.y; su.z += lg.z; su.w += lg.w;
            } else {
                lgr[r] = make_float4(0.f, 0.f, 0.f, 0.f);
            }
        }
    } else {
        for (int j = lane; j < deg; j += 32) {
            int s = g_srcp[e0 + j];
            float4 ss = ((const float4*)g_ssrc)[s];
            float4 ev = ((const float4*)g_esp)[e0 + j];
            su.x += __expf(lrelu(ss.x + sd.x + ev.x) - mx.x);
            su.y += __expf(lrelu(ss.y + sd.y + ev.y) - mx.y);
            su.z += __expf(lrelu(ss.z + sd.z + ev.z) - mx.z);
            su.w += __expf(lrelu(ss.w + sd.w + ev.w) - mx.w);
        }
    }
    #pragma unroll
    for (int off = 16; off; off >>= 1) {
        su.x += __shfl_xor_sync(FULL, su.x, off);
        su.y += __shfl_xor_sync(FULL, su.y, off);
        su.z += __shfl_xor_sync(FULL, su.z, off);
        su.w += __shfl_xor_sync(FULL, su.w, off);
    }

    float4 acc0 = make_float4(0.f, 0.f, 0.f, 0.f);
    float4 acc1 = make_float4(0.f, 0.f, 0.f, 0.f);
    float4 acc2 = make_float4(0.f, 0.f, 0.f, 0.f);
    float4 acc3 = make_float4(0.f, 0.f, 0.f, 0.f);

    if (fits) {
        #pragma unroll
        for (int r = 0; r < 4; r++) {
            int base = r * 32;
            if (base >= deg) break;
            int m = min(32, deg - base);
            float4 lgv = lgr[r];
            int sv = sr[r];
            for (int l = 0; l < m; l++) {
                int s = __shfl_sync(FULL, sv, l);
                float wx = __shfl_sync(FULL, lgv.x, l);
                float wy = __shfl_sync(FULL, lgv.y, l);
                float wz = __shfl_sync(FULL, lgv.z, l);
                float ww = __shfl_sync(FULL, lgv.w, l);
                const float4* zp = (const float4*)(g_z + (size_t)s * 512);
                float4 z0 = zp[lane];
                float4 z1 = zp[32 + lane];
                float4 z2 = zp[64 + lane];
                float4 z3 = zp[96 + lane];
                acc0.x += wx * z0.x; acc0.y += wx * z0.y; acc0.z += wx * z0.z; acc0.w += wx * z0.w;
                acc1.x += wy * z1.x; acc1.y += wy * z1.y; acc1.z += wy * z1.z; acc1.w += wy * z1.w;
                acc2.x += wz * z2.x; acc2.y += wz * z2.y; acc2.z += wz * z2.z; acc2.w += wz * z2.w;
                acc3.x += ww * z3.x; acc3.y += ww * z3.y; acc3.z += ww * z3.z; acc3.w += ww * z3.w;
            }
        }
    } else {
        for (int j = 0; j < deg; j++) {
            int s = g_srcp[e0 + j];
            float4 ss = ((const float4*)g_ssrc)[s];
            float4 ev = ((const float4*)g_esp)[e0 + j];
            float wx = __expf(lrelu(ss.x + sd.x + ev.x) - mx.x);
            float wy = __expf(lrelu(ss.y + sd.y + ev.y) - mx.y);
            float wz = __expf(lrelu(ss.z + sd.z + ev.z) - mx.z);
            float ww = __expf(lrelu(ss.w + sd.w + ev.w) - mx.w);
            const float4* zp = (const float4*)(g_z + (size_t)s * 512);
            float4 z0 = zp[lane];
            float4 z1 = zp[32 + lane];
            float4 z2 = zp[64 + lane];
            float4 z3 = zp[96 + lane];
            acc0.x += wx * z0.x; acc0.y += wx * z0.y; acc0.z += wx * z0.z; acc0.w += wx * z0.w;
            acc1.x += wy * z1.x; acc1.y += wy * z1.y; acc1.z += wy * z1.z; acc1.w += wy * z1.w;
            acc2.x += wz * z2.x; acc2.y += wz * z2.y; acc2.z += wz * z2.z; acc2.w += wz * z2.w;
            acc3.x += ww * z3.x; acc3.y += ww * z3.y; acc3.z += ww * z3.z; acc3.w += ww * z3.w;
        }
    }

    float inv0 = 1.f / (su.x + 1e-16f);
    float inv1 = 1.f / (su.y + 1e-16f);
    float inv2 = 1.f / (su.z + 1e-16f);
    float inv3 = 1.f / (su.w + 1e-16f);

    float4 xq[4];
    xq[0] = make_float4(acc0.x * inv0, acc0.y * inv0, acc0.z * inv0, acc0.w * inv0);
    xq[1] = make_float4(acc1.x * inv1, acc1.y * inv1, acc1.z * inv1, acc1.w * inv1);
    xq[2] = make_float4(acc2.x * inv2, acc2.y * inv2, acc2.z * inv2, acc2.w * inv2);
    xq[3] = make_float4(acc3.x * inv3, acc3.y * inv3, acc3.z * inv3, acc3.w * inv3);

    // MVSiLU + residual + squared-norm, per q
    int hf = lane & 1;
    float ssq[4];
    const float4* hres = (const float4*)(g_h + (size_t)n * 512);
    #pragma unroll
    for (int q = 0; q < 4; q++) {
        int c = q * 16 + (lane >> 1);
        float4 x = xq[q];
        if (hf == 0) {
            float nA = x.x;
            float nB = x.y * x.y + x.z * x.z + x.w * x.w;
            float gA = sigmoidf(sa[c * 4 + 0] * nA + sbp[c * 4 + 0]);
            float gB = sigmoidf(sa[c * 4 + 1] * nB + sbp[c * 4 + 1]);
            x.x *= gA; x.y *= gB; x.z *= gB; x.w *= gB;
        } else {
            float nA = x.x * x.x + x.y * x.y + x.z * x.z;
            float nB = x.w * x.w;
            float gA = sigmoidf(sa[c * 4 + 2] * nA + sbp[c * 4 + 2]);
            float gB = sigmoidf(sa[c * 4 + 3] * nB + sbp[c * 4 + 3]);
            x.x *= gA; x.y *= gA; x.z *= gA; x.w *= gB;
        }
        float4 r = hres[q * 32 + lane];
        x.x += r.x; x.y += r.y; x.z += r.z; x.w += r.w;
        xq[q] = x;
        ssq[q] = x.x * x.x + x.y * x.y + x.z * x.z + x.w * x.w;
    }

    // per-channel norms (pair across hf) then mean over 64 channels
    float cnsum = 0.f;
    float cn[4];
    #pragma unroll
    for (int q = 0; q < 4; q++) {
        float s2 = ssq[q] + __shfl_xor_sync(FULL, ssq[q], 1);
        cn[q] = sqrtf(s2);
        cnsum += cn[q];
    }
    #pragma unroll
    for (int off = 16; off > 1; off >>= 1) cnsum += __shfl_xor_sync(FULL, cnsum, off);
    cnsum += __shfl_xor_sync(FULL, cnsum, 1);
    float mean = cnsum * (1.f / 128.f) + 1e-6f;   // (cnsum/2)/64
    float invm = 1.f / mean;

    float4* hout = (float4*)(g_h + (size_t)n * 512);
    #pragma unroll
    for (int q = 0; q < 4; q++) {
        int c = q * 16 + (lane >> 1);
        float scale = lna[c] * invm;
        float4 x = xq[q];
        hout[q * 32 + lane] = make_float4(x.x * scale, x.y * scale, x.z * scale, x.w * scale);
    }
}

// ---------------- prepool (scalar blade) + graph pooling ----------------
__global__ void __launch_bounds__(64) k_prepool(const float* __restrict__ ppw,
        const float* __restrict__ ppb, const int* __restrict__ batch, int N) {
    __shared__ float x0[64];
    int n = blockIdx.x, tid = threadIdx.x;
    x0[tid] = g_h[(size_t)n * 512 + tid * 8];
    __syncthreads();
    float acc = ppb[tid];
    const float* wr = ppw + tid * 64;
    #pragma unroll 8
    for (int i = 0; i < 64; i++) acc += wr[i] * x0[i];
    atomicAdd(&g_gsum[batch[n] * 64 + tid], acc);
}

__global__ void __launch_bounds__(64) k_post(const float* __restrict__ pw1,
        const float* __restrict__ pb1, const float* __restrict__ pw2,
        const float* __restrict__ pb2, float* __restrict__ out) {
    __shared__ float sg[64];
    __shared__ float sh[64];
    int b = blockIdx.x, tid = threadIdx.x;
    sg[tid] = g_gsum[b * 64 + tid];
    __syncthreads();
    float a = pb1[tid];
    const float* wr = pw1 + tid * 64;
    #pragma unroll 8
    for (int i = 0; i < 64; i++) a += wr[i] * sg[i];
    float s = a * sigmoidf(a);
    sh[tid] = s * pw2[tid];
    __syncthreads();
    for (int st = 32; st; st >>= 1) {
        if (tid < st) sh[tid] += sh[tid + st];
        __syncthreads();
    }
    if (tid == 0) out[b] = sh[0] + pb2[0];
}

// ---------------- launch ----------------
extern "C" void kernel_launch(void* const* d_in, const int* in_sizes, int n_in,
                              void* d_out, int out_size) {
    const float* pos   = (const float*)d_in[0];
    const int*   zi    = (const int*)d_in[1];
    const int*   ei    = (const int*)d_in[2];
    const int*   batch = (const int*)d_in[3];
    const float* atomw = (const float*)d_in[4];
    const float* inw   = (const float*)d_in[5];
    const float* inb   = (const float*)d_in[6];
    const float* ew1   = (const float*)d_in[7];
    const float* eb1   = (const float*)d_in[8];
    const float* ew2   = (const float*)d_in[9];
    const float* eb2   = (const float*)d_in[10];
    const float* projw = (const float*)d_in[11];
    const float* projb = (const float*)d_in[12];
    const float* asrc  = (const float*)d_in[13];
    const float* adst  = (const float*)d_in[14];
    const float* wsrc  = (const float*)d_in[15];
    const float* wdst  = (const float*)d_in[16];
    const float* lna   = (const float*)d_in[17];
    const float* silua = (const float*)d_in[18];
    const float* silub = (const float*)d_in[19];
    const float* ppw   = (const float*)d_in[20];
    const float* ppb   = (const float*)d_in[21];
    const float* pw1   = (const float*)d_in[22];
    const float* pb1   = (const float*)d_in[23];
    const float* pw2   = (const float*)d_in[24];
    const float* pb2   = (const float*)d_in[25];
    float* out = (float*)d_out;

    int N = in_sizes[0] / 3;
    int E = in_sizes[2] / 2;
    const int* src = ei;
    const int* dst = ei + E;

    cudaFuncSetAttribute(k_mvlin, cudaFuncAttributeMaxDynamicSharedMemorySize, 99584);

    k_zero<<<64, 256>>>(N);
    k_init<<<(E + 255) / 256, 256>>>(pos, batch, dst, N, E);
    k_scan<<<1, 1024>>>(N, E);
    k_edgefill<<<(E + 127) / 128, 128>>>(pos, src, dst, ew1, eb1, ew2, eb2, E);
    k_embed<<<(N + 31) / 32, 256>>>(zi, batch, pos, atomw, inw, inb, N);

    for (int l = 0; l < 4; l++) {
        k_mvlin<<<(N + 15) / 16, 256, 99584>>>(projw + (size_t)l * 4 * 64 * 64,
                                               projb + l * 64,
                                               asrc + l * 512, adst + l * 512,
                                               wsrc + l * 16, wdst + l * 16, N);
        k_attn<<<(N + 3) / 4, 128>>>(silua + l * 256, silub + l * 256, lna + l * 64, N);
    }

    k_prepool<<<N, 64>>>(ppw, ppb, batch, N);
    k_post<<<NB, 64>>>(pw1, pb1, pw2, pb2, out);
}

// round 6
// speedup vs baseline: 1.2122x; 1.0829x over previous
#include <cuda_runtime.h>
#include <cuda_fp16.h>
#include <math.h>

#define NN 20000
#define EE 320000
#define NB 256
#define HIDC 64

// ---------------- scratch (device globals; no allocation) ----------------
__device__ float  g_h[(size_t)NN * 512];
__device__ __half g_zh[(size_t)NN * 512];   // z in fp16 (aggregation-only consumer)
__device__ float  g_esp[(size_t)EE * 4];    // edge scalar, CSR order
__device__ int    g_srcp[EE];               // src, CSR order
__device__ float  g_ssrc[NN * 4];
__device__ float  g_sdst[NN * 4];
__device__ float  g_cnt[NB];
__device__ float  g_psum[NB * 3];
__device__ int    g_deg[NN];
__device__ int    g_off[NN + 1];
__device__ int    g_cur[NN];
__device__ int    g_bsum[64];
__device__ float  g_gsum[NB * HIDC];

// ---------------- helpers ----------------
__device__ __forceinline__ float lrelu(float v) { return v > 0.f ? v : 0.2f * v; }
__device__ __forceinline__ float sigmoidf(float v) { return 1.f / (1.f + __expf(-v)); }

__device__ __forceinline__ void cvt8(uint4 p, float* f) {
    float2 t;
    t = __half22float2(*(__half2*)&p.x); f[0] = t.x; f[1] = t.y;
    t = __half22float2(*(__half2*)&p.y); f[2] = t.x; f[3] = t.y;
    t = __half22float2(*(__half2*)&p.z); f[4] = t.x; f[5] = t.y;
    t = __half22float2(*(__half2*)&p.w); f[6] = t.x; f[7] = t.y;
}

// gate one channel's 8 blades (grades 0,1,1,1,2,2,2,3)
__device__ __forceinline__ void mvgate(float* x, float4 a, float4 b) {
    float gA = sigmoidf(a.x * x[0] + b.x);
    float nB = x[1] * x[1] + x[2] * x[2] + x[3] * x[3];
    float gB = sigmoidf(a.y * nB + b.y);
    float nC = x[4] * x[4] + x[5] * x[5] + x[6] * x[6];
    float gC = sigmoidf(a.z * nC + b.z);
    float gD = sigmoidf(a.w * x[7] * x[7] + b.w);
    x[0] *= gA; x[1] *= gB; x[2] *= gB; x[3] *= gB;
    x[4] *= gC; x[5] *= gC; x[6] *= gC; x[7] *= gD;
}

// ---------------- 0: zero scratch ----------------
__global__ void k_zero(int N) {
    int total = NB + NB * 3 + NB * HIDC + N;
    for (int i = blockIdx.x * blockDim.x + threadIdx.x; i < total; i += gridDim.x * blockDim.x) {
        if (i < NB) g_cnt[i] = 0.f;
        else if (i < NB + NB * 3) g_psum[i - NB] = 0.f;
        else if (i < NB + NB * 3 + NB * HIDC) g_gsum[i - NB - NB * 3] = 0.f;
        else g_deg[i - NB - NB * 3 - NB * HIDC] = 0;
    }
}

// ---------------- 1: batch stats + degree count ----------------
__global__ void k_init(const float* __restrict__ pos, const int* __restrict__ batch,
                       const int* __restrict__ dst, int N, int E) {
    int i = blockIdx.x * blockDim.x + threadIdx.x;
    if (i < N) {
        int b = batch[i];
        atomicAdd(&g_cnt[b], 1.f);
        atomicAdd(&g_psum[b * 3 + 0], pos[i * 3 + 0]);
        atomicAdd(&g_psum[b * 3 + 1], pos[i * 3 + 1]);
        atomicAdd(&g_psum[b * 3 + 2], pos[i * 3 + 2]);
    }
    if (i < E) atomicAdd(&g_deg[dst[i]], 1);
}

// ---------------- scan phase A: per-1024-block exclusive scan ----------------
__global__ void __launch_bounds__(1024) k_scanA(int N) {
    __shared__ int swt[32];
    int t = threadIdx.x, b = blockIdx.x;
    int i = b * 1024 + t;
    int lane = t & 31, wid = t >> 5;
    int v = (i < N) ? g_deg[i] : 0;
    int x = v;
    #pragma unroll
    for (int o = 1; o < 32; o <<= 1) {
        int y = __shfl_up_sync(0xffffffffu, x, o);
        if (lane >= o) x += y;
    }
    if (lane == 31) swt[wid] = x;
    __syncthreads();
    if (t < 32) {
        int w = swt[t];
        #pragma unroll
        for (int o = 1; o < 32; o <<= 1) {
            int y = __shfl_up_sync(0xffffffffu, w, o);
            if (t >= o) w += y;
        }
        swt[t] = w;
    }
    __syncthreads();
    int base = (wid == 0) ? 0 : swt[wid - 1];
    if (i < N) g_off[i] = base + x - v;
    if (t == 1023) g_bsum[b] = base + x;
}

// ---------------- scan phase B: add block offsets, set cur ----------------
__global__ void __launch_bounds__(256) k_scanB(int N, int E, int G) {
    __shared__ int soff;
    int b = blockIdx.x, t = threadIdx.x;
    if (t == 0) {
        int s = 0;
        for (int j = 0; j < b; j++) s += g_bsum[j];
        soff = s;
        if (b == 0) g_off[N] = E;
    }
    __syncthreads();
    int s = soff;
    for (int k = t; k < 1024; k += 256) {
        int i = b * 1024 + k;
        if (i < N) {
            int val = g_off[i] + s;
            g_off[i] = val;
            g_cur[i] = val;
        }
    }
}

// ---------------- edge RBF-MLP + direct CSR scatter ----------------
__global__ void __launch_bounds__(128) k_edgefill(const float* __restrict__ pos,
        const int* __restrict__ src, const int* __restrict__ dst,
        const float* __restrict__ ew1, const float* __restrict__ eb1,
        const float* __restrict__ ew2, const float* __restrict__ eb2, int E) {
    __shared__ float s1[64 * 20];
    __shared__ float sb1[64];
    __shared__ float s2T[4 * 64];   // s2T[o*4+h] = ew2[h*64+o]
    __shared__ float sb2v[4];
    int tid = threadIdx.x;
    for (int i = tid; i < 1280; i += 128) s1[i] = ew1[i];
    if (tid < 64) sb1[tid] = eb1[tid];
    for (int i = tid; i < 256; i += 128) {
        int o = i >> 2, h = i & 3;
        s2T[i] = ew2[h * 64 + o];
    }
    if (tid < 4) sb2v[tid] = eb2[tid];
    __syncthreads();
    int e = blockIdx.x * 128 + tid;
    if (e >= E) return;
    int s = src[e], d = dst[e];
    float dx = pos[s * 3] - pos[d * 3];
    float dy = pos[s * 3 + 1] - pos[d * 3 + 1];
    float dz = pos[s * 3 + 2] - pos[d * 3 + 2];
    float d2 = dx * dx + dy * dy + dz * dz;
    float dist = d2 > 0.f ? sqrtf(d2) : 0.f;
    const float width = 10.f / 19.f;
    const float invw = 19.f / 10.f;
    float rbf[20];
    #pragma unroll
    for (int k = 0; k < 20; k++) {
        float t = (dist - width * k) * invw;
        rbf[k] = __expf(-0.5f * t * t);
    }
    float a0 = 0.f, a1 = 0.f, a2 = 0.f, a3 = 0.f;
    #pragma unroll 2
    for (int o = 0; o < 64; o++) {
        float hv = sb1[o];
        const float4* w4 = (const float4*)&s1[o * 20];
        #pragma unroll
        for (int q = 0; q < 5; q++) {
            float4 w = w4[q];
            hv += w.x * rbf[q * 4] + w.y * rbf[q * 4 + 1] + w.z * rbf[q * 4 + 2] + w.w * rbf[q * 4 + 3];
        }
        float sv = hv * sigmoidf(hv);
        float4 w2 = ((const float4*)s2T)[o];
        a0 += w2.x * sv; a1 += w2.y * sv; a2 += w2.z * sv; a3 += w2.w * sv;
    }
    int p = atomicAdd(&g_cur[d], 1);
    g_srcp[p] = s;
    ((float4*)g_esp)[p] = make_float4(a0 + sb2v[0], a1 + sb2v[1], a2 + sb2v[2], a3 + sb2v[3]);
}

// ---------------- node embedding + input proj (32 nodes/block) ----------------
__global__ void __launch_bounds__(256) k_embed(const int* __restrict__ zi,
        const int* __restrict__ batch, const float* __restrict__ pos,
        const float* __restrict__ atomw, const float* __restrict__ inw,
        const float* __restrict__ inb, int N) {
    __shared__ float wT[65 * 68];
    __shared__ float aT[64 * 36];
    __shared__ float sb[64];
    __shared__ float spx[32], spy[32], spz[32];
    __shared__ int   sz[32];
    int tid = threadIdx.x;
    int n0 = blockIdx.x * 32;

    if (tid < 32) {
        int n = n0 + tid;
        if (n < N) {
            int b = batch[n];
            float ic = 1.f / fmaxf(g_cnt[b], 1.f);
            spx[tid] = pos[n * 3 + 0] - g_psum[b * 3 + 0] * ic;
            spy[tid] = pos[n * 3 + 1] - g_psum[b * 3 + 1] * ic;
            spz[tid] = pos[n * 3 + 2] - g_psum[b * 3 + 2] * ic;
            sz[tid] = zi[n];
        } else { spx[tid] = spy[tid] = spz[tid] = 0.f; sz[tid] = 0; }
    }
    if (tid >= 32 && tid < 96) sb[tid - 32] = inb[tid - 32];
    for (int idx = tid; idx < 64 * 65; idx += 256) {
        int o = idx / 65, i = idx % 65;
        wT[i * 68 + o] = inw[idx];
    }
    __syncthreads();
    for (int idx = tid; idx < 64 * 32; idx += 256) {
        int n = idx & 31, i = idx >> 5;
        aT[i * 36 + n] = atomw[(size_t)sz[n] * 64 + i];
    }
    __syncthreads();

    int ox = (tid & 15) * 4;
    int nl = (tid >> 4) * 2;
    float acc[2][4];
    #pragma unroll
    for (int a = 0; a < 2; a++)
        #pragma unroll
        for (int b = 0; b < 4; b++) acc[a][b] = 0.f;

    #pragma unroll 8
    for (int i = 0; i < 64; i++) {
        float4 w = *(const float4*)&wT[i * 68 + ox];
        float2 a = *(const float2*)&aT[i * 36 + nl];
        acc[0][0] += a.x * w.x; acc[0][1] += a.x * w.y; acc[0][2] += a.x * w.z; acc[0][3] += a.x * w.w;
        acc[1][0] += a.y * w.x; acc[1][1] += a.y * w.y; acc[1][2] += a.y * w.z; acc[1][3] += a.y * w.w;
    }

    #pragma unroll
    for (int jj = 0; jj < 2; jj++) {
        int n = n0 + nl + jj;
        if (n >= N) break;
        float px = spx[nl + jj], py = spy[nl + jj], pz = spz[nl + jj];
        #pragma unroll
        for (int cc = 0; cc < 4; cc++) {
            int o = ox + cc;
            float vw = wT[64 * 68 + o];
            float4* hp = (float4*)(g_h + (size_t)n * 512 + o * 8);
            hp[0] = make_float4(acc[jj][cc] + sb[o], vw * px, vw * py, vw * pz);
            hp[1] = make_float4(0.f, 0.f, 0.f, 0.f);
        }
    }
}

// ---------------- per-grade MVLinear + fused sprep epilogue (z -> fp16) ----------------
__global__ void __launch_bounds__(256) k_mvlin(const float* __restrict__ W,
        const float* __restrict__ B, const float* __restrict__ Asrc,
        const float* __restrict__ Adst, const float* __restrict__ Wsrc,
        const float* __restrict__ Wdst, int N) {
    extern __shared__ float sm[];
    float* Ws = sm;
    float* Xs = sm + 16640;
    float* Bs = sm + 16640 + 8192;
    int tid = threadIdx.x;
    int n0 = blockIdx.x * 16;
    for (int idx = tid; idx < 16384; idx += 256) {
        int row = idx >> 6, i = idx & 63;
        Ws[row * 65 + i] = W[idx];
    }
    if (tid < 64) Bs[tid] = B[tid];
    for (int f = tid; f < 2048; f += 256) {
        int j = f >> 7, e4 = f & 127;
        int n = n0 + j;
        float4 v = (n < N) ? ((const float4*)g_h)[(size_t)n * 128 + e4]
                           : make_float4(0.f, 0.f, 0.f, 0.f);
        ((float4*)Xs)[j * 128 + e4] = v;
    }
    __syncthreads();
    int combo = tid & 127;
    int o = combo >> 1, half = combo & 1;
    int j0 = (tid >> 7) * 8;
    float acc[8][4];
    #pragma unroll
    for (int j = 0; j < 8; j++)
        #pragma unroll
        for (int c = 0; c < 4; c++) acc[j][c] = 0.f;
    const float* wrowA = Ws + ((half * 2) * 64 + o) * 65;
    const float* wrowB = wrowA + 64 * 65;
    #pragma unroll 4
    for (int i = 0; i < 64; i++) {
        float wA = wrowA[i];
        float wB = wrowB[i];
        float w0 = wA;
        float w1 = half ? wA : wB;
        float w2 = half ? wA : wB;
        float w3 = wB;
        #pragma unroll
        for (int j = 0; j < 8; j++) {
            float4 x = *(const float4*)&Xs[(j0 + j) * 512 + i * 8 + half * 4];
            acc[j][0] += w0 * x.x;
            acc[j][1] += w1 * x.y;
            acc[j][2] += w2 * x.z;
            acc[j][3] += w3 * x.w;
        }
    }
    int h = o >> 4, c = o & 15;
    const float* Ab = Asrc + ((h * 16 + c) * 8) + half * 4;
    const float* Db = Adst + ((h * 16 + c) * 8) + half * 4;
    float wsA, wsB, wdA, wdB;
    if (half == 0) { wsA = Wsrc[h * 4 + 0]; wsB = Wsrc[h * 4 + 1];
                     wdA = Wdst[h * 4 + 0]; wdB = Wdst[h * 4 + 1]; }
    else           { wsA = Wsrc[h * 4 + 2]; wsB = Wsrc[h * 4 + 3];
                     wdA = Wdst[h * 4 + 2]; wdB = Wdst[h * 4 + 3]; }
    float avs0, avs1, avs2, avs3, avd0, avd1, avd2, avd3;
    if (half == 0) {
        avs0 = Ab[0] * wsA; avs1 = Ab[1] * wsB; avs2 = Ab[2] * wsB; avs3 = Ab[3] * wsB;
        avd0 = Db[0] * wdA; avd1 = Db[1] * wdB; avd2 = Db[2] * wdB; avd3 = Db[3] * wdB;
    } else {
        avs0 = Ab[0] * wsA; avs1 = Ab[1] * wsA; avs2 = Ab[2] * wsA; avs3 = Ab[3] * wsB;
        avd0 = Db[0] * wdA; avd1 = Db[1] * wdA; avd2 = Db[2] * wdA; avd3 = Db[3] * wdB;
    }
    float bb = (half == 0) ? Bs[o] : 0.f;
    int lane = tid & 31;
    int hwarp = (tid >> 5) & 3;
    #pragma unroll
    for (int j = 0; j < 8; j++) {
        int n = n0 + j0 + j;
        float v0 = acc[j][0] + bb, v1 = acc[j][1], v2 = acc[j][2], v3 = acc[j][3];
        if (n < N) {
            __half2 ha = __floats2half2_rn(v0, v1);
            __half2 hb = __floats2half2_rn(v2, v3);
            uint2 u;
            u.x = *(unsigned*)&ha;
            u.y = *(unsigned*)&hb;
            *(uint2*)(g_zh + (size_t)n * 512 + o * 8 + half * 4) = u;
        }
        float ps = v0 * avs0 + v1 * avs1 + v2 * avs2 + v3 * avs3;
        float pd = v0 * avd0 + v1 * avd1 + v2 * avd2 + v3 * avd3;
        #pragma unroll
        for (int off = 16; off; off >>= 1) {
            ps += __shfl_xor_sync(0xffffffffu, ps, off);
            pd += __shfl_xor_sync(0xffffffffu, pd, off);
        }
        if (lane == 0 && n < N) {
            g_ssrc[n * 4 + hwarp] = ps;
            g_sdst[n * 4 + hwarp] = pd;
        }
    }
}

// ---------------- warp-per-node attention + MVSiLU + residual + LN ----------------
// lane L owns components [16L, 16L+16) = channels 2L, 2L+1; head = L>>3 (one per lane).
__global__ void __launch_bounds__(128) k_attn(const float* __restrict__ sa,
        const float* __restrict__ sbp, const float* __restrict__ lna, int N) {
    int n = blockIdx.x * 4 + (threadIdx.x >> 5);
    int lane = threadIdx.x & 31;
    if (n >= N) return;
    int e0 = g_off[n];
    int deg = g_off[n + 1] - e0;
    float4 sd = ((const float4*)g_sdst)[n];
    const unsigned FULL = 0xffffffffu;
    int hsel = lane >> 3;

    bool fits = (deg <= 128);
    float4 lgr[4];
    int sr[4];
    float4 mx = make_float4(-3e38f, -3e38f, -3e38f, -3e38f);

    if (fits) {
        #pragma unroll
        for (int r = 0; r < 4; r++) {
            int j = lane + r * 32;
            if (j < deg) {
                int s = g_srcp[e0 + j];
                sr[r] = s;
                float4 ss = ((const float4*)g_ssrc)[s];
                float4 ev = ((const float4*)g_esp)[e0 + j];
                float4 lg = make_float4(lrelu(ss.x + sd.x + ev.x), lrelu(ss.y + sd.y + ev.y),
                                        lrelu(ss.z + sd.z + ev.z), lrelu(ss.w + sd.w + ev.w));
                lgr[r] = lg;
                mx.x = fmaxf(mx.x, lg.x); mx.y = fmaxf(mx.y, lg.y);
                mx.z = fmaxf(mx.z, lg.z); mx.w = fmaxf(mx.w, lg.w);
            } else {
                sr[r] = 0;
                lgr[r] = make_float4(-3e38f, -3e38f, -3e38f, -3e38f);
            }
        }
    } else {
        for (int j = lane; j < deg; j += 32) {
            int s = g_srcp[e0 + j];
            float4 ss = ((const float4*)g_ssrc)[s];
            float4 ev = ((const float4*)g_esp)[e0 + j];
            mx.x = fmaxf(mx.x, lrelu(ss.x + sd.x + ev.x));
            mx.y = fmaxf(mx.y, lrelu(ss.y + sd.y + ev.y));
            mx.z = fmaxf(mx.z, lrelu(ss.z + sd.z + ev.z));
            mx.w = fmaxf(mx.w, lrelu(ss.w + sd.w + ev.w));
        }
    }
    #pragma unroll
    for (int off = 16; off; off >>= 1) {
        mx.x = fmaxf(mx.x, __shfl_xor_sync(FULL, mx.x, off));
        mx.y = fmaxf(mx.y, __shfl_xor_sync(FULL, mx.y, off));
        mx.z = fmaxf(mx.z, __shfl_xor_sync(FULL, mx.z, off));
        mx.w = fmaxf(mx.w, __shfl_xor_sync(FULL, mx.w, off));
    }

    float4 su = make_float4(0.f, 0.f, 0.f, 0.f);
    if (fits) {
        #pragma unroll
        for (int r = 0; r < 4; r++) {
            int j = lane + r * 32;
            if (j < deg) {
                float4 lg = lgr[r];
                lg.x = __expf(lg.x - mx.x); lg.y = __expf(lg.y - mx.y);
                lg.z = __expf(lg.z - mx.z); lg.w = __expf(lg.w - mx.w);
                lgr[r] = lg;
                su.x += lg.x; su.y += lg.y; su.z += lg.z; su.w += lg.w;
            } else {
                lgr[r] = make_float4(0.f, 0.f, 0.f, 0.f);
            }
        }
    } else {
        for (int j = lane; j < deg; j += 32) {
            int s = g_srcp[e0 + j];
            float4 ss = ((const float4*)g_ssrc)[s];
            float4 ev = ((const float4*)g_esp)[e0 + j];
            su.x += __expf(lrelu(ss.x + sd.x + ev.x) - mx.x);
            su.y += __expf(lrelu(ss.y + sd.y + ev.y) - mx.y);
            su.z += __expf(lrelu(ss.z + sd.z + ev.z) - mx.z);
            su.w += __expf(lrelu(ss.w + sd.w + ev.w) - mx.w);
        }
    }
    #pragma unroll
    for (int off = 16; off; off >>= 1) {
        su.x += __shfl_xor_sync(FULL, su.x, off);
        su.y += __shfl_xor_sync(FULL, su.y, off);
        su.z += __shfl_xor_sync(FULL, su.z, off);
        su.w += __shfl_xor_sync(FULL, su.w, off);
    }

    float acc[16];
    #pragma unroll
    for (int k = 0; k < 16; k++) acc[k] = 0.f;

    if (fits) {
        #pragma unroll
        for (int r = 0; r < 4; r++) {
            int base = r * 32;
            if (base >= deg) break;
            int m = min(32, deg - base);
            float4 lgv = lgr[r];
            int sv = sr[r];
            // prefetch edge 0
            int s0 = __shfl_sync(FULL, sv, 0);
            float b0 = __shfl_sync(FULL, lgv.x, 0);
            float b1 = __shfl_sync(FULL, lgv.y, 0);
            float b2 = __shfl_sync(FULL, lgv.z, 0);
            float b3 = __shfl_sync(FULL, lgv.w, 0);
            float aP = hsel == 0 ? b0 : hsel == 1 ? b1 : hsel == 2 ? b2 : b3;
            const uint4* zp = (const uint4*)(g_zh + (size_t)s0 * 512);
            uint4 pA = zp[lane * 2];
            uint4 pB = zp[lane * 2 + 1];
            for (int l = 0; l < m; l++) {
                uint4 cA = pA, cB = pB;
                float a = aP;
                if (l + 1 < m) {
                    int s = __shfl_sync(FULL, sv, l + 1);
                    b0 = __shfl_sync(FULL, lgv.x, l + 1);
                    b1 = __shfl_sync(FULL, lgv.y, l + 1);
                    b2 = __shfl_sync(FULL, lgv.z, l + 1);
                    b3 = __shfl_sync(FULL, lgv.w, l + 1);
                    aP = hsel == 0 ? b0 : hsel == 1 ? b1 : hsel == 2 ? b2 : b3;
                    zp = (const uint4*)(g_zh + (size_t)s * 512);
                    pA = zp[lane * 2];
                    pB = zp[lane * 2 + 1];
                }
                float f[16];
                cvt8(cA, f);
                cvt8(cB, f + 8);
                #pragma unroll
                for (int k = 0; k < 16; k++) acc[k] += a * f[k];
            }
        }
    } else {
        for (int j = 0; j < deg; j++) {
            int s = g_srcp[e0 + j];
            float4 ss = ((const float4*)g_ssrc)[s];
            float4 ev = ((const float4*)g_esp)[e0 + j];
            float w0 = __expf(lrelu(ss.x + sd.x + ev.x) - mx.x);
            float w1 = __expf(lrelu(ss.y + sd.y + ev.y) - mx.y);
            float w2 = __expf(lrelu(ss.z + sd.z + ev.z) - mx.z);
            float w3 = __expf(lrelu(ss.w + sd.w + ev.w) - mx.w);
            float a = hsel == 0 ? w0 : hsel == 1 ? w1 : hsel == 2 ? w2 : w3;
            const uint4* zp = (const uint4*)(g_zh + (size_t)s * 512);
            uint4 pA = zp[lane * 2];
            uint4 pB = zp[lane * 2 + 1];
            float f[16];
            cvt8(pA, f);
            cvt8(pB, f + 8);
            #pragma unroll
            for (int k = 0; k < 16; k++) acc[k] += a * f[k];
        }
    }

    float sh = hsel == 0 ? su.x : hsel == 1 ? su.y : hsel == 2 ? su.z : su.w;
    float inv = 1.f / (sh + 1e-16f);
    float x[16];
    #pragma unroll
    for (int k = 0; k < 16; k++) x[k] = acc[k] * inv;

    // MVSiLU (lane-local; channels c0=2L, c1=2L+1)
    int c0 = lane * 2, c1 = lane * 2 + 1;
    float4 saA = ((const float4*)sa)[c0], sbA = ((const float4*)sbp)[c0];
    float4 saB = ((const float4*)sa)[c1], sbB = ((const float4*)sbp)[c1];
    mvgate(x, saA, sbA);
    mvgate(x + 8, saB, sbB);

    // residual
    const float4* hr = (const float4*)(g_h + (size_t)n * 512) + lane * 4;
    float4 r0 = hr[0], r1 = hr[1], r2 = hr[2], r3 = hr[3];
    x[0] += r0.x;  x[1] += r0.y;  x[2] += r0.z;  x[3] += r0.w;
    x[4] += r1.x;  x[5] += r1.y;  x[6] += r1.z;  x[7] += r1.w;
    x[8] += r2.x;  x[9] += r2.y;  x[10] += r2.z; x[11] += r2.w;
    x[12] += r3.x; x[13] += r3.y; x[14] += r3.z; x[15] += r3.w;

    // MVLayerNorm (lane-local channel norms)
    float ss0 = 0.f, ss1 = 0.f;
    #pragma unroll
    for (int k = 0; k < 8; k++) { ss0 += x[k] * x[k]; ss1 += x[8 + k] * x[8 + k]; }
    float cn = sqrtf(ss0) + sqrtf(ss1);
    #pragma unroll
    for (int off = 16; off; off >>= 1) cn += __shfl_xor_sync(FULL, cn, off);
    float mean = cn * (1.f / 64.f) + 1e-6f;
    float invm = 1.f / mean;
    float sc0 = lna[c0] * invm, sc1 = lna[c1] * invm;

    float4* hw = (float4*)(g_h + (size_t)n * 512) + lane * 4;
    hw[0] = make_float4(x[0] * sc0, x[1] * sc0, x[2] * sc0, x[3] * sc0);
    hw[1] = make_float4(x[4] * sc0, x[5] * sc0, x[6] * sc0, x[7] * sc0);
    hw[2] = make_float4(x[8] * sc1, x[9] * sc1, x[10] * sc1, x[11] * sc1);
    hw[3] = make_float4(x[12] * sc1, x[13] * sc1, x[14] * sc1, x[15] * sc1);
}

// ---------------- prepool (scalar blade) + graph pooling ----------------
__global__ void __launch_bounds__(64) k_prepool(const float* __restrict__ ppw,
        const float* __restrict__ ppb, const int* __restrict__ batch, int N) {
    __shared__ float x0[64];
    int n = blockIdx.x, tid = threadIdx.x;
    x0[tid] = g_h[(size_t)n * 512 + tid * 8];
    __syncthreads();
    float acc = ppb[tid];
    const float* wr = ppw + tid * 64;
    #pragma unroll 8
    for (int i = 0; i < 64; i++) acc += wr[i] * x0[i];
    atomicAdd(&g_gsum[batch[n] * 64 + tid], acc);
}

__global__ void __launch_bounds__(64) k_post(const float* __restrict__ pw1,
        const float* __restrict__ pb1, const float* __restrict__ pw2,
        const float* __restrict__ pb2, float* __restrict__ out) {
    __shared__ float sg[64];
    __shared__ float sh[64];
    int b = blockIdx.x, tid = threadIdx.x;
    sg[tid] = g_gsum[b * 64 + tid];
    __syncthreads();
    float a = pb1[tid];
    const float* wr = pw1 + tid * 64;
    #pragma unroll 8
    for (int i = 0; i < 64; i++) a += wr[i] * sg[i];
    float s = a * sigmoidf(a);
    sh[tid] = s * pw2[tid];
    __syncthreads();
    for (int st = 32; st; st >>= 1) {
        if (tid < st) sh[tid] += sh[tid + st];
        __syncthreads();
    }
    if (tid == 0) out[b] = sh[0] + pb2[0];
}

// ---------------- launch ----------------
extern "C" void kernel_launch(void* const* d_in, const int* in_sizes, int n_in,
                              void* d_out, int out_size) {
    const float* pos   = (const float*)d_in[0];
    const int*   zi    = (const int*)d_in[1];
    const int*   ei    = (const int*)d_in[2];
    const int*   batch = (const int*)d_in[3];
    const float* atomw = (const float*)d_in[4];
    const float* inw   = (const float*)d_in[5];
    const float* inb   = (const float*)d_in[6];
    const float* ew1   = (const float*)d_in[7];
    const float* eb1   = (const float*)d_in[8];
    const float* ew2   = (const float*)d_in[9];
    const float* eb2   = (const float*)d_in[10];
    const float* projw = (const float*)d_in[11];
    const float* projb = (const float*)d_in[12];
    const float* asrc  = (const float*)d_in[13];
    const float* adst  = (const float*)d_in[14];
    const float* wsrc  = (const float*)d_in[15];
    const float* wdst  = (const float*)d_in[16];
    const float* lna   = (const float*)d_in[17];
    const float* silua = (const float*)d_in[18];
    const float* silub = (const float*)d_in[19];
    const float* ppw   = (const float*)d_in[20];
    const float* ppb   = (const float*)d_in[21];
    const float* pw1   = (const float*)d_in[22];
    const float* pb1   = (const float*)d_in[23];
    const float* pw2   = (const float*)d_in[24];
    const float* pb2   = (const float*)d_in[25];
    float* out = (float*)d_out;

    int N = in_sizes[0] / 3;
    int E = in_sizes[2] / 2;
    const int* src = ei;
    const int* dst = ei + E;
    int G = (N + 1023) / 1024;

    cudaFuncSetAttribute(k_mvlin, cudaFuncAttributeMaxDynamicSharedMemorySize, 99584);

    // order: profile slot (#4) lands on the first k_mvlin
    k_zero<<<64, 256>>>(N);
    k_init<<<(E + 255) / 256, 256>>>(pos, batch, dst, N, E);
    k_embed<<<(N + 31) / 32, 256>>>(zi, batch, pos, atomw, inw, inb, N);
    k_mvlin<<<(N + 15) / 16, 256, 99584>>>(projw, projb, asrc, adst, wsrc, wdst, N);
    k_scanA<<<G, 1024>>>(N);
    k_scanB<<<G, 256>>>(N, E, G);
    k_edgefill<<<(E + 127) / 128, 128>>>(pos, src, dst, ew1, eb1, ew2, eb2, E);

    k_attn<<<(N + 3) / 4, 128>>>(silua, silub, lna, N);
    for (int l = 1; l < 4; l++) {
        k_mvlin<<<(N + 15) / 16, 256, 99584>>>(projw + (size_t)l * 4 * 64 * 64,
                                               projb + l * 64,
                                               asrc + l * 512, adst + l * 512,
                                               wsrc + l * 16, wdst + l * 16, N);
        k_attn<<<(N + 3) / 4, 128>>>(silua + l * 256, silub + l * 256, lna + l * 64, N);
    }

    k_prepool<<<N, 64>>>(ppw, ppb, batch, N);
    k_post<<<NB, 64>>>(pw1, pb1, pw2, pb2, out);
}

// round 8
// speedup vs baseline: 1.2642x; 1.0429x over previous
#include <cuda_runtime.h>
#include <cuda_fp16.h>
#include <math.h>

#define NN 20000
#define EE 320000
#define NB 256
#define HIDC 64

// ---------------- scratch (device globals; no allocation) ----------------
__device__ float  g_h[(size_t)NN * 512];
__device__ __half g_zh[(size_t)NN * 512];   // z in fp16 (aggregation-only consumer)
__device__ float  g_esp[(size_t)EE * 4];    // edge scalar, CSR order
__device__ int    g_srcp[EE];               // src, CSR order
__device__ float  g_ssrcA[NN * 4];          // logit partials, half 0
__device__ float  g_ssrcB[NN * 4];          // logit partials, half 1
__device__ float  g_sdstA[NN * 4];
__device__ float  g_sdstB[NN * 4];
__device__ float  g_cnt[NB];
__device__ float  g_psum[NB * 3];
__device__ int    g_deg[NN];
__device__ int    g_off[NN + 1];
__device__ int    g_cur[NN];
__device__ int    g_bsum[64];
__device__ float  g_gsum[NB * HIDC];

// ---------------- helpers ----------------
__device__ __forceinline__ float lrelu(float v) { return v > 0.f ? v : 0.2f * v; }
__device__ __forceinline__ float sigmoidf(float v) { return 1.f / (1.f + __expf(-v)); }

__device__ __forceinline__ void cvt8(uint4 p, float* f) {
    float2 t;
    t = __half22float2(*(__half2*)&p.x); f[0] = t.x; f[1] = t.y;
    t = __half22float2(*(__half2*)&p.y); f[2] = t.x; f[3] = t.y;
    t = __half22float2(*(__half2*)&p.z); f[4] = t.x; f[5] = t.y;
    t = __half22float2(*(__half2*)&p.w); f[6] = t.x; f[7] = t.y;
}

__device__ __forceinline__ void mvgate(float* x, float4 a, float4 b) {
    float gA = sigmoidf(a.x * x[0] + b.x);
    float nB = x[1] * x[1] + x[2] * x[2] + x[3] * x[3];
    float gB = sigmoidf(a.y * nB + b.y);
    float nC = x[4] * x[4] + x[5] * x[5] + x[6] * x[6];
    float gC = sigmoidf(a.z * nC + b.z);
    float gD = sigmoidf(a.w * x[7] * x[7] + b.w);
    x[0] *= gA; x[1] *= gB; x[2] *= gB; x[3] *= gB;
    x[4] *= gC; x[5] *= gC; x[6] *= gC; x[7] *= gD;
}

// ---------------- 0: zero scratch ----------------
__global__ void k_zero(int N) {
    int total = NB + NB * 3 + NB * HIDC + N;
    for (int i = blockIdx.x * blockDim.x + threadIdx.x; i < total; i += gridDim.x * blockDim.x) {
        if (i < NB) g_cnt[i] = 0.f;
        else if (i < NB + NB * 3) g_psum[i - NB] = 0.f;
        else if (i < NB + NB * 3 + NB * HIDC) g_gsum[i - NB - NB * 3] = 0.f;
        else g_deg[i - NB - NB * 3 - NB * HIDC] = 0;
    }
}

// ---------------- 1: batch stats + degree count ----------------
__global__ void k_init(const float* __restrict__ pos, const int* __restrict__ batch,
                       const int* __restrict__ dst, int N, int E) {
    int i = blockIdx.x * blockDim.x + threadIdx.x;
    if (i < N) {
        int b = batch[i];
        atomicAdd(&g_cnt[b], 1.f);
        atomicAdd(&g_psum[b * 3 + 0], pos[i * 3 + 0]);
        atomicAdd(&g_psum[b * 3 + 1], pos[i * 3 + 1]);
        atomicAdd(&g_psum[b * 3 + 2], pos[i * 3 + 2]);
    }
    if (i < E) atomicAdd(&g_deg[dst[i]], 1);
}

// ---------------- scan phase A ----------------
__global__ void __launch_bounds__(1024) k_scanA(int N) {
    __shared__ int swt[32];
    int t = threadIdx.x, b = blockIdx.x;
    int i = b * 1024 + t;
    int lane = t & 31, wid = t >> 5;
    int v = (i < N) ? g_deg[i] : 0;
    int x = v;
    #pragma unroll
    for (int o = 1; o < 32; o <<= 1) {
        int y = __shfl_up_sync(0xffffffffu, x, o);
        if (lane >= o) x += y;
    }
    if (lane == 31) swt[wid] = x;
    __syncthreads();
    if (t < 32) {
        int w = swt[t];
        #pragma unroll
        for (int o = 1; o < 32; o <<= 1) {
            int y = __shfl_up_sync(0xffffffffu, w, o);
            if (t >= o) w += y;
        }
        swt[t] = w;
    }
    __syncthreads();
    int base = (wid == 0) ? 0 : swt[wid - 1];
    if (i < N) g_off[i] = base + x - v;
    if (t == 1023) g_bsum[b] = base + x;
}

// ---------------- scan phase B ----------------
__global__ void __launch_bounds__(256) k_scanB(int N, int E, int G) {
    __shared__ int soff;
    int b = blockIdx.x, t = threadIdx.x;
    if (t == 0) {
        int s = 0;
        for (int j = 0; j < b; j++) s += g_bsum[j];
        soff = s;
        if (b == 0) g_off[N] = E;
    }
    __syncthreads();
    int s = soff;
    for (int k = t; k < 1024; k += 256) {
        int i = b * 1024 + k;
        if (i < N) {
            int val = g_off[i] + s;
            g_off[i] = val;
            g_cur[i] = val;
        }
    }
}

// ---------------- edge RBF-MLP + direct CSR scatter ----------------
__global__ void __launch_bounds__(128) k_edgefill(const float* __restrict__ pos,
        const int* __restrict__ src, const int* __restrict__ dst,
        const float* __restrict__ ew1, const float* __restrict__ eb1,
        const float* __restrict__ ew2, const float* __restrict__ eb2, int E) {
    __shared__ float s1[64 * 20];
    __shared__ float sb1[64];
    __shared__ float s2T[4 * 64];
    __shared__ float sb2v[4];
    int tid = threadIdx.x;
    for (int i = tid; i < 1280; i += 128) s1[i] = ew1[i];
    if (tid < 64) sb1[tid] = eb1[tid];
    for (int i = tid; i < 256; i += 128) {
        int o = i >> 2, h = i & 3;
        s2T[i] = ew2[h * 64 + o];
    }
    if (tid < 4) sb2v[tid] = eb2[tid];
    __syncthreads();
    int e = blockIdx.x * 128 + tid;
    if (e >= E) return;
    int s = src[e], d = dst[e];
    float dx = pos[s * 3] - pos[d * 3];
    float dy = pos[s * 3 + 1] - pos[d * 3 + 1];
    float dz = pos[s * 3 + 2] - pos[d * 3 + 2];
    float d2 = dx * dx + dy * dy + dz * dz;
    float dist = d2 > 0.f ? sqrtf(d2) : 0.f;
    const float width = 10.f / 19.f;
    const float invw = 19.f / 10.f;
    float rbf[20];
    #pragma unroll
    for (int k = 0; k < 20; k++) {
        float t = (dist - width * k) * invw;
        rbf[k] = __expf(-0.5f * t * t);
    }
    float a0 = 0.f, a1 = 0.f, a2 = 0.f, a3 = 0.f;
    #pragma unroll 2
    for (int o = 0; o < 64; o++) {
        float hv = sb1[o];
        const float4* w4 = (const float4*)&s1[o * 20];
        #pragma unroll
        for (int q = 0; q < 5; q++) {
            float4 w = w4[q];
            hv += w.x * rbf[q * 4] + w.y * rbf[q * 4 + 1] + w.z * rbf[q * 4 + 2] + w.w * rbf[q * 4 + 3];
        }
        float sv = hv * sigmoidf(hv);
        float4 w2 = ((const float4*)s2T)[o];
        a0 += w2.x * sv; a1 += w2.y * sv; a2 += w2.z * sv; a3 += w2.w * sv;
    }
    int p = atomicAdd(&g_cur[d], 1);
    g_srcp[p] = s;
    ((float4*)g_esp)[p] = make_float4(a0 + sb2v[0], a1 + sb2v[1], a2 + sb2v[2], a3 + sb2v[3]);
}

// ---------------- node embedding + input proj ----------------
__global__ void __launch_bounds__(256) k_embed(const int* __restrict__ zi,
        const int* __restrict__ batch, const float* __restrict__ pos,
        const float* __restrict__ atomw, const float* __restrict__ inw,
        const float* __restrict__ inb, int N) {
    __shared__ float wT[65 * 68];
    __shared__ float aT[64 * 36];
    __shared__ float sb[64];
    __shared__ float spx[32], spy[32], spz[32];
    __shared__ int   sz[32];
    int tid = threadIdx.x;
    int n0 = blockIdx.x * 32;

    if (tid < 32) {
        int n = n0 + tid;
        if (n < N) {
            int b = batch[n];
            float ic = 1.f / fmaxf(g_cnt[b], 1.f);
            spx[tid] = pos[n * 3 + 0] - g_psum[b * 3 + 0] * ic;
            spy[tid] = pos[n * 3 + 1] - g_psum[b * 3 + 1] * ic;
            spz[tid] = pos[n * 3 + 2] - g_psum[b * 3 + 2] * ic;
            sz[tid] = zi[n];
        } else { spx[tid] = spy[tid] = spz[tid] = 0.f; sz[tid] = 0; }
    }
    if (tid >= 32 && tid < 96) sb[tid - 32] = inb[tid - 32];
    for (int idx = tid; idx < 64 * 65; idx += 256) {
        int o = idx / 65, i = idx % 65;
        wT[i * 68 + o] = inw[idx];
    }
    __syncthreads();
    for (int idx = tid; idx < 64 * 32; idx += 256) {
        int n = idx & 31, i = idx >> 5;
        aT[i * 36 + n] = atomw[(size_t)sz[n] * 64 + i];
    }
    __syncthreads();

    int ox = (tid & 15) * 4;
    int nl = (tid >> 4) * 2;
    float acc[2][4];
    #pragma unroll
    for (int a = 0; a < 2; a++)
        #pragma unroll
        for (int b = 0; b < 4; b++) acc[a][b] = 0.f;

    #pragma unroll 8
    for (int i = 0; i < 64; i++) {
        float4 w = *(const float4*)&wT[i * 68 + ox];
        float2 a = *(const float2*)&aT[i * 36 + nl];
        acc[0][0] += a.x * w.x; acc[0][1] += a.x * w.y; acc[0][2] += a.x * w.z; acc[0][3] += a.x * w.w;
        acc[1][0] += a.y * w.x; acc[1][1] += a.y * w.y; acc[1][2] += a.y * w.z; acc[1][3] += a.y * w.w;
    }

    #pragma unroll
    for (int jj = 0; jj < 2; jj++) {
        int n = n0 + nl + jj;
        if (n >= N) break;
        float px = spx[nl + jj], py = spy[nl + jj], pz = spz[nl + jj];
        #pragma unroll
        for (int cc = 0; cc < 4; cc++) {
            int o = ox + cc;
            float vw = wT[64 * 68 + o];
            float4* hp = (float4*)(g_h + (size_t)n * 512 + o * 8);
            hp[0] = make_float4(acc[jj][cc] + sb[o], vw * px, vw * py, vw * pz);
            hp[1] = make_float4(0.f, 0.f, 0.f, 0.f);
        }
    }
}

// ---------------- per-grade MVLinear v2: half-split, 4ox4nx4b register tiles ----------------
// grid (ceil(N/64), 2); blockIdx.y = half. W transposed in smem at stride 68 (float4-aligned).
__global__ void __launch_bounds__(256, 2) k_mvlin(const float* __restrict__ W,
        const float* __restrict__ B, const float* __restrict__ Asrc,
        const float* __restrict__ Adst, const float* __restrict__ Wsrc,
        const float* __restrict__ Wdst, int N) {
    extern __shared__ float sm[];
    float* WsT = sm;            // 2 grades * 64i * 68 = 8704 floats
    float* Xs  = sm + 8704;     // 64 nodes * 256 floats = 16384
    int tid = threadIdx.x;
    int half = blockIdx.y;
    int n0 = blockIdx.x * 64;
    const unsigned FULL = 0xffffffffu;

    const float* Wg = W + (size_t)(half * 2) * 4096;
    for (int idx = tid; idx < 4096; idx += 256) {
        int o = idx >> 6, i = idx & 63;
        WsT[i * 68 + o]        = Wg[o * 64 + i];
        WsT[4352 + i * 68 + o] = Wg[4096 + o * 64 + i];
    }
    for (int idx = tid; idx < 4096; idx += 256) {
        int j = idx >> 6, i4 = idx & 63;
        int n = n0 + j;
        float4 v = (n < N) ? ((const float4*)g_h)[(size_t)n * 128 + i4 * 2 + half]
                           : make_float4(0.f, 0.f, 0.f, 0.f);
        *(float4*)&Xs[j * 256 + i4 * 4] = v;
    }
    __syncthreads();

    int og = tid & 15, ng = tid >> 4;
    int o0 = og * 4, nb = ng * 4;
    float acc[4][4][4];   // [oo][jj][blade]
    #pragma unroll
    for (int a = 0; a < 4; a++)
        #pragma unroll
        for (int b = 0; b < 4; b++)
            #pragma unroll
            for (int c = 0; c < 4; c++) acc[a][b][c] = 0.f;

    const float* WsA = WsT;
    const float* WsB = WsT + 4352;
    if (half == 0) {
        #pragma unroll 2
        for (int i = 0; i < 64; i++) {
            float4 wa = *(const float4*)&WsA[i * 68 + o0];
            float4 wb = *(const float4*)&WsB[i * 68 + o0];
            float4 xv[4];
            #pragma unroll
            for (int jj = 0; jj < 4; jj++) xv[jj] = *(const float4*)&Xs[(nb + jj) * 256 + i * 4];
            float wA[4] = {wa.x, wa.y, wa.z, wa.w};
            float wB[4] = {wb.x, wb.y, wb.z, wb.w};
            #pragma unroll
            for (int oo = 0; oo < 4; oo++)
                #pragma unroll
                for (int jj = 0; jj < 4; jj++) {
                    acc[oo][jj][0] += wA[oo] * xv[jj].x;   // blade0 grade0
                    acc[oo][jj][1] += wB[oo] * xv[jj].y;   // blades1-3 grade1
                    acc[oo][jj][2] += wB[oo] * xv[jj].z;
                    acc[oo][jj][3] += wB[oo] * xv[jj].w;
                }
        }
    } else {
        #pragma unroll 2
        for (int i = 0; i < 64; i++) {
            float4 wa = *(const float4*)&WsA[i * 68 + o0];
            float4 wb = *(const float4*)&WsB[i * 68 + o0];
            float4 xv[4];
            #pragma unroll
            for (int jj = 0; jj < 4; jj++) xv[jj] = *(const float4*)&Xs[(nb + jj) * 256 + i * 4];
            float wA[4] = {wa.x, wa.y, wa.z, wa.w};
            float wB[4] = {wb.x, wb.y, wb.z, wb.w};
            #pragma unroll
            for (int oo = 0; oo < 4; oo++)
                #pragma unroll
                for (int jj = 0; jj < 4; jj++) {
                    acc[oo][jj][0] += wA[oo] * xv[jj].x;   // blades4-6 grade2
                    acc[oo][jj][1] += wA[oo] * xv[jj].y;
                    acc[oo][jj][2] += wA[oo] * xv[jj].z;
                    acc[oo][jj][3] += wB[oo] * xv[jj].w;   // blade7 grade3
                }
        }
    }

    // epilogue: bias, fp16 z store, logit partials
    int head = og >> 2;
    float ws0, ws1, wd0, wd1;
    if (half == 0) { ws0 = Wsrc[head * 4 + 0]; ws1 = Wsrc[head * 4 + 1];
                     wd0 = Wdst[head * 4 + 0]; wd1 = Wdst[head * 4 + 1]; }
    else           { ws0 = Wsrc[head * 4 + 2]; ws1 = Wsrc[head * 4 + 3];
                     wd0 = Wdst[head * 4 + 2]; wd1 = Wdst[head * 4 + 3]; }
    float avs[4][4], avd[4][4], bias[4];
    #pragma unroll
    for (int oo = 0; oo < 4; oo++) {
        int o = o0 + oo;
        const float* Ab = Asrc + o * 8 + half * 4;
        const float* Db = Adst + o * 8 + half * 4;
        if (half == 0) {
            avs[oo][0] = Ab[0] * ws0; avs[oo][1] = Ab[1] * ws1; avs[oo][2] = Ab[2] * ws1; avs[oo][3] = Ab[3] * ws1;
            avd[oo][0] = Db[0] * wd0; avd[oo][1] = Db[1] * wd1; avd[oo][2] = Db[2] * wd1; avd[oo][3] = Db[3] * wd1;
            bias[oo] = B[o];
        } else {
            avs[oo][0] = Ab[0] * ws0; avs[oo][1] = Ab[1] * ws0; avs[oo][2] = Ab[2] * ws0; avs[oo][3] = Ab[3] * ws1;
            avd[oo][0] = Db[0] * wd0; avd[oo][1] = Db[1] * wd0; avd[oo][2] = Db[2] * wd0; avd[oo][3] = Db[3] * wd1;
            bias[oo] = 0.f;
        }
    }

    #pragma unroll
    for (int jj = 0; jj < 4; jj++) {
        int n = n0 + nb + jj;
        bool ok = (n < N);
        float ps = 0.f, pd = 0.f;
        #pragma unroll
        for (int oo = 0; oo < 4; oo++) {
            float v0 = acc[oo][jj][0] + bias[oo];
            float v1 = acc[oo][jj][1], v2 = acc[oo][jj][2], v3 = acc[oo][jj][3];
            if (ok) {
                __half2 ha = __floats2half2_rn(v0, v1);
                __half2 hb = __floats2half2_rn(v2, v3);
                uint2 u;
                u.x = *(unsigned*)&ha;
                u.y = *(unsigned*)&hb;
                *(uint2*)(g_zh + (size_t)n * 512 + (o0 + oo) * 8 + half * 4) = u;
            }
            ps += v0 * avs[oo][0] + v1 * avs[oo][1] + v2 * avs[oo][2] + v3 * avs[oo][3];
            pd += v0 * avd[oo][0] + v1 * avd[oo][1] + v2 * avd[oo][2] + v3 * avd[oo][3];
        }
        ps += __shfl_xor_sync(FULL, ps, 1);
        ps += __shfl_xor_sync(FULL, ps, 2);
        pd += __shfl_xor_sync(FULL, pd, 1);
        pd += __shfl_xor_sync(FULL, pd, 2);
        if ((tid & 3) == 0 && ok) {
            if (half == 0) { g_ssrcA[n * 4 + head] = ps; g_sdstA[n * 4 + head] = pd; }
            else           { g_ssrcB[n * 4 + head] = ps; g_sdstB[n * 4 + head] = pd; }
        }
    }
}

// ---------------- warp-per-node attention + MVSiLU + residual + LN ----------------
__global__ void __launch_bounds__(128) k_attn(const float* __restrict__ sa,
        const float* __restrict__ sbp, const float* __restrict__ lna, int N) {
    int n = blockIdx.x * 4 + (threadIdx.x >> 5);
    int lane = threadIdx.x & 31;
    if (n >= N) return;
    int e0 = g_off[n];
    int deg = g_off[n + 1] - e0;
    float4 sdA = ((const float4*)g_sdstA)[n];
    float4 sdB = ((const float4*)g_sdstB)[n];
    float4 sd = make_float4(sdA.x + sdB.x, sdA.y + sdB.y, sdA.z + sdB.z, sdA.w + sdB.w);
    const unsigned FULL = 0xffffffffu;
    int hsel = lane >> 3;

    bool fits = (deg <= 128);
    float4 lgr[4];
    int sr[4];
    float4 mx = make_float4(-3e38f, -3e38f, -3e38f, -3e38f);

    if (fits) {
        #pragma unroll
        for (int r = 0; r < 4; r++) {
            int j = lane + r * 32;
            if (j < deg) {
                int s = g_srcp[e0 + j];
                sr[r] = s;
                float4 sA = ((const float4*)g_ssrcA)[s];
                float4 sB = ((const float4*)g_ssrcB)[s];
                float4 ev = ((const float4*)g_esp)[e0 + j];
                float4 lg = make_float4(lrelu(sA.x + sB.x + sd.x + ev.x),
                                        lrelu(sA.y + sB.y + sd.y + ev.y),
                                        lrelu(sA.z + sB.z + sd.z + ev.z),
                                        lrelu(sA.w + sB.w + sd.w + ev.w));
                lgr[r] = lg;
                mx.x = fmaxf(mx.x, lg.x); mx.y = fmaxf(mx.y, lg.y);
                mx.z = fmaxf(mx.z, lg.z); mx.w = fmaxf(mx.w, lg.w);
            } else {
                sr[r] = 0;
                lgr[r] = make_float4(-3e38f, -3e38f, -3e38f, -3e38f);
            }
        }
    } else {
        for (int j = lane; j < deg; j += 32) {
            int s = g_srcp[e0 + j];
            float4 sA = ((const float4*)g_ssrcA)[s];
            float4 sB = ((const float4*)g_ssrcB)[s];
            float4 ev = ((const float4*)g_esp)[e0 + j];
            mx.x = fmaxf(mx.x, lrelu(sA.x + sB.x + sd.x + ev.x));
            mx.y = fmaxf(mx.y, lrelu(sA.y + sB.y + sd.y + ev.y));
            mx.z = fmaxf(mx.z, lrelu(sA.z + sB.z + sd.z + ev.z));
            mx.w = fmaxf(mx.w, lrelu(sA.w + sB.w + sd.w + ev.w));
        }
    }
    #pragma unroll
    for (int off = 16; off; off >>= 1) {
        mx.x = fmaxf(mx.x, __shfl_xor_sync(FULL, mx.x, off));
        mx.y = fmaxf(mx.y, __shfl_xor_sync(FULL, mx.y, off));
        mx.z = fmaxf(mx.z, __shfl_xor_sync(FULL, mx.z, off));
        mx.w = fmaxf(mx.w, __shfl_xor_sync(FULL, mx.w, off));
    }

    float4 su = make_float4(0.f, 0.f, 0.f, 0.f);
    if (fits) {
        #pragma unroll
        for (int r = 0; r < 4; r++) {
            int j = lane + r * 32;
            if (j < deg) {
                float4 lg = lgr[r];
                lg.x = __expf(lg.x - mx.x); lg.y = __expf(lg.y - mx.y);
                lg.z = __expf(lg.z - mx.z); lg.w = __expf(lg.w - mx.w);
                lgr[r] = lg;
                su.x += lg.x; su.y += lg.y; su.z += lg.z; su.w += lg.w;
            } else {
                lgr[r] = make_float4(0.f, 0.f, 0.f, 0.f);
            }
        }
    } else {
        for (int j = lane; j < deg; j += 32) {
            int s = g_srcp[e0 + j];
            float4 sA = ((const float4*)g_ssrcA)[s];
            float4 sB = ((const float4*)g_ssrcB)[s];
            float4 ev = ((const float4*)g_esp)[e0 + j];
            su.x += __expf(lrelu(sA.x + sB.x + sd.x + ev.x) - mx.x);
            su.y += __expf(lrelu(sA.y + sB.y + sd.y + ev.y) - mx.y);
            su.z += __expf(lrelu(sA.z + sB.z + sd.z + ev.z) - mx.z);
            su.w += __expf(lrelu(sA.w + sB.w + sd.w + ev.w) - mx.w);
        }
    }
    #pragma unroll
    for (int off = 16; off; off >>= 1) {
        su.x += __shfl_xor_sync(FULL, su.x, off);
        su.y += __shfl_xor_sync(FULL, su.y, off);
        su.z += __shfl_xor_sync(FULL, su.z, off);
        su.w += __shfl_xor_sync(FULL, su.w, off);
    }

    float acc[16];
    #pragma unroll
    for (int k = 0; k < 16; k++) acc[k] = 0.f;

    if (fits) {
        #pragma unroll
        for (int r = 0; r < 4; r++) {
            int base = r * 32;
            if (base >= deg) break;
            int m = min(32, deg - base);
            float4 lgv = lgr[r];
            int sv = sr[r];
            int s0 = __shfl_sync(FULL, sv, 0);
            float b0 = __shfl_sync(FULL, lgv.x, 0);
            float b1 = __shfl_sync(FULL, lgv.y, 0);
            float b2 = __shfl_sync(FULL, lgv.z, 0);
            float b3 = __shfl_sync(FULL, lgv.w, 0);
            float aP = hsel == 0 ? b0 : hsel == 1 ? b1 : hsel == 2 ? b2 : b3;
            const uint4* zp = (const uint4*)(g_zh + (size_t)s0 * 512);
            uint4 pA = zp[lane * 2];
            uint4 pB = zp[lane * 2 + 1];
            for (int l = 0; l < m; l++) {
                uint4 cA = pA, cB = pB;
                float a = aP;
                if (l + 1 < m) {
                    int s = __shfl_sync(FULL, sv, l + 1);
                    b0 = __shfl_sync(FULL, lgv.x, l + 1);
                    b1 = __shfl_sync(FULL, lgv.y, l + 1);
                    b2 = __shfl_sync(FULL, lgv.z, l + 1);
                    b3 = __shfl_sync(FULL, lgv.w, l + 1);
                    aP = hsel == 0 ? b0 : hsel == 1 ? b1 : hsel == 2 ? b2 : b3;
                    zp = (const uint4*)(g_zh + (size_t)s * 512);
                    pA = zp[lane * 2];
                    pB = zp[lane * 2 + 1];
                }
                float f[16];
                cvt8(cA, f);
                cvt8(cB, f + 8);
                #pragma unroll
                for (int k = 0; k < 16; k++) acc[k] += a * f[k];
            }
        }
    } else {
        for (int j = 0; j < deg; j++) {
            int s = g_srcp[e0 + j];
            float4 sA = ((const float4*)g_ssrcA)[s];
            float4 sB = ((const float4*)g_ssrcB)[s];
            float4 ev = ((const float4*)g_esp)[e0 + j];
            float w0 = __expf(lrelu(sA.x + sB.x + sd.x + ev.x) - mx.x);
            float w1 = __expf(lrelu(sA.y + sB.y + sd.y + ev.y) - mx.y);
            float w2 = __expf(lrelu(sA.z + sB.z + sd.z + ev.z) - mx.z);
            float w3 = __expf(lrelu(sA.w + sB.w + sd.w + ev.w) - mx.w);
            float a = hsel == 0 ? w0 : hsel == 1 ? w1 : hsel == 2 ? w2 : w3;
            const uint4* zp = (const uint4*)(g_zh + (size_t)s * 512);
            uint4 pA = zp[lane * 2];
            uint4 pB = zp[lane * 2 + 1];
            float f[16];
            cvt8(pA, f);
            cvt8(pB, f + 8);
            #pragma unroll
            for (int k = 0; k < 16; k++) acc[k] += a * f[k];
        }
    }

    float sh = hsel == 0 ? su.x : hsel == 1 ? su.y : hsel == 2 ? su.z : su.w;
    float inv = 1.f / (sh + 1e-16f);
    float x[16];
    #pragma unroll
    for (int k = 0; k < 16; k++) x[k] = acc[k] * inv;

    int c0 = lane * 2, c1 = lane * 2 + 1;
    float4 saA = ((const float4*)sa)[c0], sbA = ((const float4*)sbp)[c0];
    float4 saB = ((const float4*)sa)[c1], sbB = ((const float4*)sbp)[c1];
    mvgate(x, saA, sbA);
    mvgate(x + 8, saB, sbB);

    const float4* hr = (const float4*)(g_h + (size_t)n * 512) + lane * 4;
    float4 r0 = hr[0], r1 = hr[1], r2 = hr[2], r3 = hr[3];
    x[0] += r0.x;  x[1] += r0.y;  x[2] += r0.z;  x[3] += r0.w;
    x[4] += r1.x;  x[5] += r1.y;  x[6] += r1.z;  x[7] += r1.w;
    x[8] += r2.x;  x[9] += r2.y;  x[10] += r2.z; x[11] += r2.w;
    x[12] += r3.x; x[13] += r3.y; x[14] += r3.z; x[15] += r3.w;

    float ss0 = 0.f, ss1 = 0.f;
    #pragma unroll
    for (int k = 0; k < 8; k++) { ss0 += x[k] * x[k]; ss1 += x[8 + k] * x[8 + k]; }
    float cn = sqrtf(ss0) + sqrtf(ss1);
    #pragma unroll
    for (int off = 16; off; off >>= 1) cn += __shfl_xor_sync(FULL, cn, off);
    float mean = cn * (1.f / 64.f) + 1e-6f;
    float invm = 1.f / mean;
    float sc0 = lna[c0] * invm, sc1 = lna[c1] * invm;

    float4* hw = (float4*)(g_h + (size_t)n * 512) + lane * 4;
    hw[0] = make_float4(x[0] * sc0, x[1] * sc0, x[2] * sc0, x[3] * sc0);
    hw[1] = make_float4(x[4] * sc0, x[5] * sc0, x[6] * sc0, x[7] * sc0);
    hw[2] = make_float4(x[8] * sc1, x[9] * sc1, x[10] * sc1, x[11] * sc1);
    hw[3] = make_float4(x[12] * sc1, x[13] * sc1, x[14] * sc1, x[15] * sc1);
}

// ---------------- prepool + graph pooling ----------------
__global__ void __launch_bounds__(64) k_prepool(const float* __restrict__ ppw,
        const float* __restrict__ ppb, const int* __restrict__ batch, int N) {
    __shared__ float x0[64];
    int n = blockIdx.x, tid = threadIdx.x;
    x0[tid] = g_h[(size_t)n * 512 + tid * 8];
    __syncthreads();
    float acc = ppb[tid];
    const float* wr = ppw + tid * 64;
    #pragma unroll 8
    for (int i = 0; i < 64; i++) acc += wr[i] * x0[i];
    atomicAdd(&g_gsum[batch[n] * 64 + tid], acc);
}

__global__ void __launch_bounds__(64) k_post(const float* __restrict__ pw1,
        const float* __restrict__ pb1, const float* __restrict__ pw2,
        const float* __restrict__ pb2, float* __restrict__ out) {
    __shared__ float sg[64];
    __shared__ float sh[64];
    int b = blockIdx.x, tid = threadIdx.x;
    sg[tid] = g_gsum[b * 64 + tid];
    __syncthreads();
    float a = pb1[tid];
    const float* wr = pw1 + tid * 64;
    #pragma unroll 8
    for (int i = 0; i < 64; i++) a += wr[i] * sg[i];
    float s = a * sigmoidf(a);
    sh[tid] = s * pw2[tid];
    __syncthreads();
    for (int st = 32; st; st >>= 1) {
        if (tid < st) sh[tid] += sh[tid + st];
        __syncthreads();
    }
    if (tid == 0) out[b] = sh[0] + pb2[0];
}

// ---------------- launch ----------------
extern "C" void kernel_launch(void* const* d_in, const int* in_sizes, int n_in,
                              void* d_out, int out_size) {
    const float* pos   = (const float*)d_in[0];
    const int*   zi    = (const int*)d_in[1];
    const int*   ei    = (const int*)d_in[2];
    const int*   batch = (const int*)d_in[3];
    const float* atomw = (const float*)d_in[4];
    const float* inw   = (const float*)d_in[5];
    const float* inb   = (const float*)d_in[6];
    const float* ew1   = (const float*)d_in[7];
    const float* eb1   = (const float*)d_in[8];
    const float* ew2   = (const float*)d_in[9];
    const float* eb2   = (const float*)d_in[10];
    const float* projw = (const float*)d_in[11];
    const float* projb = (const float*)d_in[12];
    const float* asrc  = (const float*)d_in[13];
    const float* adst  = (const float*)d_in[14];
    const float* wsrc  = (const float*)d_in[15];
    const float* wdst  = (const float*)d_in[16];
    const float* lna   = (const float*)d_in[17];
    const float* silua = (const float*)d_in[18];
    const float* silub = (const float*)d_in[19];
    const float* ppw   = (const float*)d_in[20];
    const float* ppb   = (const float*)d_in[21];
    const float* pw1   = (const float*)d_in[22];
    const float* pb1   = (const float*)d_in[23];
    const float* pw2   = (const float*)d_in[24];
    const float* pb2   = (const float*)d_in[25];
    float* out = (float*)d_out;

    int N = in_sizes[0] / 3;
    int E = in_sizes[2] / 2;
    const int* src = ei;
    const int* dst = ei + E;
    int G = (N + 1023) / 1024;
    const int MVSMEM = (8704 + 16384) * 4;   // 100352 B

    cudaFuncSetAttribute(k_mvlin, cudaFuncAttributeMaxDynamicSharedMemorySize, MVSMEM);

    k_zero<<<64, 256>>>(N);
    k_init<<<(E + 255) / 256, 256>>>(pos, batch, dst, N, E);
    k_embed<<<(N + 31) / 32, 256>>>(zi, batch, pos, atomw, inw, inb, N);
    dim3 mvgrid((N + 63) / 64, 2);
    k_mvlin<<<mvgrid, 256, MVSMEM>>>(projw, projb, asrc, adst, wsrc, wdst, N);
    k_scanA<<<G, 1024>>>(N);
    k_scanB<<<G, 256>>>(N, E, G);
    k_edgefill<<<(E + 127) / 128, 128>>>(pos, src, dst, ew1, eb1, ew2, eb2, E);

    k_attn<<<(N + 3) / 4, 128>>>(silua, silub, lna, N);
    for (int l = 1; l < 4; l++) {
        k_mvlin<<<mvgrid, 256, MVSMEM>>>(projw + (size_t)l * 4 * 64 * 64,
                                         projb + l * 64,
                                         asrc + l * 512, adst + l * 512,
                                         wsrc + l * 16, wdst + l * 16, N);
        k_attn<<<(N + 3) / 4, 128>>>(silua + l * 256, silub + l * 256, lna + l * 64, N);
    }

    k_prepool<<<N, 64>>>(ppw, ppb, batch, N);
    k_post<<<NB, 64>>>(pw1, pb1, pw2, pb2, out);
}

// round 9
// speedup vs baseline: 1.4008x; 1.1081x over previous
#include <cuda_runtime.h>
#include <cuda_fp16.h>
#include <math.h>

#define NN 20000
#define EE 320000
#define NB 256
#define HIDC 64

// ---------------- scratch (device globals; no allocation) ----------------
__device__ float  g_h[(size_t)NN * 512];
__device__ __half g_zh[(size_t)NN * 512];
__device__ float  g_esp[(size_t)EE * 4];
__device__ int    g_srcp[EE];
__device__ float  g_ssrcA[NN * 4];
__device__ float  g_ssrcB[NN * 4];
__device__ float  g_sdstA[NN * 4];
__device__ float  g_sdstB[NN * 4];
__device__ float  g_ssrc[NN * 4];    // combined
__device__ float  g_sdst[NN * 4];    // combined
__device__ float  g_cnt[NB];
__device__ float  g_psum[NB * 3];
__device__ int    g_deg[NN];
__device__ int    g_off[NN + 1];
__device__ int    g_cur[NN];
__device__ int    g_bsum[64];
__device__ float  g_gsum[NB * HIDC];

// ---------------- helpers ----------------
__device__ __forceinline__ float lrelu(float v) { return v > 0.f ? v : 0.2f * v; }
__device__ __forceinline__ float sigmoidf(float v) { return 1.f / (1.f + __expf(-v)); }

__device__ __forceinline__ void cvt8(uint4 p, float* f) {
    float2 t;
    t = __half22float2(*(__half2*)&p.x); f[0] = t.x; f[1] = t.y;
    t = __half22float2(*(__half2*)&p.y); f[2] = t.x; f[3] = t.y;
    t = __half22float2(*(__half2*)&p.z); f[4] = t.x; f[5] = t.y;
    t = __half22float2(*(__half2*)&p.w); f[6] = t.x; f[7] = t.y;
}

__device__ __forceinline__ void mvgate(float* x, float4 a, float4 b) {
    float gA = sigmoidf(a.x * x[0] + b.x);
    float nB = x[1] * x[1] + x[2] * x[2] + x[3] * x[3];
    float gB = sigmoidf(a.y * nB + b.y);
    float nC = x[4] * x[4] + x[5] * x[5] + x[6] * x[6];
    float gC = sigmoidf(a.z * nC + b.z);
    float gD = sigmoidf(a.w * x[7] * x[7] + b.w);
    x[0] *= gA; x[1] *= gB; x[2] *= gB; x[3] *= gB;
    x[4] *= gC; x[5] *= gC; x[6] *= gC; x[7] *= gD;
}

// ---------------- 0: zero scratch ----------------
__global__ void k_zero(int N) {
    int total = NB + NB * 3 + NB * HIDC + N;
    for (int i = blockIdx.x * blockDim.x + threadIdx.x; i < total; i += gridDim.x * blockDim.x) {
        if (i < NB) g_cnt[i] = 0.f;
        else if (i < NB + NB * 3) g_psum[i - NB] = 0.f;
        else if (i < NB + NB * 3 + NB * HIDC) g_gsum[i - NB - NB * 3] = 0.f;
        else g_deg[i - NB - NB * 3 - NB * HIDC] = 0;
    }
}

// ---------------- 1: batch stats + degree count ----------------
__global__ void k_init(const float* __restrict__ pos, const int* __restrict__ batch,
                       const int* __restrict__ dst, int N, int E) {
    int i = blockIdx.x * blockDim.x + threadIdx.x;
    if (i < N) {
        int b = batch[i];
        atomicAdd(&g_cnt[b], 1.f);
        atomicAdd(&g_psum[b * 3 + 0], pos[i * 3 + 0]);
        atomicAdd(&g_psum[b * 3 + 1], pos[i * 3 + 1]);
        atomicAdd(&g_psum[b * 3 + 2], pos[i * 3 + 2]);
    }
    if (i < E) atomicAdd(&g_deg[dst[i]], 1);
}

// ---------------- scan phase A ----------------
__global__ void __launch_bounds__(1024) k_scanA(int N) {
    __shared__ int swt[32];
    int t = threadIdx.x, b = blockIdx.x;
    int i = b * 1024 + t;
    int lane = t & 31, wid = t >> 5;
    int v = (i < N) ? g_deg[i] : 0;
    int x = v;
    #pragma unroll
    for (int o = 1; o < 32; o <<= 1) {
        int y = __shfl_up_sync(0xffffffffu, x, o);
        if (lane >= o) x += y;
    }
    if (lane == 31) swt[wid] = x;
    __syncthreads();
    if (t < 32) {
        int w = swt[t];
        #pragma unroll
        for (int o = 1; o < 32; o <<= 1) {
            int y = __shfl_up_sync(0xffffffffu, w, o);
            if (t >= o) w += y;
        }
        swt[t] = w;
    }
    __syncthreads();
    int base = (wid == 0) ? 0 : swt[wid - 1];
    if (i < N) g_off[i] = base + x - v;
    if (t == 1023) g_bsum[b] = base + x;
}

// ---------------- scan phase B ----------------
__global__ void __launch_bounds__(256) k_scanB(int N, int E, int G) {
    __shared__ int soff;
    int b = blockIdx.x, t = threadIdx.x;
    if (t == 0) {
        int s = 0;
        for (int j = 0; j < b; j++) s += g_bsum[j];
        soff = s;
        if (b == 0) g_off[N] = E;
    }
    __syncthreads();
    int s = soff;
    for (int k = t; k < 1024; k += 256) {
        int i = b * 1024 + k;
        if (i < N) {
            int val = g_off[i] + s;
            g_off[i] = val;
            g_cur[i] = val;
        }
    }
}

// ---------------- edge RBF-MLP + direct CSR scatter ----------------
__global__ void __launch_bounds__(128) k_edgefill(const float* __restrict__ pos,
        const int* __restrict__ src, const int* __restrict__ dst,
        const float* __restrict__ ew1, const float* __restrict__ eb1,
        const float* __restrict__ ew2, const float* __restrict__ eb2, int E) {
    __shared__ float s1[64 * 20];
    __shared__ float sb1[64];
    __shared__ float s2T[4 * 64];
    __shared__ float sb2v[4];
    int tid = threadIdx.x;
    for (int i = tid; i < 1280; i += 128) s1[i] = ew1[i];
    if (tid < 64) sb1[tid] = eb1[tid];
    for (int i = tid; i < 256; i += 128) {
        int o = i >> 2, h = i & 3;
        s2T[i] = ew2[h * 64 + o];
    }
    if (tid < 4) sb2v[tid] = eb2[tid];
    __syncthreads();
    int e = blockIdx.x * 128 + tid;
    if (e >= E) return;
    int s = src[e], d = dst[e];
    float dx = pos[s * 3] - pos[d * 3];
    float dy = pos[s * 3 + 1] - pos[d * 3 + 1];
    float dz = pos[s * 3 + 2] - pos[d * 3 + 2];
    float d2 = dx * dx + dy * dy + dz * dz;
    float dist = d2 > 0.f ? sqrtf(d2) : 0.f;
    const float width = 10.f / 19.f;
    const float invw = 19.f / 10.f;
    float rbf[20];
    #pragma unroll
    for (int k = 0; k < 20; k++) {
        float t = (dist - width * k) * invw;
        rbf[k] = __expf(-0.5f * t * t);
    }
    float a0 = 0.f, a1 = 0.f, a2 = 0.f, a3 = 0.f;
    #pragma unroll 2
    for (int o = 0; o < 64; o++) {
        float hv = sb1[o];
        const float4* w4 = (const float4*)&s1[o * 20];
        #pragma unroll
        for (int q = 0; q < 5; q++) {
            float4 w = w4[q];
            hv += w.x * rbf[q * 4] + w.y * rbf[q * 4 + 1] + w.z * rbf[q * 4 + 2] + w.w * rbf[q * 4 + 3];
        }
        float sv = hv * sigmoidf(hv);
        float4 w2 = ((const float4*)s2T)[o];
        a0 += w2.x * sv; a1 += w2.y * sv; a2 += w2.z * sv; a3 += w2.w * sv;
    }
    int p = atomicAdd(&g_cur[d], 1);
    g_srcp[p] = s;
    ((float4*)g_esp)[p] = make_float4(a0 + sb2v[0], a1 + sb2v[1], a2 + sb2v[2], a3 + sb2v[3]);
}

// ---------------- node embedding + input proj ----------------
__global__ void __launch_bounds__(256) k_embed(const int* __restrict__ zi,
        const int* __restrict__ batch, const float* __restrict__ pos,
        const float* __restrict__ atomw, const float* __restrict__ inw,
        const float* __restrict__ inb, int N) {
    __shared__ float wT[65 * 68];
    __shared__ float aT[64 * 36];
    __shared__ float sb[64];
    __shared__ float spx[32], spy[32], spz[32];
    __shared__ int   sz[32];
    int tid = threadIdx.x;
    int n0 = blockIdx.x * 32;

    if (tid < 32) {
        int n = n0 + tid;
        if (n < N) {
            int b = batch[n];
            float ic = 1.f / fmaxf(g_cnt[b], 1.f);
            spx[tid] = pos[n * 3 + 0] - g_psum[b * 3 + 0] * ic;
            spy[tid] = pos[n * 3 + 1] - g_psum[b * 3 + 1] * ic;
            spz[tid] = pos[n * 3 + 2] - g_psum[b * 3 + 2] * ic;
            sz[tid] = zi[n];
        } else { spx[tid] = spy[tid] = spz[tid] = 0.f; sz[tid] = 0; }
    }
    if (tid >= 32 && tid < 96) sb[tid - 32] = inb[tid - 32];
    for (int idx = tid; idx < 64 * 65; idx += 256) {
        int o = idx / 65, i = idx % 65;
        wT[i * 68 + o] = inw[idx];
    }
    __syncthreads();
    for (int idx = tid; idx < 64 * 32; idx += 256) {
        int n = idx & 31, i = idx >> 5;
        aT[i * 36 + n] = atomw[(size_t)sz[n] * 64 + i];
    }
    __syncthreads();

    int ox = (tid & 15) * 4;
    int nl = (tid >> 4) * 2;
    float acc[2][4];
    #pragma unroll
    for (int a = 0; a < 2; a++)
        #pragma unroll
        for (int b = 0; b < 4; b++) acc[a][b] = 0.f;

    #pragma unroll 8
    for (int i = 0; i < 64; i++) {
        float4 w = *(const float4*)&wT[i * 68 + ox];
        float2 a = *(const float2*)&aT[i * 36 + nl];
        acc[0][0] += a.x * w.x; acc[0][1] += a.x * w.y; acc[0][2] += a.x * w.z; acc[0][3] += a.x * w.w;
        acc[1][0] += a.y * w.x; acc[1][1] += a.y * w.y; acc[1][2] += a.y * w.z; acc[1][3] += a.y * w.w;
    }

    #pragma unroll
    for (int jj = 0; jj < 2; jj++) {
        int n = n0 + nl + jj;
        if (n >= N) break;
        float px = spx[nl + jj], py = spy[nl + jj], pz = spz[nl + jj];
        #pragma unroll
        for (int cc = 0; cc < 4; cc++) {
            int o = ox + cc;
            float vw = wT[64 * 68 + o];
            float4* hp = (float4*)(g_h + (size_t)n * 512 + o * 8);
            hp[0] = make_float4(acc[jj][cc] + sb[o], vw * px, vw * py, vw * pz);
            hp[1] = make_float4(0.f, 0.f, 0.f, 0.f);
        }
    }
}

// ---------------- per-grade MVLinear v3: 32-node tiles, 3 blocks/SM ----------------
// grid (ceil(N/32), 2); blockIdx.y = half. 2 nodes/thread, epilogue reads Asrc/Adst inline.
__global__ void __launch_bounds__(256, 3) k_mvlin(const float* __restrict__ W,
        const float* __restrict__ B, const float* __restrict__ Asrc,
        const float* __restrict__ Adst, const float* __restrict__ Wsrc,
        const float* __restrict__ Wdst, int N) {
    extern __shared__ float sm[];
    float* WsT = sm;            // 2 grades * 64i * 68 = 8704 floats
    float* Xs  = sm + 8704;     // 32 nodes * 256 floats = 8192
    int tid = threadIdx.x;
    int half = blockIdx.y;
    int n0 = blockIdx.x * 32;
    const unsigned FULL = 0xffffffffu;

    const float* Wg = W + (size_t)(half * 2) * 4096;
    for (int idx = tid; idx < 4096; idx += 256) {
        int o = idx >> 6, i = idx & 63;
        WsT[i * 68 + o]        = Wg[o * 64 + i];
        WsT[4352 + i * 68 + o] = Wg[4096 + o * 64 + i];
    }
    for (int idx = tid; idx < 2048; idx += 256) {
        int j = idx >> 6, i4 = idx & 63;
        int n = n0 + j;
        float4 v = (n < N) ? ((const float4*)g_h)[(size_t)n * 128 + i4 * 2 + half]
                           : make_float4(0.f, 0.f, 0.f, 0.f);
        *(float4*)&Xs[j * 256 + i4 * 4] = v;
    }
    __syncthreads();

    int og = tid & 15, ng = tid >> 4;
    int o0 = og * 4, nb = ng * 2;
    float acc[4][2][4];   // [oo][jj][blade]
    #pragma unroll
    for (int a = 0; a < 4; a++)
        #pragma unroll
        for (int b = 0; b < 2; b++)
            #pragma unroll
            for (int c = 0; c < 4; c++) acc[a][b][c] = 0.f;

    if (half == 0) {
        #pragma unroll 4
        for (int i = 0; i < 64; i++) {
            float4 wa = *(const float4*)&WsT[i * 68 + o0];
            float4 wb = *(const float4*)&WsT[4352 + i * 68 + o0];
            float4 x0 = *(const float4*)&Xs[nb * 256 + i * 4];
            float4 x1 = *(const float4*)&Xs[(nb + 1) * 256 + i * 4];
            float wA[4] = {wa.x, wa.y, wa.z, wa.w};
            float wB[4] = {wb.x, wb.y, wb.z, wb.w};
            #pragma unroll
            for (int oo = 0; oo < 4; oo++) {
                acc[oo][0][0] += wA[oo] * x0.x;
                acc[oo][0][1] += wB[oo] * x0.y;
                acc[oo][0][2] += wB[oo] * x0.z;
                acc[oo][0][3] += wB[oo] * x0.w;
                acc[oo][1][0] += wA[oo] * x1.x;
                acc[oo][1][1] += wB[oo] * x1.y;
                acc[oo][1][2] += wB[oo] * x1.z;
                acc[oo][1][3] += wB[oo] * x1.w;
            }
        }
    } else {
        #pragma unroll 4
        for (int i = 0; i < 64; i++) {
            float4 wa = *(const float4*)&WsT[i * 68 + o0];
            float4 wb = *(const float4*)&WsT[4352 + i * 68 + o0];
            float4 x0 = *(const float4*)&Xs[nb * 256 + i * 4];
            float4 x1 = *(const float4*)&Xs[(nb + 1) * 256 + i * 4];
            float wA[4] = {wa.x, wa.y, wa.z, wa.w};
            float wB[4] = {wb.x, wb.y, wb.z, wb.w};
            #pragma unroll
            for (int oo = 0; oo < 4; oo++) {
                acc[oo][0][0] += wA[oo] * x0.x;
                acc[oo][0][1] += wA[oo] * x0.y;
                acc[oo][0][2] += wA[oo] * x0.z;
                acc[oo][0][3] += wB[oo] * x0.w;
                acc[oo][1][0] += wA[oo] * x1.x;
                acc[oo][1][1] += wA[oo] * x1.y;
                acc[oo][1][2] += wA[oo] * x1.z;
                acc[oo][1][3] += wB[oo] * x1.w;
            }
        }
    }

    // epilogue: bias, fp16 z store, logit partials (Asrc/Adst read inline, L1-hit)
    int head = og >> 2;
    float ws0, ws1, wd0, wd1;
    if (half == 0) { ws0 = Wsrc[head * 4 + 0]; ws1 = Wsrc[head * 4 + 1];
                     wd0 = Wdst[head * 4 + 0]; wd1 = Wdst[head * 4 + 1]; }
    else           { ws0 = Wsrc[head * 4 + 2]; ws1 = Wsrc[head * 4 + 3];
                     wd0 = Wdst[head * 4 + 2]; wd1 = Wdst[head * 4 + 3]; }

    #pragma unroll
    for (int jj = 0; jj < 2; jj++) {
        int n = n0 + nb + jj;
        bool ok = (n < N);
        float ps = 0.f, pd = 0.f;
        #pragma unroll
        for (int oo = 0; oo < 4; oo++) {
            int o = o0 + oo;
            float bb = (half == 0) ? B[o] : 0.f;
            float v0 = acc[oo][jj][0] + bb;
            float v1 = acc[oo][jj][1], v2 = acc[oo][jj][2], v3 = acc[oo][jj][3];
            if (ok) {
                __half2 ha = __floats2half2_rn(v0, v1);
                __half2 hb = __floats2half2_rn(v2, v3);
                uint2 u;
                u.x = *(unsigned*)&ha;
                u.y = *(unsigned*)&hb;
                *(uint2*)(g_zh + (size_t)n * 512 + o * 8 + half * 4) = u;
            }
            float4 Ab = *(const float4*)(Asrc + o * 8 + half * 4);
            float4 Db = *(const float4*)(Adst + o * 8 + half * 4);
            if (half == 0) {
                ps += v0 * Ab.x * ws0 + v1 * Ab.y * ws1 + v2 * Ab.z * ws1 + v3 * Ab.w * ws1;
                pd += v0 * Db.x * wd0 + v1 * Db.y * wd1 + v2 * Db.z * wd1 + v3 * Db.w * wd1;
            } else {
                ps += v0 * Ab.x * ws0 + v1 * Ab.y * ws0 + v2 * Ab.z * ws0 + v3 * Ab.w * ws1;
                pd += v0 * Db.x * wd0 + v1 * Db.y * wd0 + v2 * Db.z * wd0 + v3 * Db.w * wd1;
            }
        }
        ps += __shfl_xor_sync(FULL, ps, 1);
        ps += __shfl_xor_sync(FULL, ps, 2);
        pd += __shfl_xor_sync(FULL, pd, 1);
        pd += __shfl_xor_sync(FULL, pd, 2);
        if ((tid & 3) == 0 && ok) {
            if (half == 0) { g_ssrcA[n * 4 + head] = ps; g_sdstA[n * 4 + head] = pd; }
            else           { g_ssrcB[n * 4 + head] = ps; g_sdstB[n * 4 + head] = pd; }
        }
    }
}

// ---------------- combine logit partials ----------------
__global__ void k_comb(int N) {
    int i = blockIdx.x * 256 + threadIdx.x;
    if (i < N * 4) {
        g_ssrc[i] = g_ssrcA[i] + g_ssrcB[i];
        g_sdst[i] = g_sdstA[i] + g_sdstB[i];
    }
}

// ---------------- warp-per-node attention + MVSiLU + residual + LN ----------------
// lane L owns components [16L,16L+16) = channels 2L,2L+1; head = L>>3.
__global__ void __launch_bounds__(128) k_attn(const float* __restrict__ sa,
        const float* __restrict__ sbp, const float* __restrict__ lna, int N) {
    __shared__ float4 salpha[4][64];
    __shared__ int    ssidx[4][64];
    int wslot = threadIdx.x >> 5;
    int n = blockIdx.x * 4 + wslot;
    int lane = threadIdx.x & 31;
    if (n >= N) return;
    int e0 = g_off[n];
    int deg = g_off[n + 1] - e0;
    float4 sd = ((const float4*)g_sdst)[n];
    const unsigned FULL = 0xffffffffu;
    int hsel = lane >> 3;

    bool fits = (deg <= 64);
    float4 mx = make_float4(-3e38f, -3e38f, -3e38f, -3e38f);

    if (fits) {
        #pragma unroll
        for (int r = 0; r < 2; r++) {
            int j = lane + r * 32;
            if (j < deg) {
                int s = g_srcp[e0 + j];
                float4 ss = ((const float4*)g_ssrc)[s];
                float4 ev = ((const float4*)g_esp)[e0 + j];
                float4 lg = make_float4(lrelu(ss.x + sd.x + ev.x), lrelu(ss.y + sd.y + ev.y),
                                        lrelu(ss.z + sd.z + ev.z), lrelu(ss.w + sd.w + ev.w));
                salpha[wslot][j] = lg;
                ssidx[wslot][j] = s;
                mx.x = fmaxf(mx.x, lg.x); mx.y = fmaxf(mx.y, lg.y);
                mx.z = fmaxf(mx.z, lg.z); mx.w = fmaxf(mx.w, lg.w);
            }
        }
    } else {
        for (int j = lane; j < deg; j += 32) {
            int s = g_srcp[e0 + j];
            float4 ss = ((const float4*)g_ssrc)[s];
            float4 ev = ((const float4*)g_esp)[e0 + j];
            mx.x = fmaxf(mx.x, lrelu(ss.x + sd.x + ev.x));
            mx.y = fmaxf(mx.y, lrelu(ss.y + sd.y + ev.y));
            mx.z = fmaxf(mx.z, lrelu(ss.z + sd.z + ev.z));
            mx.w = fmaxf(mx.w, lrelu(ss.w + sd.w + ev.w));
        }
    }
    #pragma unroll
    for (int off = 16; off; off >>= 1) {
        mx.x = fmaxf(mx.x, __shfl_xor_sync(FULL, mx.x, off));
        mx.y = fmaxf(mx.y, __shfl_xor_sync(FULL, mx.y, off));
        mx.z = fmaxf(mx.z, __shfl_xor_sync(FULL, mx.z, off));
        mx.w = fmaxf(mx.w, __shfl_xor_sync(FULL, mx.w, off));
    }

    float4 su = make_float4(0.f, 0.f, 0.f, 0.f);
    if (fits) {
        __syncwarp();
        #pragma unroll
        for (int r = 0; r < 2; r++) {
            int j = lane + r * 32;
            if (j < deg) {
                float4 lg = salpha[wslot][j];
                lg.x = __expf(lg.x - mx.x); lg.y = __expf(lg.y - mx.y);
                lg.z = __expf(lg.z - mx.z); lg.w = __expf(lg.w - mx.w);
                su.x += lg.x; su.y += lg.y; su.z += lg.z; su.w += lg.w;
                salpha[wslot][j] = lg;
            }
        }
        __syncwarp();
    } else {
        for (int j = lane; j < deg; j += 32) {
            int s = g_srcp[e0 + j];
            float4 ss = ((const float4*)g_ssrc)[s];
            float4 ev = ((const float4*)g_esp)[e0 + j];
            su.x += __expf(lrelu(ss.x + sd.x + ev.x) - mx.x);
            su.y += __expf(lrelu(ss.y + sd.y + ev.y) - mx.y);
            su.z += __expf(lrelu(ss.z + sd.z + ev.z) - mx.z);
            su.w += __expf(lrelu(ss.w + sd.w + ev.w) - mx.w);
        }
    }
    #pragma unroll
    for (int off = 16; off; off >>= 1) {
        su.x += __shfl_xor_sync(FULL, su.x, off);
        su.y += __shfl_xor_sync(FULL, su.y, off);
        su.z += __shfl_xor_sync(FULL, su.z, off);
        su.w += __shfl_xor_sync(FULL, su.w, off);
    }

    float acc[16];
    #pragma unroll
    for (int k = 0; k < 16; k++) acc[k] = 0.f;

    if (fits) {
        const float* sal = (const float*)&salpha[wslot][0];
        const int* sidx = ssidx[wslot];
        int m = deg;
        uint4 A0, B0, A1, B1;
        float w0v = 0.f, w1v = 0.f;
        if (m > 0) {
            int s = sidx[0];
            w0v = sal[hsel];
            const uint4* zp = (const uint4*)(g_zh + (size_t)s * 512);
            A0 = zp[lane * 2]; B0 = zp[lane * 2 + 1];
        }
        if (m > 1) {
            int s = sidx[1];
            w1v = sal[4 + hsel];
            const uint4* zp = (const uint4*)(g_zh + (size_t)s * 512);
            A1 = zp[lane * 2]; B1 = zp[lane * 2 + 1];
        }
        for (int l = 0; l < m; l++) {
            uint4 cA, cB;
            float a;
            if ((l & 1) == 0) { cA = A0; cB = B0; a = w0v; }
            else              { cA = A1; cB = B1; a = w1v; }
            int lp = l + 2;
            if (lp < m) {
                int s = sidx[lp];
                float av = sal[lp * 4 + hsel];
                const uint4* zp = (const uint4*)(g_zh + (size_t)s * 512);
                if ((l & 1) == 0) { A0 = zp[lane * 2]; B0 = zp[lane * 2 + 1]; w0v = av; }
                else              { A1 = zp[lane * 2]; B1 = zp[lane * 2 + 1]; w1v = av; }
            }
            float f[16];
            cvt8(cA, f);
            cvt8(cB, f + 8);
            #pragma unroll
            for (int k = 0; k < 16; k++) acc[k] += a * f[k];
        }
    } else {
        for (int j = 0; j < deg; j++) {
            int s = g_srcp[e0 + j];
            float4 ss = ((const float4*)g_ssrc)[s];
            float4 ev = ((const float4*)g_esp)[e0 + j];
            float w0 = __expf(lrelu(ss.x + sd.x + ev.x) - mx.x);
            float w1 = __expf(lrelu(ss.y + sd.y + ev.y) - mx.y);
            float w2 = __expf(lrelu(ss.z + sd.z + ev.z) - mx.z);
            float w3 = __expf(lrelu(ss.w + sd.w + ev.w) - mx.w);
            float a = hsel == 0 ? w0 : hsel == 1 ? w1 : hsel == 2 ? w2 : w3;
            const uint4* zp = (const uint4*)(g_zh + (size_t)s * 512);
            uint4 pA = zp[lane * 2];
            uint4 pB = zp[lane * 2 + 1];
            float f[16];
            cvt8(pA, f);
            cvt8(pB, f + 8);
            #pragma unroll
            for (int k = 0; k < 16; k++) acc[k] += a * f[k];
        }
    }

    float sh = hsel == 0 ? su.x : hsel == 1 ? su.y : hsel == 2 ? su.z : su.w;
    float inv = 1.f / (sh + 1e-16f);
    float x[16];
    #pragma unroll
    for (int k = 0; k < 16; k++) x[k] = acc[k] * inv;

    int c0 = lane * 2, c1 = lane * 2 + 1;
    float4 saA = ((const float4*)sa)[c0], sbA = ((const float4*)sbp)[c0];
    float4 saB = ((const float4*)sa)[c1], sbB = ((const float4*)sbp)[c1];
    mvgate(x, saA, sbA);
    mvgate(x + 8, saB, sbB);

    const float4* hr = (const float4*)(g_h + (size_t)n * 512) + lane * 4;
    float4 r0 = hr[0], r1 = hr[1], r2 = hr[2], r3 = hr[3];
    x[0] += r0.x;  x[1] += r0.y;  x[2] += r0.z;  x[3] += r0.w;
    x[4] += r1.x;  x[5] += r1.y;  x[6] += r1.z;  x[7] += r1.w;
    x[8] += r2.x;  x[9] += r2.y;  x[10] += r2.z; x[11] += r2.w;
    x[12] += r3.x; x[13] += r3.y; x[14] += r3.z; x[15] += r3.w;

    float ss0 = 0.f, ss1 = 0.f;
    #pragma unroll
    for (int k = 0; k < 8; k++) { ss0 += x[k] * x[k]; ss1 += x[8 + k] * x[8 + k]; }
    float cn = sqrtf(ss0) + sqrtf(ss1);
    #pragma unroll
    for (int off = 16; off; off >>= 1) cn += __shfl_xor_sync(FULL, cn, off);
    float mean = cn * (1.f / 64.f) + 1e-6f;
    float invm = 1.f / mean;
    float sc0 = lna[c0] * invm, sc1 = lna[c1] * invm;

    float4* hw = (float4*)(g_h + (size_t)n * 512) + lane * 4;
    hw[0] = make_float4(x[0] * sc0, x[1] * sc0, x[2] * sc0, x[3] * sc0);
    hw[1] = make_float4(x[4] * sc0, x[5] * sc0, x[6] * sc0, x[7] * sc0);
    hw[2] = make_float4(x[8] * sc1, x[9] * sc1, x[10] * sc1, x[11] * sc1);
    hw[3] = make_float4(x[12] * sc1, x[13] * sc1, x[14] * sc1, x[15] * sc1);
}

// ---------------- prepool + graph pooling ----------------
__global__ void __launch_bounds__(64) k_prepool(const float* __restrict__ ppw,
        const float* __restrict__ ppb, const int* __restrict__ batch, int N) {
    __shared__ float x0[64];
    int n = blockIdx.x, tid = threadIdx.x;
    x0[tid] = g_h[(size_t)n * 512 + tid * 8];
    __syncthreads();
    float acc = ppb[tid];
    const float* wr = ppw + tid * 64;
    #pragma unroll 8
    for (int i = 0; i < 64; i++) acc += wr[i] * x0[i];
    atomicAdd(&g_gsum[batch[n] * 64 + tid], acc);
}

__global__ void __launch_bounds__(64) k_post(const float* __restrict__ pw1,
        const float* __restrict__ pb1, const float* __restrict__ pw2,
        const float* __restrict__ pb2, float* __restrict__ out) {
    __shared__ float sg[64];
    __shared__ float sh[64];
    int b = blockIdx.x, tid = threadIdx.x;
    sg[tid] = g_gsum[b * 64 + tid];
    __syncthreads();
    float a = pb1[tid];
    const float* wr = pw1 + tid * 64;
    #pragma unroll 8
    for (int i = 0; i < 64; i++) a += wr[i] * sg[i];
    float s = a * sigmoidf(a);
    sh[tid] = s * pw2[tid];
    __syncthreads();
    for (int st = 32; st; st >>= 1) {
        if (tid < st) sh[tid] += sh[tid + st];
        __syncthreads();
    }
    if (tid == 0) out[b] = sh[0] + pb2[0];
}

// ---------------- launch ----------------
extern "C" void kernel_launch(void* const* d_in, const int* in_sizes, int n_in,
                              void* d_out, int out_size) {
    const float* pos   = (const float*)d_in[0];
    const int*   zi    = (const int*)d_in[1];
    const int*   ei    = (const int*)d_in[2];
    const int*   batch = (const int*)d_in[3];
    const float* atomw = (const float*)d_in[4];
    const float* inw   = (const float*)d_in[5];
    const float* inb   = (const float*)d_in[6];
    const float* ew1   = (const float*)d_in[7];
    const float* eb1   = (const float*)d_in[8];
    const float* ew2   = (const float*)d_in[9];
    const float* eb2   = (const float*)d_in[10];
    const float* projw = (const float*)d_in[11];
    const float* projb = (const float*)d_in[12];
    const float* asrc  = (const float*)d_in[13];
    const float* adst  = (const float*)d_in[14];
    const float* wsrc  = (const float*)d_in[15];
    const float* wdst  = (const float*)d_in[16];
    const float* lna   = (const float*)d_in[17];
    const float* silua = (const float*)d_in[18];
    const float* silub = (const float*)d_in[19];
    const float* ppw   = (const float*)d_in[20];
    const float* ppb   = (const float*)d_in[21];
    const float* pw1   = (const float*)d_in[22];
    const float* pb1   = (const float*)d_in[23];
    const float* pw2   = (const float*)d_in[24];
    const float* pb2   = (const float*)d_in[25];
    float* out = (float*)d_out;

    int N = in_sizes[0] / 3;
    int E = in_sizes[2] / 2;
    const int* src = ei;
    const int* dst = ei + E;
    int G = (N + 1023) / 1024;
    const int MVSMEM = (8704 + 8192) * 4;   // 67584 B

    cudaFuncSetAttribute(k_mvlin, cudaFuncAttributeMaxDynamicSharedMemorySize, MVSMEM);

    k_zero<<<64, 256>>>(N);
    k_init<<<(E + 255) / 256, 256>>>(pos, batch, dst, N, E);
    k_embed<<<(N + 31) / 32, 256>>>(zi, batch, pos, atomw, inw, inb, N);
    dim3 mvgrid((N + 31) / 32, 2);
    k_mvlin<<<mvgrid, 256, MVSMEM>>>(projw, projb, asrc, adst, wsrc, wdst, N);
    k_scanA<<<G, 1024>>>(N);
    k_scanB<<<G, 256>>>(N, E, G);
    k_edgefill<<<(E + 127) / 128, 128>>>(pos, src, dst, ew1, eb1, ew2, eb2, E);

    k_comb<<<(N * 4 + 255) / 256, 256>>>(N);
    k_attn<<<(N + 3) / 4, 128>>>(silua, silub, lna, N);
    for (int l = 1; l < 4; l++) {
        k_mvlin<<<mvgrid, 256, MVSMEM>>>(projw + (size_t)l * 4 * 64 * 64,
                                         projb + l * 64,
                                         asrc + l * 512, adst + l * 512,
                                         wsrc + l * 16, wdst + l * 16, N);
        k_comb<<<(N * 4 + 255) / 256, 256>>>(N);
        k_attn<<<(N + 3) / 4, 128>>>(silua + l * 256, silub + l * 256, lna + l * 64, N);
    }

    k_prepool<<<N, 64>>>(ppw, ppb, batch, N);
    k_post<<<NB, 64>>>(pw1, pb1, pw2, pb2, out);
}